// round 1
// baseline (speedup 1.0000x reference)
#include <cuda_runtime.h>
#include <math.h>

// Problem dims (fixed by setup_inputs)
#define BB 8
#define LX 512
#define NWTOK 384
#define SS 896          // sequence length after concat (L-1)
#define DD 1024
#define NH 16
#define HD 64
#define FFD 4096
#define NLAYER 4

// ---------------- scratch (device globals; no allocations allowed) ----------------
__device__ float g_tgt[BB * SS * DD];              // 29.4 MB
__device__ float g_qkv[BB * SS * 3 * DD];          // 88 MB
__device__ float g_scores[(long)BB * NH * SS * SS];// 411 MB
__device__ float g_attno[BB * SS * DD];            // 29.4 MB
__device__ float g_hid[(long)BB * SS * FFD];       // 117 MB
__device__ float g_tmp[BB * SS * DD];              // 29.4 MB
__device__ int   g_xmask[BB * LX];

// ---------------- helpers ----------------
__device__ __forceinline__ float gelu_exact(float x) {
    return 0.5f * x * (1.0f + erff(x * 0.70710678118654752f));
}

// ---------------- generic tiled SGEMM: C = act(alpha * A*B(^T) + bias) ----------------
// A: (M,K) row-major, lda
// TRANSB=true : B is (N,K) row-major (C[m,n] = dot(A[m,:], B[n,:]))
// TRANSB=false: B is (K,N) row-major
// Batched via blockIdx.z with two-level strides: z -> (zo = z/innerCount, zi = z%innerCount)
template<bool TRANSB, int ACT>
__global__ void sgemm64(const float* __restrict__ A, const float* __restrict__ Bm,
                        const float* __restrict__ bias, float* __restrict__ C,
                        int M, int N, int K, int lda, int ldb, int ldc,
                        float alpha,
                        long sAo, long sAi, long sBo, long sBi, long sCo, long sCi,
                        int innerCount)
{
    int z = blockIdx.z;
    int zo = z / innerCount, zi = z % innerCount;
    A  += zo * sAo + (long)zi * sAi;
    Bm += zo * sBo + (long)zi * sBi;
    C  += zo * sCo + (long)zi * sCi;

    __shared__ float As[64][17];   // [m][k]
    __shared__ float Bs[16][65];   // [k][n]

    const int tid = threadIdx.x;
    const int tx = tid & 15;
    const int ty = tid >> 4;
    const int m0 = blockIdx.x * 64;
    const int n0 = blockIdx.y * 64;

    float acc[4][4] = {};

    for (int k0 = 0; k0 < K; k0 += 16) {
        #pragma unroll
        for (int p = 0; p < 4; p++) {
            int m = (tid >> 4) + p * 16;
            int k = tid & 15;
            As[m][k] = A[(long)(m0 + m) * lda + (k0 + k)];
        }
        if (TRANSB) {
            #pragma unroll
            for (int p = 0; p < 4; p++) {
                int n = (tid >> 4) + p * 16;
                int k = tid & 15;
                Bs[k][n] = Bm[(long)(n0 + n) * ldb + (k0 + k)];
            }
        } else {
            #pragma unroll
            for (int p = 0; p < 4; p++) {
                int k = (tid >> 6) + p * 4;
                int n = tid & 63;
                Bs[k][n] = Bm[(long)(k0 + k) * ldb + (n0 + n)];
            }
        }
        __syncthreads();
        #pragma unroll
        for (int k = 0; k < 16; k++) {
            float a[4], b[4];
            #pragma unroll
            for (int i = 0; i < 4; i++) a[i] = As[ty * 4 + i][k];
            #pragma unroll
            for (int j = 0; j < 4; j++) b[j] = Bs[k][tx * 4 + j];
            #pragma unroll
            for (int i = 0; i < 4; i++)
                #pragma unroll
                for (int j = 0; j < 4; j++)
                    acc[i][j] = fmaf(a[i], b[j], acc[i][j]);
        }
        __syncthreads();
    }

    #pragma unroll
    for (int i = 0; i < 4; i++) {
        int m = m0 + ty * 4 + i;
        #pragma unroll
        for (int j = 0; j < 4; j++) {
            int n = n0 + tx * 4 + j;
            float v = acc[i][j] * alpha;
            if (bias) v += bias[n];
            if (ACT == 1) v = gelu_exact(v);
            C[(long)m * ldc + n] = v;
        }
    }
}

// ---------------- embedding: x tokens (rows 0..511) ----------------
__global__ void embed_x_kernel(const float* __restrict__ x,
                               const float* __restrict__ W_nail,
                               const float* __restrict__ b_nail)
{
    const float RSC = 0.99995000374968753f; // 1/sqrt(1.0001)
    int row = blockIdx.x;                   // b*LX + l
    int b = row / LX;
    const float* xr = x + (long)row * 64;
    __shared__ float xn[63];
    __shared__ float t_sh;
    int tid = threadIdx.x;
    if (tid == 0) {
        float t0 = xr[0];
        g_xmask[row] = isnan(t0) ? 1 : 0;
        t_sh = isnan(t0) ? 0.f : t0;
    }
    if (tid < 63) {
        float v = xr[tid + 1];
        if (isnan(v)) v = 0.f;
        v *= RSC;
        xn[tid] = fminf(fmaxf(v, -5.f), 5.f);
    }
    __syncthreads();
    float t = t_sh;
    const float kfac = -logf(1000.f) / 1024.f;
    for (int d = tid; d < DD; d += 256) {
        const float* wr = W_nail + d * 63;
        float acc = b_nail[d];
        #pragma unroll 7
        for (int c = 0; c < 63; c++) acc = fmaf(xn[c], wr[c], acc);
        int i = d >> 1;
        float ang = t * expf((float)i * kfac);
        acc += (d & 1) ? cosf(ang) : sinf(ang);
        g_tgt[((long)b * SS + (row % LX)) * DD + d] = acc;
    }
}

// ---------------- embedding: w tokens (rows 512..895) + global PE ----------------
__global__ void embed_w_kernel(const float* __restrict__ w,
                               const float* __restrict__ W_cond,
                               const float* __restrict__ b_cond)
{
    const float RSC = 0.99995000374968753f;
    int row = blockIdx.x;                 // b*NWTOK + r
    int b = row / NWTOK, r = row % NWTOK;
    const float* wr6 = w + (long)b * (NWTOK * 6) + r * 6;
    __shared__ float wn[6];
    int tid = threadIdx.x;
    if (tid < 6) {
        float v = wr6[tid];
        if (isnan(v)) v = 0.f;
        v *= RSC;
        wn[tid] = fminf(fmaxf(v, -5.f), 5.f);
    }
    __syncthreads();
    int spos = LX + r;
    const float kfac = -logf(1000.f) / 1024.f;
    for (int d = tid; d < DD; d += 256) {
        const float* wc = W_cond + d * 6;
        float acc = b_cond[d];
        #pragma unroll
        for (int c = 0; c < 6; c++) acc = fmaf(wn[c], wc[c], acc);
        int i = d >> 1;
        float ang = (float)spos * expf((float)i * kfac);
        acc += (d & 1) ? cosf(ang) : sinf(ang);
        g_tgt[((long)b * SS + spos) * DD + d] = acc;
    }
}

// ---------------- masked softmax (in-place on g_scores) ----------------
// valid(k): k < LX ? !x_mask[b,k] : k <= q   (x_mask override of causal for first LX cols)
__global__ void softmax_kernel()
{
    long row = (long)blockIdx.x * 8 + (threadIdx.x >> 5);   // over B*NH*SS rows
    if (row >= (long)BB * NH * SS) return;
    int lane = threadIdx.x & 31;
    int q = (int)(row % SS);
    int b = (int)(row / ((long)NH * SS));
    float* p = g_scores + row * SS;
    const int* xm = g_xmask + b * LX;
    int lim = (q < LX) ? LX : (q + 1);

    float mx = -3.0e38f;
    for (int k = lane; k < lim; k += 32) {
        bool valid = (k < LX) ? (xm[k] == 0) : true;
        if (valid) mx = fmaxf(mx, p[k]);
    }
    #pragma unroll
    for (int o = 16; o > 0; o >>= 1) mx = fmaxf(mx, __shfl_xor_sync(0xffffffffu, mx, o));

    float sum = 0.f;
    for (int k = lane; k < lim; k += 32) {
        bool valid = (k < LX) ? (xm[k] == 0) : true;
        float e = valid ? expf(p[k] - mx) : 0.f;
        p[k] = e;
        sum += e;
    }
    #pragma unroll
    for (int o = 16; o > 0; o >>= 1) sum += __shfl_xor_sync(0xffffffffu, sum, o);
    float inv = 1.f / sum;
    for (int k = lane; k < SS; k += 32)
        p[k] = (k < lim) ? p[k] * inv : 0.f;
}

// ---------------- residual add + LayerNorm (in-place on g_tgt) ----------------
__global__ void resid_ln_kernel(const float* __restrict__ delta,
                                const float* __restrict__ g,
                                const float* __restrict__ beta)
{
    long row = blockIdx.x;               // B*SS rows
    float* t = g_tgt + row * DD;
    const float* dl = delta + row * DD;
    int tid = threadIdx.x;               // 256
    float v[4];
    float s = 0.f;
    #pragma unroll
    for (int i = 0; i < 4; i++) { int idx = tid + i * 256; v[i] = t[idx] + dl[idx]; s += v[i]; }
    __shared__ float red[256];
    red[tid] = s; __syncthreads();
    #pragma unroll
    for (int o = 128; o > 0; o >>= 1) { if (tid < o) red[tid] += red[tid + o]; __syncthreads(); }
    float mean = red[0] * (1.f / 1024.f);
    __syncthreads();
    float s2 = 0.f;
    #pragma unroll
    for (int i = 0; i < 4; i++) { float d = v[i] - mean; s2 += d * d; }
    red[tid] = s2; __syncthreads();
    #pragma unroll
    for (int o = 128; o > 0; o >>= 1) { if (tid < o) red[tid] += red[tid + o]; __syncthreads(); }
    float inv = rsqrtf(red[0] * (1.f / 1024.f) + 1e-5f);
    #pragma unroll
    for (int i = 0; i < 4; i++) {
        int idx = tid + i * 256;
        t[idx] = (v[i] - mean) * inv * g[idx] + beta[idx];
    }
}

// ---------------- head + loss ----------------
__global__ void loss_kernel(const float* __restrict__ W_ham, const float* __restrict__ b_ham,
                            const float* __restrict__ y, const float* __restrict__ w,
                            float* __restrict__ out)
{
    __shared__ float red[256];
    int tid = threadIdx.x;
    float acc = 0.f;
    for (int idx = tid; idx < BB * 144; idx += 256) {
        int b = idx / 144;
        int j = idx % 144;
        const float* row = g_tgt + ((long)b * SS + (SS - 1)) * DD;
        const float* wr = W_ham + (long)j * DD;
        float dot = b_ham[j];
        for (int k = 0; k < DD; k++) dot = fmaf(row[k], wr[k], dot);
        // y_resid = y - w[:, -1]
        float yr = y[b * 144 + j] - w[(long)b * 2304 + 2160 + j];
        float d = dot - yr;
        acc += d * d;
    }
    red[tid] = acc; __syncthreads();
    #pragma unroll
    for (int o = 128; o > 0; o >>= 1) { if (tid < o) red[tid] += red[tid + o]; __syncthreads(); }
    if (tid == 0) out[0] = red[0] / (float)(BB * 144);
}

// ---------------- launch ----------------
extern "C" void kernel_launch(void* const* d_in, const int* in_sizes, int n_in,
                              void* d_out, int out_size)
{
    const float* x      = (const float*)d_in[0];
    const float* w      = (const float*)d_in[1];
    const float* y      = (const float*)d_in[2];
    const float* W_nail = (const float*)d_in[3];
    const float* b_nail = (const float*)d_in[4];
    const float* W_cond = (const float*)d_in[5];
    const float* b_cond = (const float*)d_in[6];
    const float* Wqkv   = (const float*)d_in[7];
    const float* bqkv   = (const float*)d_in[8];
    const float* Wo     = (const float*)d_in[9];
    const float* bo     = (const float*)d_in[10];
    const float* ln1_g  = (const float*)d_in[11];
    const float* ln1_b  = (const float*)d_in[12];
    const float* ln2_g  = (const float*)d_in[13];
    const float* ln2_b  = (const float*)d_in[14];
    const float* W1     = (const float*)d_in[15];
    const float* b1     = (const float*)d_in[16];
    const float* W2     = (const float*)d_in[17];
    const float* b2     = (const float*)d_in[18];
    const float* W_ham  = (const float*)d_in[19];
    const float* b_ham  = (const float*)d_in[20];

    float *p_tgt, *p_qkv, *p_scores, *p_attno, *p_hid, *p_tmp;
    cudaGetSymbolAddress((void**)&p_tgt,    g_tgt);
    cudaGetSymbolAddress((void**)&p_qkv,    g_qkv);
    cudaGetSymbolAddress((void**)&p_scores, g_scores);
    cudaGetSymbolAddress((void**)&p_attno,  g_attno);
    cudaGetSymbolAddress((void**)&p_hid,    g_hid);
    cudaGetSymbolAddress((void**)&p_tmp,    g_tmp);

    const int M = BB * SS;            // 7168
    dim3 blk(256);

    // embeddings -> g_tgt
    embed_x_kernel<<<BB * LX, blk>>>(x, W_nail, b_nail);
    embed_w_kernel<<<BB * NWTOK, blk>>>(w, W_cond, b_cond);

    const long sTok   = (long)SS * 3 * DD;     // per-batch stride in g_qkv
    const long sScB   = (long)NH * SS * SS;    // per-batch stride in g_scores
    const long sScH   = (long)SS * SS;         // per-head stride in g_scores
    const long sOB    = (long)SS * DD;         // per-batch stride in g_attno

    for (int l = 0; l < NLAYER; l++) {
        const float* Wqkv_l = Wqkv + (long)l * 3 * DD * DD;
        const float* bqkv_l = bqkv + (long)l * 3 * DD;
        const float* Wo_l   = Wo   + (long)l * DD * DD;
        const float* bo_l   = bo   + (long)l * DD;
        const float* W1_l   = W1   + (long)l * FFD * DD;
        const float* b1_l   = b1   + (long)l * FFD;
        const float* W2_l   = W2   + (long)l * DD * FFD;
        const float* b2_l   = b2   + (long)l * DD;

        // qkv = tgt @ Wqkv^T + bqkv   (7168 x 3072 x 1024)
        sgemm64<true, 0><<<dim3(M / 64, 3 * DD / 64, 1), blk>>>(
            p_tgt, Wqkv_l, bqkv_l, p_qkv,
            M, 3 * DD, DD, DD, DD, 3 * DD, 1.f,
            0, 0, 0, 0, 0, 0, 1);

        // scores[b,h] = Q K^T / 8    (896 x 896 x 64, batched over 128)
        sgemm64<true, 0><<<dim3(SS / 64, SS / 64, BB * NH), blk>>>(
            p_qkv, p_qkv + DD, nullptr, p_scores,
            SS, SS, HD, 3 * DD, 3 * DD, SS, 0.125f,
            sTok, HD, sTok, HD, sScB, sScH, NH);

        // masked softmax
        softmax_kernel<<<(BB * NH * SS + 7) / 8, blk>>>();

        // attno[b,h] = attn @ V      (896 x 64 x 896, batched, NN)
        sgemm64<false, 0><<<dim3(SS / 64, 1, BB * NH), blk>>>(
            p_scores, p_qkv + 2 * DD, nullptr, p_attno,
            SS, HD, SS, SS, 3 * DD, DD, 1.f,
            sScB, sScH, sTok, HD, sOB, HD, NH);

        // tmp = attno @ Wo^T + bo
        sgemm64<true, 0><<<dim3(M / 64, DD / 64, 1), blk>>>(
            p_attno, Wo_l, bo_l, p_tmp,
            M, DD, DD, DD, DD, DD, 1.f,
            0, 0, 0, 0, 0, 0, 1);

        // tgt = LN(tgt + tmp)
        resid_ln_kernel<<<M, blk>>>(p_tmp, ln1_g + l * DD, ln1_b + l * DD);

        // hid = gelu(tgt @ W1^T + b1)
        sgemm64<true, 1><<<dim3(M / 64, FFD / 64, 1), blk>>>(
            p_tgt, W1_l, b1_l, p_hid,
            M, FFD, DD, DD, DD, FFD, 1.f,
            0, 0, 0, 0, 0, 0, 1);

        // tmp = hid @ W2^T + b2
        sgemm64<true, 0><<<dim3(M / 64, DD / 64, 1), blk>>>(
            p_hid, W2_l, b2_l, p_tmp,
            M, DD, FFD, FFD, FFD, DD, 1.f,
            0, 0, 0, 0, 0, 0, 1);

        // tgt = LN(tgt + tmp)
        resid_ln_kernel<<<M, blk>>>(p_tmp, ln2_g + l * DD, ln2_b + l * DD);
    }

    loss_kernel<<<1, blk>>>(W_ham, b_ham, y, w, (float*)d_out);
}

// round 3
// speedup vs baseline: 3.4624x; 3.4624x over previous
#include <cuda_runtime.h>
#include <cuda_bf16.h>
#include <math.h>
#include <stdint.h>

// Problem dims (fixed by setup_inputs)
#define BB 8
#define LX 512
#define NWTOK 384
#define SS 896
#define DD 1024
#define NH 16
#define HD 64
#define FFD 4096
#define NLAYER 4

// ---------------- scratch (device globals) ----------------
__device__ float g_tgt[BB * SS * DD];
__device__ __nv_bfloat16 g_tgt_h[BB * SS * DD];
__device__ __nv_bfloat16 g_tgt_l[BB * SS * DD];
__device__ __nv_bfloat16 g_qkv_h[(size_t)BB * SS * 3 * DD];
__device__ __nv_bfloat16 g_qkv_l[(size_t)BB * SS * 3 * DD];
__device__ __nv_bfloat16 g_vT_h[(size_t)BB * DD * SS];
__device__ __nv_bfloat16 g_vT_l[(size_t)BB * DD * SS];
__device__ float g_scores[(size_t)BB * NH * SS * SS];
__device__ __nv_bfloat16 g_p_h[(size_t)BB * NH * SS * SS];
__device__ __nv_bfloat16 g_p_l[(size_t)BB * NH * SS * SS];
__device__ __nv_bfloat16 g_attno_h[(size_t)BB * SS * DD];
__device__ __nv_bfloat16 g_attno_l[(size_t)BB * SS * DD];
__device__ __nv_bfloat16 g_hid_h[(size_t)BB * SS * FFD];
__device__ __nv_bfloat16 g_hid_l[(size_t)BB * SS * FFD];
__device__ float g_tmp[BB * SS * DD];
__device__ int   g_xmask[BB * LX];
// weight bf16 pairs
__device__ __nv_bfloat16 g_wqkv_h[(size_t)NLAYER * 3 * DD * DD];
__device__ __nv_bfloat16 g_wqkv_l[(size_t)NLAYER * 3 * DD * DD];
__device__ __nv_bfloat16 g_wo_h[(size_t)NLAYER * DD * DD];
__device__ __nv_bfloat16 g_wo_l[(size_t)NLAYER * DD * DD];
__device__ __nv_bfloat16 g_w1_h[(size_t)NLAYER * FFD * DD];
__device__ __nv_bfloat16 g_w1_l[(size_t)NLAYER * FFD * DD];
__device__ __nv_bfloat16 g_w2_h[(size_t)NLAYER * DD * FFD];
__device__ __nv_bfloat16 g_w2_l[(size_t)NLAYER * DD * FFD];

// ---------------- helpers ----------------
__device__ __forceinline__ uint32_t smem_u32(const void* p) {
    uint32_t a;
    asm("{ .reg .u64 t; cvta.to.shared.u64 t, %1; cvt.u32.u64 %0, t; }" : "=r"(a) : "l"(p));
    return a;
}
__device__ __forceinline__ void cp_async16(uint32_t saddr, const void* gaddr) {
    asm volatile("cp.async.cg.shared.global [%0], [%1], 16;" :: "r"(saddr), "l"(gaddr));
}
__device__ __forceinline__ void cp_commit() {
    asm volatile("cp.async.commit_group;" ::: "memory");
}
template<int N>
__device__ __forceinline__ void cp_wait() {
    asm volatile("cp.async.wait_group %0;" :: "n"(N) : "memory");
}
__device__ __forceinline__ void ldsm_x4(uint32_t (&r)[4], uint32_t addr) {
    asm volatile("ldmatrix.sync.aligned.m8n8.x4.shared.b16 {%0,%1,%2,%3}, [%4];"
        : "=r"(r[0]), "=r"(r[1]), "=r"(r[2]), "=r"(r[3]) : "r"(addr));
}
__device__ __forceinline__ void mma16816(float (&d)[4], const uint32_t (&a)[4],
                                         uint32_t b0, uint32_t b1) {
    asm volatile("mma.sync.aligned.m16n8k16.row.col.f32.bf16.bf16.f32 "
        "{%0,%1,%2,%3}, {%4,%5,%6,%7}, {%8,%9}, {%0,%1,%2,%3};"
        : "+f"(d[0]), "+f"(d[1]), "+f"(d[2]), "+f"(d[3])
        : "r"(a[0]), "r"(a[1]), "r"(a[2]), "r"(a[3]), "r"(b0), "r"(b1));
}
__device__ __forceinline__ float gelu_exact(float x) {
    return 0.5f * x * (1.0f + erff(x * 0.70710678118654752f));
}
__device__ __forceinline__ uint32_t pack_pair_h(float f0, float f1, uint32_t& lo) {
    __nv_bfloat16 h0 = __float2bfloat16(f0);
    __nv_bfloat16 h1 = __float2bfloat16(f1);
    __nv_bfloat16 l0 = __float2bfloat16(f0 - __bfloat162float(h0));
    __nv_bfloat16 l1 = __float2bfloat16(f1 - __bfloat162float(h1));
    uint32_t hi;
    ((__nv_bfloat16*)&hi)[0] = h0; ((__nv_bfloat16*)&hi)[1] = h1;
    ((__nv_bfloat16*)&lo)[0] = l0; ((__nv_bfloat16*)&lo)[1] = l1;
    return hi;
}

// =====================================================================
// mma.sync GEMM:  C = act(alpha * (A @ B^T) + bias)
// A = Ah+Al (M,K) bf16 pair row-major, B = Bh+Bl (N,K) bf16 pair row-major.
// Split product: Ah*Bh + Ah*Bl + Al*Bh accumulated fp32.
// BM=128 fixed, BN template (128 or 64), BK=32, K multiple of 32.
// OUTMODE 0: fp32 C;  OUTMODE 1: bf16 hi/lo pair Ch/Cl.
// Batched via blockIdx.z (zo = z/innerCount, zi = z%innerCount).
// =====================================================================
template<int BN, int ACT, int OUTMODE>
__global__ void __launch_bounds__(256, 1)
mma_gemm(const __nv_bfloat16* __restrict__ Ah, const __nv_bfloat16* __restrict__ Al,
         const __nv_bfloat16* __restrict__ Bh, const __nv_bfloat16* __restrict__ Bl,
         const float* __restrict__ bias,
         float* __restrict__ Cf, __nv_bfloat16* __restrict__ Ch, __nv_bfloat16* __restrict__ Cl,
         int K, int lda, int ldb, int ldc, float alpha,
         long aZo, long aZi, long bZo, long bZi, long cZo, long cZi, int innerCount)
{
    extern __shared__ __align__(16) char sm[];
    constexpr int ROWB = 80;                    // 32 bf16 + 8 bf16 pad = 80B (16B aligned)
    constexpr int B_OFF = 2 * 128 * ROWB;
    constexpr int STAGE = (2 * 128 + 2 * BN) * ROWB;
    constexpr int NT = BN / 16;                 // n8 tiles per warp

    const int z  = blockIdx.z;
    const int zo = z / innerCount, zi = z - zo * innerCount;
    Ah += zo * aZo + (long)zi * aZi;
    Al += zo * aZo + (long)zi * aZi;
    Bh += zo * bZo + (long)zi * bZi;
    Bl += zo * bZo + (long)zi * bZi;

    const int tid = threadIdx.x;
    const int wid = tid >> 5, lane = tid & 31;
    const int warp_m = wid >> 1, warp_n = wid & 1;
    const int m0 = blockIdx.x * 128;
    const int n0 = blockIdx.y * BN;
    const uint32_t smem_base = smem_u32(sm);
    const int nch = K >> 5;

    float acc[2][NT][4];
    #pragma unroll
    for (int a = 0; a < 2; a++)
        #pragma unroll
        for (int b = 0; b < NT; b++)
            #pragma unroll
            for (int c = 0; c < 4; c++) acc[a][b][c] = 0.f;

    auto load_stage = [&](int stage, int ch) {
        const int k0 = ch << 5;
        const uint32_t sbase = smem_base + stage * STAGE;
        #pragma unroll
        for (int i = tid; i < 1024; i += 256) {
            int hl = i >> 9, idx = i & 511, row = idx >> 2, seg = idx & 3;
            const __nv_bfloat16* g = (hl ? Al : Ah) + (long)(m0 + row) * lda + k0 + seg * 8;
            cp_async16(sbase + (hl * 128 + row) * ROWB + seg * 16, g);
        }
        #pragma unroll
        for (int i = tid; i < BN * 8; i += 256) {
            int hl = i / (BN * 4), idx = i - hl * (BN * 4), row = idx >> 2, seg = idx & 3;
            const __nv_bfloat16* g = (hl ? Bl : Bh) + (long)(n0 + row) * ldb + k0 + seg * 8;
            cp_async16(sbase + B_OFF + (hl * BN + row) * ROWB + seg * 16, g);
        }
        cp_commit();
    };

    auto compute = [&](int stage) {
        const uint32_t sbase = smem_base + stage * STAGE;
        const int arow = warp_m * 32 + (lane & 15);
        const int bn   = (lane & 7) + (lane >> 4) * 8;
        const int bka  = ((lane >> 3) & 1) * 8;
        #pragma unroll
        for (int kk = 0; kk < 2; kk++) {
            const int acol = kk * 16 + (lane >> 4) * 8;
            uint32_t ah[2][4], al[2][4];
            #pragma unroll
            for (int mt = 0; mt < 2; mt++) {
                ldsm_x4(ah[mt], sbase + (arow + mt * 16) * ROWB + acol * 2);
                ldsm_x4(al[mt], sbase + (128 + arow + mt * 16) * ROWB + acol * 2);
            }
            const int bk = kk * 16 + bka;
            #pragma unroll
            for (int nt2 = 0; nt2 < NT / 2; nt2++) {
                uint32_t bh[4], bl[4];
                uint32_t baddr = sbase + B_OFF +
                    (warp_n * (BN / 2) + nt2 * 16 + bn) * ROWB + bk * 2;
                ldsm_x4(bh, baddr);
                ldsm_x4(bl, baddr + BN * ROWB);
                #pragma unroll
                for (int mt = 0; mt < 2; mt++) {
                    #pragma unroll
                    for (int j = 0; j < 2; j++) {
                        mma16816(acc[mt][nt2 * 2 + j], ah[mt], bh[2 * j], bh[2 * j + 1]);
                        mma16816(acc[mt][nt2 * 2 + j], ah[mt], bl[2 * j], bl[2 * j + 1]);
                        mma16816(acc[mt][nt2 * 2 + j], al[mt], bh[2 * j], bh[2 * j + 1]);
                    }
                }
            }
        }
    };

    load_stage(0, 0);
    for (int ch = 0; ch < nch; ch++) {
        if (ch + 1 < nch) { load_stage((ch + 1) & 1, ch + 1); cp_wait<1>(); }
        else cp_wait<0>();
        __syncthreads();
        compute(ch & 1);
        __syncthreads();
    }

    // epilogue
    const long cbase = zo * cZo + (long)zi * cZi;
    const int r0 = lane >> 2, c0 = (lane & 3) * 2;
    #pragma unroll
    for (int mt = 0; mt < 2; mt++) {
        #pragma unroll
        for (int nt = 0; nt < NT; nt++) {
            const int n = n0 + warp_n * (BN / 2) + nt * 8 + c0;
            float bv0 = bias ? bias[n] : 0.f;
            float bv1 = bias ? bias[n + 1] : 0.f;
            #pragma unroll
            for (int hrow = 0; hrow < 2; hrow++) {
                const int m = m0 + warp_m * 32 + mt * 16 + r0 + hrow * 8;
                float f0 = acc[mt][nt][hrow * 2 + 0] * alpha + bv0;
                float f1 = acc[mt][nt][hrow * 2 + 1] * alpha + bv1;
                if (ACT == 1) { f0 = gelu_exact(f0); f1 = gelu_exact(f1); }
                const long off = cbase + (long)m * ldc + n;
                if (OUTMODE == 0) {
                    *(float2*)(Cf + off) = make_float2(f0, f1);
                } else {
                    uint32_t lo;
                    uint32_t hi = pack_pair_h(f0, f1, lo);
                    *(uint32_t*)(Ch + off) = hi;
                    *(uint32_t*)(Cl + off) = lo;
                }
            }
        }
    }
}

// ---------------- fp32 -> bf16 hi/lo pair conversion ----------------
__global__ void cvt_pair_kernel(const float* __restrict__ src,
                                __nv_bfloat16* __restrict__ h,
                                __nv_bfloat16* __restrict__ l, long n4)
{
    long i = (long)blockIdx.x * blockDim.x + threadIdx.x;
    if (i >= n4) return;
    float4 v = *(const float4*)(src + i * 4);
    uint2 hv, lv;
    __nv_bfloat16* hp = (__nv_bfloat16*)&hv;
    __nv_bfloat16* lp = (__nv_bfloat16*)&lv;
    float f[4] = {v.x, v.y, v.z, v.w};
    #pragma unroll
    for (int q = 0; q < 4; q++) {
        __nv_bfloat16 hh = __float2bfloat16(f[q]);
        hp[q] = hh;
        lp[q] = __float2bfloat16(f[q] - __bfloat162float(hh));
    }
    *(uint2*)(h + i * 4) = hv;
    *(uint2*)(l + i * 4) = lv;
}

// ---------------- V transpose: qkv pair (token-major) -> vT pair [b][h][d][t] ----------------
__global__ void vT_kernel()
{
    __shared__ __nv_bfloat16 th[32][33];
    __shared__ __nv_bfloat16 tl[32][33];
    int z = blockIdx.z;
    int b = z / NH, h = z % NH;
    int t0 = blockIdx.x * 32;
    int d0 = blockIdx.y * 32;
    int tx = threadIdx.x, ty = threadIdx.y;  // 32 x 8
    #pragma unroll
    for (int i = 0; i < 4; i++) {
        int t = t0 + ty + i * 8;
        int d = d0 + tx;
        size_t src = ((size_t)(b * SS + t)) * (3 * DD) + 2 * DD + h * 64 + d;
        th[ty + i * 8][tx] = g_qkv_h[src];
        tl[ty + i * 8][tx] = g_qkv_l[src];
    }
    __syncthreads();
    #pragma unroll
    for (int i = 0; i < 4; i++) {
        int d = d0 + ty + i * 8;
        int t = t0 + tx;
        size_t dst = ((size_t)((b * NH + h) * HD + d)) * SS + t;
        g_vT_h[dst] = th[tx][ty + i * 8];
        g_vT_l[dst] = tl[tx][ty + i * 8];
    }
}

// ---------------- embedding: x tokens ----------------
__global__ void embed_x_kernel(const float* __restrict__ x,
                               const float* __restrict__ W_nail,
                               const float* __restrict__ b_nail)
{
    const float RSC = 0.99995000374968753f;
    int row = blockIdx.x;
    int b = row / LX;
    const float* xr = x + (long)row * 64;
    __shared__ float xn[63];
    __shared__ float t_sh;
    int tid = threadIdx.x;
    if (tid == 0) {
        float t0 = xr[0];
        g_xmask[row] = isnan(t0) ? 1 : 0;
        t_sh = isnan(t0) ? 0.f : t0;
    }
    if (tid < 63) {
        float v = xr[tid + 1];
        if (isnan(v)) v = 0.f;
        v *= RSC;
        xn[tid] = fminf(fmaxf(v, -5.f), 5.f);
    }
    __syncthreads();
    float t = t_sh;
    const float kfac = -logf(1000.f) / 1024.f;
    for (int d = tid; d < DD; d += 256) {
        const float* wr = W_nail + d * 63;
        float acc = b_nail[d];
        #pragma unroll 7
        for (int c = 0; c < 63; c++) acc = fmaf(xn[c], wr[c], acc);
        int i = d >> 1;
        float ang = t * expf((float)i * kfac);
        acc += (d & 1) ? cosf(ang) : sinf(ang);
        size_t idx = ((size_t)b * SS + (row % LX)) * DD + d;
        g_tgt[idx] = acc;
        __nv_bfloat16 hh = __float2bfloat16(acc);
        g_tgt_h[idx] = hh;
        g_tgt_l[idx] = __float2bfloat16(acc - __bfloat162float(hh));
    }
}

// ---------------- embedding: w tokens + global PE ----------------
__global__ void embed_w_kernel(const float* __restrict__ w,
                               const float* __restrict__ W_cond,
                               const float* __restrict__ b_cond)
{
    const float RSC = 0.99995000374968753f;
    int row = blockIdx.x;
    int b = row / NWTOK, r = row % NWTOK;
    const float* wr6 = w + (long)b * (NWTOK * 6) + r * 6;
    __shared__ float wn[6];
    int tid = threadIdx.x;
    if (tid < 6) {
        float v = wr6[tid];
        if (isnan(v)) v = 0.f;
        v *= RSC;
        wn[tid] = fminf(fmaxf(v, -5.f), 5.f);
    }
    __syncthreads();
    int spos = LX + r;
    const float kfac = -logf(1000.f) / 1024.f;
    for (int d = tid; d < DD; d += 256) {
        const float* wc = W_cond + d * 6;
        float acc = b_cond[d];
        #pragma unroll
        for (int c = 0; c < 6; c++) acc = fmaf(wn[c], wc[c], acc);
        int i = d >> 1;
        float ang = (float)spos * expf((float)i * kfac);
        acc += (d & 1) ? cosf(ang) : sinf(ang);
        size_t idx = ((size_t)b * SS + spos) * DD + d;
        g_tgt[idx] = acc;
        __nv_bfloat16 hh = __float2bfloat16(acc);
        g_tgt_h[idx] = hh;
        g_tgt_l[idx] = __float2bfloat16(acc - __bfloat162float(hh));
    }
}

// ---------------- masked softmax: fp32 scores -> bf16 pair probs ----------------
__global__ void softmax_kernel()
{
    size_t row = (size_t)blockIdx.x * 8 + (threadIdx.x >> 5);
    if (row >= (size_t)BB * NH * SS) return;
    int lane = threadIdx.x & 31;
    int q = (int)(row % SS);
    int b = (int)(row / ((size_t)NH * SS));
    const float* p = g_scores + row * SS;
    const int* xm = g_xmask + b * LX;
    const int lim = (q < LX) ? LX : (q + 1);

    float v[28];
    bool ok[28];
    float mx = -3.0e38f;
    #pragma unroll
    for (int i = 0; i < 28; i++) {
        int k = lane + i * 32;
        v[i] = p[k];
        bool valid = (k < lim) && ((k < LX) ? (xm[k] == 0) : true);
        ok[i] = valid;
        if (valid) mx = fmaxf(mx, v[i]);
    }
    #pragma unroll
    for (int o = 16; o > 0; o >>= 1) mx = fmaxf(mx, __shfl_xor_sync(0xffffffffu, mx, o));
    float sum = 0.f;
    #pragma unroll
    for (int i = 0; i < 28; i++) {
        float e = ok[i] ? expf(v[i] - mx) : 0.f;
        v[i] = e;
        sum += e;
    }
    #pragma unroll
    for (int o = 16; o > 0; o >>= 1) sum += __shfl_xor_sync(0xffffffffu, sum, o);
    float inv = 1.f / sum;
    __nv_bfloat16* ph = g_p_h + row * SS;
    __nv_bfloat16* pl = g_p_l + row * SS;
    #pragma unroll
    for (int i = 0; i < 28; i++) {
        int k = lane + i * 32;
        float val = v[i] * inv;
        __nv_bfloat16 hh = __float2bfloat16(val);
        ph[k] = hh;
        pl[k] = __float2bfloat16(val - __bfloat162float(hh));
    }
}

// ---------------- residual add + LayerNorm (in-place on g_tgt, emits bf16 pair) ----------------
__global__ void resid_ln_kernel(const float* __restrict__ delta,
                                const float* __restrict__ g,
                                const float* __restrict__ beta)
{
    size_t row = blockIdx.x;
    float* t = g_tgt + row * DD;
    const float* dl = delta + row * DD;
    int tid = threadIdx.x;
    float v[4];
    float s = 0.f;
    #pragma unroll
    for (int i = 0; i < 4; i++) { int idx = tid + i * 256; v[i] = t[idx] + dl[idx]; s += v[i]; }
    __shared__ float red[256];
    red[tid] = s; __syncthreads();
    #pragma unroll
    for (int o = 128; o > 0; o >>= 1) { if (tid < o) red[tid] += red[tid + o]; __syncthreads(); }
    float mean = red[0] * (1.f / 1024.f);
    __syncthreads();
    float s2 = 0.f;
    #pragma unroll
    for (int i = 0; i < 4; i++) { float d = v[i] - mean; s2 += d * d; }
    red[tid] = s2; __syncthreads();
    #pragma unroll
    for (int o = 128; o > 0; o >>= 1) { if (tid < o) red[tid] += red[tid + o]; __syncthreads(); }
    float inv = rsqrtf(red[0] * (1.f / 1024.f) + 1e-5f);
    #pragma unroll
    for (int i = 0; i < 4; i++) {
        int idx = tid + i * 256;
        float out = (v[i] - mean) * inv * g[idx] + beta[idx];
        t[idx] = out;
        __nv_bfloat16 hh = __float2bfloat16(out);
        g_tgt_h[row * DD + idx] = hh;
        g_tgt_l[row * DD + idx] = __float2bfloat16(out - __bfloat162float(hh));
    }
}

// ---------------- head + loss ----------------
__global__ void loss_kernel(const float* __restrict__ W_ham, const float* __restrict__ b_ham,
                            const float* __restrict__ y, const float* __restrict__ w,
                            float* __restrict__ out)
{
    __shared__ float red[256];
    int tid = threadIdx.x;
    float acc = 0.f;
    for (int idx = tid; idx < BB * 144; idx += 256) {
        int b = idx / 144;
        int j = idx % 144;
        const float* row = g_tgt + ((size_t)b * SS + (SS - 1)) * DD;
        const float* wr = W_ham + (size_t)j * DD;
        float dot = b_ham[j];
        for (int k = 0; k < DD; k++) dot = fmaf(row[k], wr[k], dot);
        float yr = y[b * 144 + j] - w[(size_t)b * 2304 + 2160 + j];
        float d = dot - yr;
        acc += d * d;
    }
    red[tid] = acc; __syncthreads();
    #pragma unroll
    for (int o = 128; o > 0; o >>= 1) { if (tid < o) red[tid] += red[tid + o]; __syncthreads(); }
    if (tid == 0) out[0] = red[0] / (float)(BB * 144);
}

// ---------------- launch ----------------
extern "C" void kernel_launch(void* const* d_in, const int* in_sizes, int n_in,
                              void* d_out, int out_size)
{
    const float* x      = (const float*)d_in[0];
    const float* w      = (const float*)d_in[1];
    const float* y      = (const float*)d_in[2];
    const float* W_nail = (const float*)d_in[3];
    const float* b_nail = (const float*)d_in[4];
    const float* W_cond = (const float*)d_in[5];
    const float* b_cond = (const float*)d_in[6];
    const float* Wqkv   = (const float*)d_in[7];
    const float* bqkv   = (const float*)d_in[8];
    const float* Wo     = (const float*)d_in[9];
    const float* bo     = (const float*)d_in[10];
    const float* ln1_g  = (const float*)d_in[11];
    const float* ln1_b  = (const float*)d_in[12];
    const float* ln2_g  = (const float*)d_in[13];
    const float* ln2_b  = (const float*)d_in[14];
    const float* W1     = (const float*)d_in[15];
    const float* b1     = (const float*)d_in[16];
    const float* W2     = (const float*)d_in[17];
    const float* b2     = (const float*)d_in[18];
    const float* W_ham  = (const float*)d_in[19];
    const float* b_ham  = (const float*)d_in[20];

    float *p_tgt, *p_scores, *p_tmp;
    __nv_bfloat16 *p_tgt_h, *p_tgt_l, *p_qkv_h, *p_qkv_l, *p_vT_h, *p_vT_l;
    __nv_bfloat16 *p_p_h, *p_p_l, *p_attno_h, *p_attno_l, *p_hid_h, *p_hid_l;
    __nv_bfloat16 *p_wqkv_h, *p_wqkv_l, *p_wo_h, *p_wo_l, *p_w1_h, *p_w1_l, *p_w2_h, *p_w2_l;
    cudaGetSymbolAddress((void**)&p_tgt,    g_tgt);
    cudaGetSymbolAddress((void**)&p_scores, g_scores);
    cudaGetSymbolAddress((void**)&p_tmp,    g_tmp);
    cudaGetSymbolAddress((void**)&p_tgt_h,  g_tgt_h);
    cudaGetSymbolAddress((void**)&p_tgt_l,  g_tgt_l);
    cudaGetSymbolAddress((void**)&p_qkv_h,  g_qkv_h);
    cudaGetSymbolAddress((void**)&p_qkv_l,  g_qkv_l);
    cudaGetSymbolAddress((void**)&p_vT_h,   g_vT_h);
    cudaGetSymbolAddress((void**)&p_vT_l,   g_vT_l);
    cudaGetSymbolAddress((void**)&p_p_h,    g_p_h);
    cudaGetSymbolAddress((void**)&p_p_l,    g_p_l);
    cudaGetSymbolAddress((void**)&p_attno_h, g_attno_h);
    cudaGetSymbolAddress((void**)&p_attno_l, g_attno_l);
    cudaGetSymbolAddress((void**)&p_hid_h,  g_hid_h);
    cudaGetSymbolAddress((void**)&p_hid_l,  g_hid_l);
    cudaGetSymbolAddress((void**)&p_wqkv_h, g_wqkv_h);
    cudaGetSymbolAddress((void**)&p_wqkv_l, g_wqkv_l);
    cudaGetSymbolAddress((void**)&p_wo_h,   g_wo_h);
    cudaGetSymbolAddress((void**)&p_wo_l,   g_wo_l);
    cudaGetSymbolAddress((void**)&p_w1_h,   g_w1_h);
    cudaGetSymbolAddress((void**)&p_w1_l,   g_w1_l);
    cudaGetSymbolAddress((void**)&p_w2_h,   g_w2_h);
    cudaGetSymbolAddress((void**)&p_w2_l,   g_w2_l);

    // dynamic smem: (2*128 + 2*BN) * 80 bytes * 2 stages
    static const int SM128 = (2 * 128 + 2 * 128) * 80 * 2; // 81920
    static const int SM64  = (2 * 128 + 2 * 64) * 80 * 2;  // 61440
    cudaFuncSetAttribute(mma_gemm<128, 0, 0>, cudaFuncAttributeMaxDynamicSharedMemorySize, SM128);
    cudaFuncSetAttribute(mma_gemm<128, 0, 1>, cudaFuncAttributeMaxDynamicSharedMemorySize, SM128);
    cudaFuncSetAttribute(mma_gemm<128, 1, 1>, cudaFuncAttributeMaxDynamicSharedMemorySize, SM128);
    cudaFuncSetAttribute(mma_gemm<64, 0, 1>,  cudaFuncAttributeMaxDynamicSharedMemorySize, SM64);

    const int M = BB * SS;   // 7168
    dim3 blk(256);

    // weight conversions
    {
        long n;
        n = (long)NLAYER * 3 * DD * DD / 4;
        cvt_pair_kernel<<<(unsigned)((n + 255) / 256), blk>>>(Wqkv, p_wqkv_h, p_wqkv_l, n);
        n = (long)NLAYER * DD * DD / 4;
        cvt_pair_kernel<<<(unsigned)((n + 255) / 256), blk>>>(Wo, p_wo_h, p_wo_l, n);
        n = (long)NLAYER * FFD * DD / 4;
        cvt_pair_kernel<<<(unsigned)((n + 255) / 256), blk>>>(W1, p_w1_h, p_w1_l, n);
        n = (long)NLAYER * DD * FFD / 4;
        cvt_pair_kernel<<<(unsigned)((n + 255) / 256), blk>>>(W2, p_w2_h, p_w2_l, n);
    }

    embed_x_kernel<<<BB * LX, blk>>>(x, W_nail, b_nail);
    embed_w_kernel<<<BB * NWTOK, blk>>>(w, W_cond, b_cond);

    for (int l = 0; l < NLAYER; l++) {
        const __nv_bfloat16* wqkv_h = p_wqkv_h + (size_t)l * 3 * DD * DD;
        const __nv_bfloat16* wqkv_l = p_wqkv_l + (size_t)l * 3 * DD * DD;
        const __nv_bfloat16* wo_h   = p_wo_h + (size_t)l * DD * DD;
        const __nv_bfloat16* wo_l   = p_wo_l + (size_t)l * DD * DD;
        const __nv_bfloat16* w1_h   = p_w1_h + (size_t)l * FFD * DD;
        const __nv_bfloat16* w1_l   = p_w1_l + (size_t)l * FFD * DD;
        const __nv_bfloat16* w2_h   = p_w2_h + (size_t)l * DD * FFD;
        const __nv_bfloat16* w2_l   = p_w2_l + (size_t)l * DD * FFD;

        // QKV: (7168 x 3072 x 1024) -> bf16 pair
        mma_gemm<128, 0, 1><<<dim3(M / 128, 3 * DD / 128, 1), blk, SM128>>>(
            p_tgt_h, p_tgt_l, wqkv_h, wqkv_l, bqkv + (size_t)l * 3 * DD,
            nullptr, p_qkv_h, p_qkv_l,
            DD, DD, DD, 3 * DD, 1.f, 0, 0, 0, 0, 0, 0, 1);

        // V transpose
        vT_kernel<<<dim3(SS / 32, HD / 32, BB * NH), dim3(32, 8)>>>();

        // scores = Q K^T / 8   (per (b,h): 896 x 896 x 64) -> fp32
        mma_gemm<128, 0, 0><<<dim3(SS / 128, SS / 128, BB * NH), blk, SM128>>>(
            p_qkv_h, p_qkv_l, p_qkv_h + DD, p_qkv_l + DD, nullptr,
            p_scores, nullptr, nullptr,
            HD, 3 * DD, 3 * DD, SS, 0.125f,
            (long)SS * 3 * DD, HD, (long)SS * 3 * DD, HD,
            (long)NH * SS * SS, (long)SS * SS, NH);

        // masked softmax -> probs bf16 pair
        softmax_kernel<<<(BB * NH * SS + 7) / 8, blk>>>();

        // attno = P @ V  (per (b,h): 896 x 64 x 896) -> bf16 pair, token-major
        mma_gemm<64, 0, 1><<<dim3(SS / 128, 1, BB * NH), blk, SM64>>>(
            p_p_h, p_p_l, p_vT_h, p_vT_l, nullptr,
            nullptr, p_attno_h, p_attno_l,
            SS, SS, SS, DD, 1.f,
            (long)NH * SS * SS, (long)SS * SS,
            (long)DD * SS, (long)HD * SS,
            (long)SS * DD, HD, NH);

        // tmp = attno @ Wo^T + bo  -> fp32
        mma_gemm<128, 0, 0><<<dim3(M / 128, DD / 128, 1), blk, SM128>>>(
            p_attno_h, p_attno_l, wo_h, wo_l, bo + (size_t)l * DD,
            p_tmp, nullptr, nullptr,
            DD, DD, DD, DD, 1.f, 0, 0, 0, 0, 0, 0, 1);

        resid_ln_kernel<<<M, blk>>>(p_tmp, ln1_g + (size_t)l * DD, ln1_b + (size_t)l * DD);

        // hid = gelu(tgt @ W1^T + b1) -> bf16 pair
        mma_gemm<128, 1, 1><<<dim3(M / 128, FFD / 128, 1), blk, SM128>>>(
            p_tgt_h, p_tgt_l, w1_h, w1_l, b1 + (size_t)l * FFD,
            nullptr, p_hid_h, p_hid_l,
            DD, DD, DD, FFD, 1.f, 0, 0, 0, 0, 0, 0, 1);

        // tmp = hid @ W2^T + b2 -> fp32
        mma_gemm<128, 0, 0><<<dim3(M / 128, DD / 128, 1), blk, SM128>>>(
            p_hid_h, p_hid_l, w2_h, w2_l, b2 + (size_t)l * DD,
            p_tmp, nullptr, nullptr,
            FFD, FFD, FFD, DD, 1.f, 0, 0, 0, 0, 0, 0, 1);

        resid_ln_kernel<<<M, blk>>>(p_tmp, ln2_g + (size_t)l * DD, ln2_b + (size_t)l * DD);
    }

    loss_kernel<<<1, blk>>>(W_ham, b_ham, y, w, (float*)d_out);
}

// round 4
// speedup vs baseline: 5.1113x; 1.4762x over previous
#include <cuda_runtime.h>
#include <cuda_bf16.h>
#include <math.h>
#include <stdint.h>

// Problem dims (fixed by setup_inputs)
#define BB 8
#define LX 512
#define NWTOK 384
#define SS 896
#define DD 1024
#define NH 16
#define HD 64
#define FFD 4096
#define NLAYER 4

// ---------------- scratch (device globals) ----------------
__device__ float g_tgt[BB * SS * DD];
__device__ __nv_bfloat16 g_tgt_h[BB * SS * DD];
__device__ __nv_bfloat16 g_tgt_l[BB * SS * DD];
__device__ __nv_bfloat16 g_qkv_h[(size_t)BB * SS * 3 * DD];
__device__ __nv_bfloat16 g_qkv_l[(size_t)BB * SS * 3 * DD];
__device__ __nv_bfloat16 g_vT_h[(size_t)BB * DD * SS];
__device__ __nv_bfloat16 g_vT_l[(size_t)BB * DD * SS];
__device__ __nv_bfloat16 g_attno_h[(size_t)BB * SS * DD];
__device__ __nv_bfloat16 g_attno_l[(size_t)BB * SS * DD];
__device__ __nv_bfloat16 g_hid_h[(size_t)BB * SS * FFD];
__device__ __nv_bfloat16 g_hid_l[(size_t)BB * SS * FFD];
__device__ float g_tmp[BB * SS * DD];
__device__ int   g_xmask[BB * LX];
// weight bf16 (hi only; 2-term split rounds weights)
__device__ __nv_bfloat16 g_wqkv_h[(size_t)NLAYER * 3 * DD * DD];
__device__ __nv_bfloat16 g_wo_h[(size_t)NLAYER * DD * DD];
__device__ __nv_bfloat16 g_w1_h[(size_t)NLAYER * FFD * DD];
__device__ __nv_bfloat16 g_w2_h[(size_t)NLAYER * DD * FFD];

// ---------------- helpers ----------------
__device__ __forceinline__ uint32_t smem_u32(const void* p) {
    uint32_t a;
    asm("{ .reg .u64 t; cvta.to.shared.u64 t, %1; cvt.u32.u64 %0, t; }" : "=r"(a) : "l"(p));
    return a;
}
__device__ __forceinline__ void cp_async16(uint32_t saddr, const void* gaddr) {
    asm volatile("cp.async.cg.shared.global [%0], [%1], 16;" :: "r"(saddr), "l"(gaddr));
}
__device__ __forceinline__ void cp_commit() {
    asm volatile("cp.async.commit_group;" ::: "memory");
}
template<int N>
__device__ __forceinline__ void cp_wait() {
    asm volatile("cp.async.wait_group %0;" :: "n"(N) : "memory");
}
__device__ __forceinline__ void ldsm_x4(uint32_t (&r)[4], uint32_t addr) {
    asm volatile("ldmatrix.sync.aligned.m8n8.x4.shared.b16 {%0,%1,%2,%3}, [%4];"
        : "=r"(r[0]), "=r"(r[1]), "=r"(r[2]), "=r"(r[3]) : "r"(addr));
}
__device__ __forceinline__ void mma16816(float (&d)[4], const uint32_t (&a)[4],
                                         uint32_t b0, uint32_t b1) {
    asm volatile("mma.sync.aligned.m16n8k16.row.col.f32.bf16.bf16.f32 "
        "{%0,%1,%2,%3}, {%4,%5,%6,%7}, {%8,%9}, {%0,%1,%2,%3};"
        : "+f"(d[0]), "+f"(d[1]), "+f"(d[2]), "+f"(d[3])
        : "r"(a[0]), "r"(a[1]), "r"(a[2]), "r"(a[3]), "r"(b0), "r"(b1));
}
__device__ __forceinline__ float gelu_exact(float x) {
    return 0.5f * x * (1.0f + erff(x * 0.70710678118654752f));
}
__device__ __forceinline__ uint32_t pack_pair_h(float f0, float f1, uint32_t& lo) {
    __nv_bfloat16 h0 = __float2bfloat16(f0);
    __nv_bfloat16 h1 = __float2bfloat16(f1);
    __nv_bfloat16 l0 = __float2bfloat16(f0 - __bfloat162float(h0));
    __nv_bfloat16 l1 = __float2bfloat16(f1 - __bfloat162float(h1));
    uint32_t hi;
    ((__nv_bfloat16*)&hi)[0] = h0; ((__nv_bfloat16*)&hi)[1] = h1;
    ((__nv_bfloat16*)&lo)[0] = l0; ((__nv_bfloat16*)&lo)[1] = l1;
    return hi;
}

// =====================================================================
// Dense 2-term GEMM: C = act((Ah+Al) @ Bh^T + bias)
// A pair (M,K) row-major; B hi-only (N,K) row-major. BM=128, BN=128, BK=64.
// OUTMODE 0: fp32 C; 1: bf16 pair Ch/Cl.
// =====================================================================
template<int ACT, int OUTMODE>
__global__ void __launch_bounds__(256, 1)
mma_gemm(const __nv_bfloat16* __restrict__ Ah, const __nv_bfloat16* __restrict__ Al,
         const __nv_bfloat16* __restrict__ Bh,
         const float* __restrict__ bias,
         float* __restrict__ Cf, __nv_bfloat16* __restrict__ Ch, __nv_bfloat16* __restrict__ Cl,
         int K, int lda, int ldb, int ldc)
{
    extern __shared__ __align__(16) char sm[];
    constexpr int ROWB = 144;              // 64 bf16 + 8 pad
    constexpr int B_OFF = 256 * ROWB;
    constexpr int STAGE = 384 * ROWB;      // 55296

    const int tid = threadIdx.x;
    const int wid = tid >> 5, lane = tid & 31;
    const int warp_m = wid >> 1, warp_n = wid & 1;
    const int m0 = blockIdx.x * 128;
    const int n0 = blockIdx.y * 128;
    const uint32_t smem_base = smem_u32(sm);
    const int nch = K >> 6;

    float acc[2][8][4];
    #pragma unroll
    for (int a = 0; a < 2; a++)
        #pragma unroll
        for (int b = 0; b < 8; b++)
            #pragma unroll
            for (int c = 0; c < 4; c++) acc[a][b][c] = 0.f;

    auto load_stage = [&](int stage, int ch) {
        const int k0 = ch << 6;
        const uint32_t sbase = smem_base + stage * STAGE;
        #pragma unroll
        for (int i = tid; i < 2048; i += 256) {
            int hl = i >> 10, idx = i & 1023, row = idx >> 3, seg = idx & 7;
            const __nv_bfloat16* g = (hl ? Al : Ah) + (long)(m0 + row) * lda + k0 + seg * 8;
            cp_async16(sbase + (hl * 128 + row) * ROWB + seg * 16, g);
        }
        #pragma unroll
        for (int i = tid; i < 1024; i += 256) {
            int row = i >> 3, seg = i & 7;
            const __nv_bfloat16* g = Bh + (long)(n0 + row) * ldb + k0 + seg * 8;
            cp_async16(sbase + B_OFF + row * ROWB + seg * 16, g);
        }
        cp_commit();
    };

    auto compute = [&](int stage) {
        const uint32_t sbase = smem_base + stage * STAGE;
        const int arow = warp_m * 32 + (lane & 15);
        const int bn   = (lane & 7) + (lane >> 4) * 8;
        const int bka  = ((lane >> 3) & 1) * 8;
        #pragma unroll
        for (int kk = 0; kk < 4; kk++) {
            const int acol = kk * 16 + (lane >> 4) * 8;
            uint32_t ah[2][4], al[2][4];
            #pragma unroll
            for (int mt = 0; mt < 2; mt++) {
                ldsm_x4(ah[mt], sbase + (arow + mt * 16) * ROWB + acol * 2);
                ldsm_x4(al[mt], sbase + (128 + arow + mt * 16) * ROWB + acol * 2);
            }
            const int bk = kk * 16 + bka;
            #pragma unroll
            for (int nt2 = 0; nt2 < 4; nt2++) {
                uint32_t bh[4];
                ldsm_x4(bh, sbase + B_OFF + (warp_n * 64 + nt2 * 16 + bn) * ROWB + bk * 2);
                #pragma unroll
                for (int mt = 0; mt < 2; mt++) {
                    #pragma unroll
                    for (int j = 0; j < 2; j++) {
                        mma16816(acc[mt][nt2 * 2 + j], ah[mt], bh[2 * j], bh[2 * j + 1]);
                        mma16816(acc[mt][nt2 * 2 + j], al[mt], bh[2 * j], bh[2 * j + 1]);
                    }
                }
            }
        }
    };

    load_stage(0, 0);
    for (int ch = 0; ch < nch; ch++) {
        if (ch + 1 < nch) { load_stage((ch + 1) & 1, ch + 1); cp_wait<1>(); }
        else cp_wait<0>();
        __syncthreads();
        compute(ch & 1);
        __syncthreads();
    }

    const int r0 = lane >> 2, c0 = (lane & 3) * 2;
    #pragma unroll
    for (int mt = 0; mt < 2; mt++) {
        #pragma unroll
        for (int nt = 0; nt < 8; nt++) {
            const int n = n0 + warp_n * 64 + nt * 8 + c0;
            float bv0 = bias ? bias[n] : 0.f;
            float bv1 = bias ? bias[n + 1] : 0.f;
            #pragma unroll
            for (int hrow = 0; hrow < 2; hrow++) {
                const int m = m0 + warp_m * 32 + mt * 16 + r0 + hrow * 8;
                float f0 = acc[mt][nt][hrow * 2 + 0] + bv0;
                float f1 = acc[mt][nt][hrow * 2 + 1] + bv1;
                if (ACT == 1) { f0 = gelu_exact(f0); f1 = gelu_exact(f1); }
                const long off = (long)m * ldc + n;
                if (OUTMODE == 0) {
                    *(float2*)(Cf + off) = make_float2(f0, f1);
                } else {
                    uint32_t lo;
                    uint32_t hi = pack_pair_h(f0, f1, lo);
                    *(uint32_t*)(Ch + off) = hi;
                    *(uint32_t*)(Cl + off) = lo;
                }
            }
        }
    }
}

// =====================================================================
// Flash attention: per CTA = (q-tile of 128, one (b,h)). 8 warps x 16 rows.
// K/V chunks of 64 keys, double-buffered cp.async. QK & PV 3-term split.
// Masking: keys<LX gated by x_mask (all queries); keys>=LX causal (k<=q).
// =====================================================================
__global__ void __launch_bounds__(256, 1)
flash_kernel()
{
    extern __shared__ __align__(16) char fsm[];
    __shared__ uint32_t maskbits[16];
    constexpr int ROWB = 144;              // 64 bf16 + 8 pad
    constexpr int QH_OFF = 0;
    constexpr int QL_OFF = 128 * ROWB;
    constexpr int KV_OFF = 2 * 128 * ROWB;
    constexpr int TILE = 64 * ROWB;        // 9216
    constexpr int KSTAGE = 4 * TILE;       // Kh,Kl,Vh,Vl

    const int bh = blockIdx.y;
    const int b = bh >> 4, h = bh & 15;
    const int q0 = blockIdx.x * 128;
    const int tid = threadIdx.x;
    const int wid = tid >> 5, lane = tid & 31;
    const uint32_t smem = smem_u32(fsm);

    if (tid < 16) {
        uint32_t m = 0;
        const int* xm = g_xmask + b * LX + tid * 32;
        #pragma unroll
        for (int i = 0; i < 32; i++) m |= (xm[i] ? 1u : 0u) << i;
        maskbits[tid] = m;
    }

    // load Q (pair)
    #pragma unroll
    for (int i = tid; i < 2048; i += 256) {
        int hl = i >> 10, idx = i & 1023, row = idx >> 3, seg = idx & 7;
        const __nv_bfloat16* src = (hl ? g_qkv_l : g_qkv_h) +
            ((size_t)(b * SS + q0 + row)) * (3 * DD) + h * 64 + seg * 8;
        cp_async16(smem + (hl ? QL_OFF : QH_OFF) + row * ROWB + seg * 16, src);
    }
    cp_commit();

    const int nch = (q0 < LX) ? 8 : ((q0 + 128) >> 6);

    auto load_kv = [&](int c, int s) {
        const int k0 = c << 6;
        const uint32_t sb = smem + KV_OFF + s * KSTAGE;
        #pragma unroll
        for (int i = tid; i < 1024; i += 256) {
            int hl = i >> 9, idx = i & 511, row = idx >> 3, seg = idx & 7;
            const __nv_bfloat16* src = (hl ? g_qkv_l : g_qkv_h) +
                ((size_t)(b * SS + k0 + row)) * (3 * DD) + DD + h * 64 + seg * 8;
            cp_async16(sb + hl * TILE + row * ROWB + seg * 16, src);
        }
        #pragma unroll
        for (int i = tid; i < 1024; i += 256) {
            int hl = i >> 9, idx = i & 511, row = idx >> 3, seg = idx & 7;
            const __nv_bfloat16* src = (hl ? g_vT_l : g_vT_h) +
                ((size_t)((b * NH + h) * HD + row)) * SS + k0 + seg * 8;
            cp_async16(sb + (2 + hl) * TILE + row * ROWB + seg * 16, src);
        }
        cp_commit();
    };

    load_kv(0, 0);

    float m_[2] = {-1e30f, -1e30f}, l_[2] = {0.f, 0.f};
    float out[8][4];
    #pragma unroll
    for (int j = 0; j < 8; j++)
        #pragma unroll
        for (int e = 0; e < 4; e++) out[j][e] = 0.f;

    const int r0 = lane >> 2;
    const int qrow0 = q0 + wid * 16 + r0;      // second row = qrow0 + 8
    const int arow = wid * 16 + (lane & 15);
    const int bn   = (lane & 7) + (lane >> 4) * 8;
    const int bka  = ((lane >> 3) & 1) * 8;

    for (int c = 0; c < nch; c++) {
        if (c + 1 < nch) { load_kv(c + 1, (c + 1) & 1); cp_wait<1>(); }
        else cp_wait<0>();
        __syncthreads();
        const uint32_t sb = smem + KV_OFF + (c & 1) * KSTAGE;

        // ---- QK (3-term) ----
        float s[8][4];
        #pragma unroll
        for (int j = 0; j < 8; j++)
            #pragma unroll
            for (int e = 0; e < 4; e++) s[j][e] = 0.f;
        #pragma unroll
        for (int t = 0; t < 4; t++) {
            const int acol = t * 16 + (lane >> 4) * 8;
            uint32_t qh[4], ql[4];
            ldsm_x4(qh, smem + QH_OFF + arow * ROWB + acol * 2);
            ldsm_x4(ql, smem + QL_OFF + arow * ROWB + acol * 2);
            const int bk = t * 16 + bka;
            #pragma unroll
            for (int j = 0; j < 4; j++) {
                uint32_t kh[4], kl[4];
                uint32_t baddr = sb + (j * 16 + bn) * ROWB + bk * 2;
                ldsm_x4(kh, baddr);
                ldsm_x4(kl, baddr + TILE);
                mma16816(s[2 * j], qh, kh[0], kh[1]);
                mma16816(s[2 * j], qh, kl[0], kl[1]);
                mma16816(s[2 * j], ql, kh[0], kh[1]);
                mma16816(s[2 * j + 1], qh, kh[2], kh[3]);
                mma16816(s[2 * j + 1], qh, kl[2], kl[3]);
                mma16816(s[2 * j + 1], ql, kh[2], kh[3]);
            }
        }

        // ---- mask + online softmax ----
        const int k0 = c << 6;
        uint32_t vmask = 0;
        float cmax[2] = {-1e30f, -1e30f};
        #pragma unroll
        for (int j = 0; j < 8; j++) {
            #pragma unroll
            for (int e = 0; e < 4; e++) {
                int col = k0 + j * 8 + (lane & 3) * 2 + (e & 1);
                int row = (e < 2) ? qrow0 : (qrow0 + 8);
                bool valid = (col < LX) ? !((maskbits[col >> 5] >> (col & 31)) & 1)
                                        : (col <= row);
                float sv = s[j][e] * 0.125f;
                s[j][e] = sv;
                if (valid) {
                    vmask |= 1u << (j * 4 + e);
                    cmax[e >> 1] = fmaxf(cmax[e >> 1], sv);
                }
            }
        }
        #pragma unroll
        for (int o = 1; o <= 2; o <<= 1) {
            cmax[0] = fmaxf(cmax[0], __shfl_xor_sync(0xffffffffu, cmax[0], o));
            cmax[1] = fmaxf(cmax[1], __shfl_xor_sync(0xffffffffu, cmax[1], o));
        }
        float mn0 = fmaxf(m_[0], cmax[0]);
        float mn1 = fmaxf(m_[1], cmax[1]);
        float f0 = __expf(m_[0] - mn0);
        float f1 = __expf(m_[1] - mn1);
        float rs[2] = {0.f, 0.f};
        #pragma unroll
        for (int j = 0; j < 8; j++) {
            #pragma unroll
            for (int e = 0; e < 4; e++) {
                float mn = (e < 2) ? mn0 : mn1;
                float p = ((vmask >> (j * 4 + e)) & 1) ? __expf(s[j][e] - mn) : 0.f;
                s[j][e] = p;
                rs[e >> 1] += p;
            }
        }
        #pragma unroll
        for (int o = 1; o <= 2; o <<= 1) {
            rs[0] += __shfl_xor_sync(0xffffffffu, rs[0], o);
            rs[1] += __shfl_xor_sync(0xffffffffu, rs[1], o);
        }
        l_[0] = l_[0] * f0 + rs[0];
        l_[1] = l_[1] * f1 + rs[1];
        m_[0] = mn0; m_[1] = mn1;
        #pragma unroll
        for (int j = 0; j < 8; j++) {
            out[j][0] *= f0; out[j][1] *= f0;
            out[j][2] *= f1; out[j][3] *= f1;
        }

        // ---- PV (3-term), interleaved P-frag build per k-step ----
        #pragma unroll
        for (int t = 0; t < 4; t++) {
            uint32_t ph[4], pl[4];
            {
                uint32_t lo;
                ph[0] = pack_pair_h(s[2 * t][0], s[2 * t][1], lo);     pl[0] = lo;
                ph[1] = pack_pair_h(s[2 * t][2], s[2 * t][3], lo);     pl[1] = lo;
                ph[2] = pack_pair_h(s[2 * t + 1][0], s[2 * t + 1][1], lo); pl[2] = lo;
                ph[3] = pack_pair_h(s[2 * t + 1][2], s[2 * t + 1][3], lo); pl[3] = lo;
            }
            const int bk = t * 16 + bka;
            #pragma unroll
            for (int j = 0; j < 4; j++) {
                uint32_t vh[4], vl[4];
                uint32_t baddr = sb + 2 * TILE + (j * 16 + bn) * ROWB + bk * 2;
                ldsm_x4(vh, baddr);
                ldsm_x4(vl, baddr + TILE);
                mma16816(out[2 * j], ph, vh[0], vh[1]);
                mma16816(out[2 * j], ph, vl[0], vl[1]);
                mma16816(out[2 * j], pl, vh[0], vh[1]);
                mma16816(out[2 * j + 1], ph, vh[2], vh[3]);
                mma16816(out[2 * j + 1], ph, vl[2], vl[3]);
                mma16816(out[2 * j + 1], pl, vh[2], vh[3]);
            }
        }
        __syncthreads();
    }

    // ---- epilogue: normalize + write attno pair (token-major) ----
    float inv0 = 1.f / l_[0];
    float inv1 = 1.f / l_[1];
    #pragma unroll
    for (int j = 0; j < 8; j++) {
        const int d = h * 64 + j * 8 + (lane & 3) * 2;
        {
            const size_t off = ((size_t)(b * SS + qrow0)) * DD + d;
            uint32_t lo;
            uint32_t hi = pack_pair_h(out[j][0] * inv0, out[j][1] * inv0, lo);
            *(uint32_t*)(g_attno_h + off) = hi;
            *(uint32_t*)(g_attno_l + off) = lo;
        }
        {
            const size_t off = ((size_t)(b * SS + qrow0 + 8)) * DD + d;
            uint32_t lo;
            uint32_t hi = pack_pair_h(out[j][2] * inv1, out[j][3] * inv1, lo);
            *(uint32_t*)(g_attno_h + off) = hi;
            *(uint32_t*)(g_attno_l + off) = lo;
        }
    }
}

// ---------------- fp32 -> bf16 (hi only, for weights) ----------------
__global__ void cvt_h_kernel(const float* __restrict__ src,
                             __nv_bfloat16* __restrict__ h, long n4)
{
    long i = (long)blockIdx.x * blockDim.x + threadIdx.x;
    if (i >= n4) return;
    float4 v = *(const float4*)(src + i * 4);
    uint2 hv;
    __nv_bfloat16* hp = (__nv_bfloat16*)&hv;
    hp[0] = __float2bfloat16(v.x);
    hp[1] = __float2bfloat16(v.y);
    hp[2] = __float2bfloat16(v.z);
    hp[3] = __float2bfloat16(v.w);
    *(uint2*)(h + i * 4) = hv;
}

// ---------------- V transpose: qkv pair -> vT pair [b][h][d][t] ----------------
__global__ void vT_kernel()
{
    __shared__ __nv_bfloat16 th[32][33];
    __shared__ __nv_bfloat16 tl[32][33];
    int z = blockIdx.z;
    int b = z / NH, h = z % NH;
    int t0 = blockIdx.x * 32;
    int d0 = blockIdx.y * 32;
    int tx = threadIdx.x, ty = threadIdx.y;  // 32 x 8
    #pragma unroll
    for (int i = 0; i < 4; i++) {
        int t = t0 + ty + i * 8;
        int d = d0 + tx;
        size_t src = ((size_t)(b * SS + t)) * (3 * DD) + 2 * DD + h * 64 + d;
        th[ty + i * 8][tx] = g_qkv_h[src];
        tl[ty + i * 8][tx] = g_qkv_l[src];
    }
    __syncthreads();
    #pragma unroll
    for (int i = 0; i < 4; i++) {
        int d = d0 + ty + i * 8;
        int t = t0 + tx;
        size_t dst = ((size_t)((b * NH + h) * HD + d)) * SS + t;
        g_vT_h[dst] = th[tx][ty + i * 8];
        g_vT_l[dst] = tl[tx][ty + i * 8];
    }
}

// ---------------- embedding: x tokens ----------------
__global__ void embed_x_kernel(const float* __restrict__ x,
                               const float* __restrict__ W_nail,
                               const float* __restrict__ b_nail)
{
    const float RSC = 0.99995000374968753f;
    int row = blockIdx.x;
    int b = row / LX;
    const float* xr = x + (long)row * 64;
    __shared__ float xn[63];
    __shared__ float t_sh;
    int tid = threadIdx.x;
    if (tid == 0) {
        float t0 = xr[0];
        g_xmask[row] = isnan(t0) ? 1 : 0;
        t_sh = isnan(t0) ? 0.f : t0;
    }
    if (tid < 63) {
        float v = xr[tid + 1];
        if (isnan(v)) v = 0.f;
        v *= RSC;
        xn[tid] = fminf(fmaxf(v, -5.f), 5.f);
    }
    __syncthreads();
    float t = t_sh;
    const float kfac = -logf(1000.f) / 1024.f;
    for (int d = tid; d < DD; d += 256) {
        const float* wr = W_nail + d * 63;
        float acc = b_nail[d];
        #pragma unroll 7
        for (int c = 0; c < 63; c++) acc = fmaf(xn[c], wr[c], acc);
        int i = d >> 1;
        float ang = t * expf((float)i * kfac);
        acc += (d & 1) ? cosf(ang) : sinf(ang);
        size_t idx = ((size_t)b * SS + (row % LX)) * DD + d;
        g_tgt[idx] = acc;
        __nv_bfloat16 hh = __float2bfloat16(acc);
        g_tgt_h[idx] = hh;
        g_tgt_l[idx] = __float2bfloat16(acc - __bfloat162float(hh));
    }
}

// ---------------- embedding: w tokens + global PE ----------------
__global__ void embed_w_kernel(const float* __restrict__ w,
                               const float* __restrict__ W_cond,
                               const float* __restrict__ b_cond)
{
    const float RSC = 0.99995000374968753f;
    int row = blockIdx.x;
    int b = row / NWTOK, r = row % NWTOK;
    const float* wr6 = w + (long)b * (NWTOK * 6) + r * 6;
    __shared__ float wn[6];
    int tid = threadIdx.x;
    if (tid < 6) {
        float v = wr6[tid];
        if (isnan(v)) v = 0.f;
        v *= RSC;
        wn[tid] = fminf(fmaxf(v, -5.f), 5.f);
    }
    __syncthreads();
    int spos = LX + r;
    const float kfac = -logf(1000.f) / 1024.f;
    for (int d = tid; d < DD; d += 256) {
        const float* wc = W_cond + d * 6;
        float acc = b_cond[d];
        #pragma unroll
        for (int c = 0; c < 6; c++) acc = fmaf(wn[c], wc[c], acc);
        int i = d >> 1;
        float ang = (float)spos * expf((float)i * kfac);
        acc += (d & 1) ? cosf(ang) : sinf(ang);
        size_t idx = ((size_t)b * SS + spos) * DD + d;
        g_tgt[idx] = acc;
        __nv_bfloat16 hh = __float2bfloat16(acc);
        g_tgt_h[idx] = hh;
        g_tgt_l[idx] = __float2bfloat16(acc - __bfloat162float(hh));
    }
}

// ---------------- residual add + LayerNorm (in-place, emits bf16 pair) ----------------
__global__ void resid_ln_kernel(const float* __restrict__ delta,
                                const float* __restrict__ g,
                                const float* __restrict__ beta)
{
    size_t row = blockIdx.x;
    float* t = g_tgt + row * DD;
    const float* dl = delta + row * DD;
    int tid = threadIdx.x;
    float v[4];
    float s = 0.f;
    #pragma unroll
    for (int i = 0; i < 4; i++) { int idx = tid + i * 256; v[i] = t[idx] + dl[idx]; s += v[i]; }
    __shared__ float red[256];
    red[tid] = s; __syncthreads();
    #pragma unroll
    for (int o = 128; o > 0; o >>= 1) { if (tid < o) red[tid] += red[tid + o]; __syncthreads(); }
    float mean = red[0] * (1.f / 1024.f);
    __syncthreads();
    float s2 = 0.f;
    #pragma unroll
    for (int i = 0; i < 4; i++) { float d = v[i] - mean; s2 += d * d; }
    red[tid] = s2; __syncthreads();
    #pragma unroll
    for (int o = 128; o > 0; o >>= 1) { if (tid < o) red[tid] += red[tid + o]; __syncthreads(); }
    float inv = rsqrtf(red[0] * (1.f / 1024.f) + 1e-5f);
    #pragma unroll
    for (int i = 0; i < 4; i++) {
        int idx = tid + i * 256;
        float out = (v[i] - mean) * inv * g[idx] + beta[idx];
        t[idx] = out;
        __nv_bfloat16 hh = __float2bfloat16(out);
        g_tgt_h[row * DD + idx] = hh;
        g_tgt_l[row * DD + idx] = __float2bfloat16(out - __bfloat162float(hh));
    }
}

// ---------------- head + loss ----------------
__global__ void loss_kernel(const float* __restrict__ W_ham, const float* __restrict__ b_ham,
                            const float* __restrict__ y, const float* __restrict__ w,
                            float* __restrict__ out)
{
    __shared__ float red[256];
    int tid = threadIdx.x;
    float acc = 0.f;
    for (int idx = tid; idx < BB * 144; idx += 256) {
        int b = idx / 144;
        int j = idx % 144;
        const float* row = g_tgt + ((size_t)b * SS + (SS - 1)) * DD;
        const float* wr = W_ham + (size_t)j * DD;
        float dot = b_ham[j];
        for (int k = 0; k < DD; k++) dot = fmaf(row[k], wr[k], dot);
        float yr = y[b * 144 + j] - w[(size_t)b * 2304 + 2160 + j];
        float d = dot - yr;
        acc += d * d;
    }
    red[tid] = acc; __syncthreads();
    #pragma unroll
    for (int o = 128; o > 0; o >>= 1) { if (tid < o) red[tid] += red[tid + o]; __syncthreads(); }
    if (tid == 0) out[0] = red[0] / (float)(BB * 144);
}

// ---------------- launch ----------------
extern "C" void kernel_launch(void* const* d_in, const int* in_sizes, int n_in,
                              void* d_out, int out_size)
{
    const float* x      = (const float*)d_in[0];
    const float* w      = (const float*)d_in[1];
    const float* y      = (const float*)d_in[2];
    const float* W_nail = (const float*)d_in[3];
    const float* b_nail = (const float*)d_in[4];
    const float* W_cond = (const float*)d_in[5];
    const float* b_cond = (const float*)d_in[6];
    const float* Wqkv   = (const float*)d_in[7];
    const float* bqkv   = (const float*)d_in[8];
    const float* Wo     = (const float*)d_in[9];
    const float* bo     = (const float*)d_in[10];
    const float* ln1_g  = (const float*)d_in[11];
    const float* ln1_b  = (const float*)d_in[12];
    const float* ln2_g  = (const float*)d_in[13];
    const float* ln2_b  = (const float*)d_in[14];
    const float* W1     = (const float*)d_in[15];
    const float* b1     = (const float*)d_in[16];
    const float* W2     = (const float*)d_in[17];
    const float* b2     = (const float*)d_in[18];
    const float* W_ham  = (const float*)d_in[19];
    const float* b_ham  = (const float*)d_in[20];

    float *p_tgt, *p_tmp;
    __nv_bfloat16 *p_tgt_h, *p_tgt_l, *p_qkv_h, *p_qkv_l;
    __nv_bfloat16 *p_attno_h, *p_attno_l, *p_hid_h, *p_hid_l;
    __nv_bfloat16 *p_wqkv_h, *p_wo_h, *p_w1_h, *p_w2_h;
    cudaGetSymbolAddress((void**)&p_tgt,    g_tgt);
    cudaGetSymbolAddress((void**)&p_tmp,    g_tmp);
    cudaGetSymbolAddress((void**)&p_tgt_h,  g_tgt_h);
    cudaGetSymbolAddress((void**)&p_tgt_l,  g_tgt_l);
    cudaGetSymbolAddress((void**)&p_qkv_h,  g_qkv_h);
    cudaGetSymbolAddress((void**)&p_qkv_l,  g_qkv_l);
    cudaGetSymbolAddress((void**)&p_attno_h, g_attno_h);
    cudaGetSymbolAddress((void**)&p_attno_l, g_attno_l);
    cudaGetSymbolAddress((void**)&p_hid_h,  g_hid_h);
    cudaGetSymbolAddress((void**)&p_hid_l,  g_hid_l);
    cudaGetSymbolAddress((void**)&p_wqkv_h, g_wqkv_h);
    cudaGetSymbolAddress((void**)&p_wo_h,   g_wo_h);
    cudaGetSymbolAddress((void**)&p_w1_h,   g_w1_h);
    cudaGetSymbolAddress((void**)&p_w2_h,   g_w2_h);

    static const int SMG = 384 * 144 * 2;                       // 110592 dense
    static const int SMF = 2 * 128 * 144 + 2 * 4 * 64 * 144;    // 110592 flash
    cudaFuncSetAttribute(mma_gemm<0, 0>, cudaFuncAttributeMaxDynamicSharedMemorySize, SMG);
    cudaFuncSetAttribute(mma_gemm<0, 1>, cudaFuncAttributeMaxDynamicSharedMemorySize, SMG);
    cudaFuncSetAttribute(mma_gemm<1, 1>, cudaFuncAttributeMaxDynamicSharedMemorySize, SMG);
    cudaFuncSetAttribute(flash_kernel,   cudaFuncAttributeMaxDynamicSharedMemorySize, SMF);

    const int M = BB * SS;   // 7168
    dim3 blk(256);

    // weight conversions (hi only)
    {
        long n;
        n = (long)NLAYER * 3 * DD * DD / 4;
        cvt_h_kernel<<<(unsigned)((n + 255) / 256), blk>>>(Wqkv, p_wqkv_h, n);
        n = (long)NLAYER * DD * DD / 4;
        cvt_h_kernel<<<(unsigned)((n + 255) / 256), blk>>>(Wo, p_wo_h, n);
        n = (long)NLAYER * FFD * DD / 4;
        cvt_h_kernel<<<(unsigned)((n + 255) / 256), blk>>>(W1, p_w1_h, n);
        n = (long)NLAYER * DD * FFD / 4;
        cvt_h_kernel<<<(unsigned)((n + 255) / 256), blk>>>(W2, p_w2_h, n);
    }

    embed_x_kernel<<<BB * LX, blk>>>(x, W_nail, b_nail);
    embed_w_kernel<<<BB * NWTOK, blk>>>(w, W_cond, b_cond);

    for (int l = 0; l < NLAYER; l++) {
        const __nv_bfloat16* wqkv_h = p_wqkv_h + (size_t)l * 3 * DD * DD;
        const __nv_bfloat16* wo_h   = p_wo_h + (size_t)l * DD * DD;
        const __nv_bfloat16* w1_h   = p_w1_h + (size_t)l * FFD * DD;
        const __nv_bfloat16* w2_h   = p_w2_h + (size_t)l * DD * FFD;

        // QKV: (7168 x 3072 x 1024) -> bf16 pair
        mma_gemm<0, 1><<<dim3(M / 128, 3 * DD / 128), blk, SMG>>>(
            p_tgt_h, p_tgt_l, wqkv_h, bqkv + (size_t)l * 3 * DD,
            nullptr, p_qkv_h, p_qkv_l, DD, DD, DD, 3 * DD);

        // V transpose
        vT_kernel<<<dim3(SS / 32, HD / 32, BB * NH), dim3(32, 8)>>>();

        // flash attention -> attno pair
        flash_kernel<<<dim3(SS / 128, BB * NH), blk, SMF>>>();

        // tmp = attno @ Wo^T + bo  -> fp32
        mma_gemm<0, 0><<<dim3(M / 128, DD / 128), blk, SMG>>>(
            p_attno_h, p_attno_l, wo_h, bo + (size_t)l * DD,
            p_tmp, nullptr, nullptr, DD, DD, DD, DD);

        resid_ln_kernel<<<M, blk>>>(p_tmp, ln1_g + (size_t)l * DD, ln1_b + (size_t)l * DD);

        // hid = gelu(tgt @ W1^T + b1) -> bf16 pair
        mma_gemm<1, 1><<<dim3(M / 128, FFD / 128), blk, SMG>>>(
            p_tgt_h, p_tgt_l, w1_h, b1 + (size_t)l * FFD,
            nullptr, p_hid_h, p_hid_l, DD, DD, DD, FFD);

        // tmp = hid @ W2^T + b2 -> fp32
        mma_gemm<0, 0><<<dim3(M / 128, DD / 128), blk, SMG>>>(
            p_hid_h, p_hid_l, w2_h, b2 + (size_t)l * DD,
            p_tmp, nullptr, nullptr, FFD, FFD, FFD, DD);

        resid_ln_kernel<<<M, blk>>>(p_tmp, ln2_g + (size_t)l * DD, ln2_b + (size_t)l * DD);
    }

    loss_kernel<<<1, blk>>>(W_ham, b_ham, y, w, (float*)d_out);
}

// round 5
// speedup vs baseline: 8.9801x; 1.7569x over previous
#include <cuda_runtime.h>
#include <cuda_fp16.h>
#include <math.h>
#include <stdint.h>

// Problem dims (fixed by setup_inputs)
#define BB 8
#define LX 512
#define NWTOK 384
#define SS 896
#define DD 1024
#define NH 16
#define HD 64
#define FFD 4096
#define NLAYER 4

// ---------------- scratch (device globals) ----------------
__device__ float g_tgt[BB * SS * DD];
__device__ __half g_tgt_s[BB * SS * DD];
__device__ __half g_qkv[(size_t)BB * SS * 3 * DD];
__device__ __half g_vT[(size_t)BB * DD * SS];
__device__ __half g_attno[(size_t)BB * SS * DD];
__device__ __half g_hid[(size_t)BB * SS * FFD];
__device__ float g_tmp[BB * SS * DD];
__device__ int   g_xmask[BB * LX];
// weights fp16
__device__ __half g_wqkv[(size_t)NLAYER * 3 * DD * DD];
__device__ __half g_wo[(size_t)NLAYER * DD * DD];
__device__ __half g_w1[(size_t)NLAYER * FFD * DD];
__device__ __half g_w2[(size_t)NLAYER * DD * FFD];

// ---------------- helpers ----------------
__device__ __forceinline__ uint32_t smem_u32(const void* p) {
    uint32_t a;
    asm("{ .reg .u64 t; cvta.to.shared.u64 t, %1; cvt.u32.u64 %0, t; }" : "=r"(a) : "l"(p));
    return a;
}
__device__ __forceinline__ void cp_async16(uint32_t saddr, const void* gaddr) {
    asm volatile("cp.async.cg.shared.global [%0], [%1], 16;" :: "r"(saddr), "l"(gaddr));
}
__device__ __forceinline__ void cp_commit() {
    asm volatile("cp.async.commit_group;" ::: "memory");
}
template<int N>
__device__ __forceinline__ void cp_wait() {
    asm volatile("cp.async.wait_group %0;" :: "n"(N) : "memory");
}
__device__ __forceinline__ void ldsm_x4(uint32_t (&r)[4], uint32_t addr) {
    asm volatile("ldmatrix.sync.aligned.m8n8.x4.shared.b16 {%0,%1,%2,%3}, [%4];"
        : "=r"(r[0]), "=r"(r[1]), "=r"(r[2]), "=r"(r[3]) : "r"(addr));
}
__device__ __forceinline__ void mma16816(float (&d)[4], const uint32_t (&a)[4],
                                         uint32_t b0, uint32_t b1) {
    asm volatile("mma.sync.aligned.m16n8k16.row.col.f32.f16.f16.f32 "
        "{%0,%1,%2,%3}, {%4,%5,%6,%7}, {%8,%9}, {%0,%1,%2,%3};"
        : "+f"(d[0]), "+f"(d[1]), "+f"(d[2]), "+f"(d[3])
        : "r"(a[0]), "r"(a[1]), "r"(a[2]), "r"(a[3]), "r"(b0), "r"(b1));
}
__device__ __forceinline__ float gelu_exact(float x) {
    return 0.5f * x * (1.0f + erff(x * 0.70710678118654752f));
}
__device__ __forceinline__ uint32_t pack_h2(float f0, float f1) {
    __half2 h = __floats2half2_rn(f0, f1);
    return *(uint32_t*)&h;
}

// =====================================================================
// Dense fp16 GEMM: C = act(A @ B^T + bias)
// A (M,K) half row-major; B (N,K) half row-major. BM=128, BN=128, BK=64.
// OUTMODE 0: fp32 C; 1: half C.
// =====================================================================
template<int ACT, int OUTMODE>
__global__ void __launch_bounds__(256, 2)
mma_gemm(const __half* __restrict__ A, const __half* __restrict__ B,
         const float* __restrict__ bias,
         float* __restrict__ Cf, __half* __restrict__ Ch,
         int K, int lda, int ldb, int ldc)
{
    extern __shared__ __align__(16) char sm[];
    constexpr int ROWB = 144;              // 64 half + 16B pad
    constexpr int B_OFF = 128 * ROWB;
    constexpr int STAGE = 256 * ROWB;      // 36864

    const int tid = threadIdx.x;
    const int wid = tid >> 5, lane = tid & 31;
    const int warp_m = wid >> 1, warp_n = wid & 1;
    const int m0 = blockIdx.x * 128;
    const int n0 = blockIdx.y * 128;
    const uint32_t smem_base = smem_u32(sm);
    const int nch = K >> 6;

    float acc[2][8][4];
    #pragma unroll
    for (int a = 0; a < 2; a++)
        #pragma unroll
        for (int b = 0; b < 8; b++)
            #pragma unroll
            for (int c = 0; c < 4; c++) acc[a][b][c] = 0.f;

    auto load_stage = [&](int stage, int ch) {
        const int k0 = ch << 6;
        const uint32_t sbase = smem_base + stage * STAGE;
        #pragma unroll
        for (int i = tid; i < 1024; i += 256) {
            int row = i >> 3, seg = i & 7;
            cp_async16(sbase + row * ROWB + seg * 16,
                       A + (long)(m0 + row) * lda + k0 + seg * 8);
        }
        #pragma unroll
        for (int i = tid; i < 1024; i += 256) {
            int row = i >> 3, seg = i & 7;
            cp_async16(sbase + B_OFF + row * ROWB + seg * 16,
                       B + (long)(n0 + row) * ldb + k0 + seg * 8);
        }
        cp_commit();
    };

    auto compute = [&](int stage) {
        const uint32_t sbase = smem_base + stage * STAGE;
        const int arow = warp_m * 32 + (lane & 15);
        const int bn   = (lane & 7) + (lane >> 4) * 8;
        const int bka  = ((lane >> 3) & 1) * 8;
        #pragma unroll
        for (int kk = 0; kk < 4; kk++) {
            const int acol = kk * 16 + (lane >> 4) * 8;
            uint32_t af[2][4];
            #pragma unroll
            for (int mt = 0; mt < 2; mt++)
                ldsm_x4(af[mt], sbase + (arow + mt * 16) * ROWB + acol * 2);
            const int bk = kk * 16 + bka;
            #pragma unroll
            for (int nt2 = 0; nt2 < 4; nt2++) {
                uint32_t bf[4];
                ldsm_x4(bf, sbase + B_OFF + (warp_n * 64 + nt2 * 16 + bn) * ROWB + bk * 2);
                #pragma unroll
                for (int mt = 0; mt < 2; mt++) {
                    #pragma unroll
                    for (int j = 0; j < 2; j++)
                        mma16816(acc[mt][nt2 * 2 + j], af[mt], bf[2 * j], bf[2 * j + 1]);
                }
            }
        }
    };

    load_stage(0, 0);
    for (int ch = 0; ch < nch; ch++) {
        if (ch + 1 < nch) { load_stage((ch + 1) & 1, ch + 1); cp_wait<1>(); }
        else cp_wait<0>();
        __syncthreads();
        compute(ch & 1);
        __syncthreads();
    }

    const int r0 = lane >> 2, c0 = (lane & 3) * 2;
    #pragma unroll
    for (int mt = 0; mt < 2; mt++) {
        #pragma unroll
        for (int nt = 0; nt < 8; nt++) {
            const int n = n0 + warp_n * 64 + nt * 8 + c0;
            float bv0 = bias ? bias[n] : 0.f;
            float bv1 = bias ? bias[n + 1] : 0.f;
            #pragma unroll
            for (int hrow = 0; hrow < 2; hrow++) {
                const int m = m0 + warp_m * 32 + mt * 16 + r0 + hrow * 8;
                float f0 = acc[mt][nt][hrow * 2 + 0] + bv0;
                float f1 = acc[mt][nt][hrow * 2 + 1] + bv1;
                if (ACT == 1) { f0 = gelu_exact(f0); f1 = gelu_exact(f1); }
                const long off = (long)m * ldc + n;
                if (OUTMODE == 0) *(float2*)(Cf + off) = make_float2(f0, f1);
                else              *(uint32_t*)(Ch + off) = pack_h2(f0, f1);
            }
        }
    }
}

// =====================================================================
// Flash attention (fp16): per CTA = (q-tile 128, one (b,h)). 8 warps x 16 rows.
// 64-key chunks double-buffered. keys<LX gated by x_mask; keys>=LX causal.
// =====================================================================
__global__ void __launch_bounds__(256, 2)
flash_kernel()
{
    extern __shared__ __align__(16) char fsm[];
    __shared__ uint32_t maskbits[16];
    constexpr int ROWB = 144;
    constexpr int KV_OFF = 128 * ROWB;     // after Q
    constexpr int TILE = 64 * ROWB;        // 9216
    constexpr int KSTAGE = 2 * TILE;       // K,V

    const int bh = blockIdx.y;
    const int b = bh >> 4, h = bh & 15;
    const int q0 = blockIdx.x * 128;
    const int tid = threadIdx.x;
    const int wid = tid >> 5, lane = tid & 31;
    const uint32_t smem = smem_u32(fsm);

    if (tid < 16) {
        uint32_t m = 0;
        const int* xm = g_xmask + b * LX + tid * 32;
        #pragma unroll
        for (int i = 0; i < 32; i++) m |= (xm[i] ? 1u : 0u) << i;
        maskbits[tid] = m;
    }

    // load Q
    #pragma unroll
    for (int i = tid; i < 1024; i += 256) {
        int row = i >> 3, seg = i & 7;
        cp_async16(smem + row * ROWB + seg * 16,
                   g_qkv + ((size_t)(b * SS + q0 + row)) * (3 * DD) + h * 64 + seg * 8);
    }
    cp_commit();

    const int nch = (q0 < LX) ? 8 : ((q0 + 128) >> 6);

    auto load_kv = [&](int c, int s) {
        const int k0 = c << 6;
        const uint32_t sb = smem + KV_OFF + s * KSTAGE;
        #pragma unroll
        for (int i = tid; i < 512; i += 256) {
            int row = i >> 3, seg = i & 7;
            cp_async16(sb + row * ROWB + seg * 16,
                       g_qkv + ((size_t)(b * SS + k0 + row)) * (3 * DD) + DD + h * 64 + seg * 8);
        }
        #pragma unroll
        for (int i = tid; i < 512; i += 256) {
            int row = i >> 3, seg = i & 7;
            cp_async16(sb + TILE + row * ROWB + seg * 16,
                       g_vT + ((size_t)((b * NH + h) * HD + row)) * SS + k0 + seg * 8);
        }
        cp_commit();
    };

    load_kv(0, 0);

    float m_[2] = {-1e30f, -1e30f}, l_[2] = {0.f, 0.f};
    float out[8][4];
    #pragma unroll
    for (int j = 0; j < 8; j++)
        #pragma unroll
        for (int e = 0; e < 4; e++) out[j][e] = 0.f;

    const int r0 = lane >> 2;
    const int qrow0 = q0 + wid * 16 + r0;
    const int arow = wid * 16 + (lane & 15);
    const int bn   = (lane & 7) + (lane >> 4) * 8;
    const int bka  = ((lane >> 3) & 1) * 8;

    for (int c = 0; c < nch; c++) {
        if (c + 1 < nch) { load_kv(c + 1, (c + 1) & 1); cp_wait<1>(); }
        else cp_wait<0>();
        __syncthreads();
        const uint32_t sb = smem + KV_OFF + (c & 1) * KSTAGE;

        // ---- QK ----
        float s[8][4];
        #pragma unroll
        for (int j = 0; j < 8; j++)
            #pragma unroll
            for (int e = 0; e < 4; e++) s[j][e] = 0.f;
        #pragma unroll
        for (int t = 0; t < 4; t++) {
            const int acol = t * 16 + (lane >> 4) * 8;
            uint32_t qf[4];
            ldsm_x4(qf, smem + arow * ROWB + acol * 2);
            const int bk = t * 16 + bka;
            #pragma unroll
            for (int j = 0; j < 4; j++) {
                uint32_t kf[4];
                ldsm_x4(kf, sb + (j * 16 + bn) * ROWB + bk * 2);
                mma16816(s[2 * j], qf, kf[0], kf[1]);
                mma16816(s[2 * j + 1], qf, kf[2], kf[3]);
            }
        }

        // ---- mask + online softmax ----
        const int k0 = c << 6;
        uint32_t vmask = 0;
        float cmax[2] = {-1e30f, -1e30f};
        #pragma unroll
        for (int j = 0; j < 8; j++) {
            #pragma unroll
            for (int e = 0; e < 4; e++) {
                int col = k0 + j * 8 + (lane & 3) * 2 + (e & 1);
                int row = (e < 2) ? qrow0 : (qrow0 + 8);
                bool valid = (col < LX) ? !((maskbits[col >> 5] >> (col & 31)) & 1)
                                        : (col <= row);
                float sv = s[j][e] * 0.125f;
                s[j][e] = sv;
                if (valid) {
                    vmask |= 1u << (j * 4 + e);
                    cmax[e >> 1] = fmaxf(cmax[e >> 1], sv);
                }
            }
        }
        #pragma unroll
        for (int o = 1; o <= 2; o <<= 1) {
            cmax[0] = fmaxf(cmax[0], __shfl_xor_sync(0xffffffffu, cmax[0], o));
            cmax[1] = fmaxf(cmax[1], __shfl_xor_sync(0xffffffffu, cmax[1], o));
        }
        float mn0 = fmaxf(m_[0], cmax[0]);
        float mn1 = fmaxf(m_[1], cmax[1]);
        float f0 = __expf(m_[0] - mn0);
        float f1 = __expf(m_[1] - mn1);
        float rs[2] = {0.f, 0.f};
        #pragma unroll
        for (int j = 0; j < 8; j++) {
            #pragma unroll
            for (int e = 0; e < 4; e++) {
                float mn = (e < 2) ? mn0 : mn1;
                float p = ((vmask >> (j * 4 + e)) & 1) ? __expf(s[j][e] - mn) : 0.f;
                s[j][e] = p;
                rs[e >> 1] += p;
            }
        }
        #pragma unroll
        for (int o = 1; o <= 2; o <<= 1) {
            rs[0] += __shfl_xor_sync(0xffffffffu, rs[0], o);
            rs[1] += __shfl_xor_sync(0xffffffffu, rs[1], o);
        }
        l_[0] = l_[0] * f0 + rs[0];
        l_[1] = l_[1] * f1 + rs[1];
        m_[0] = mn0; m_[1] = mn1;
        #pragma unroll
        for (int j = 0; j < 8; j++) {
            out[j][0] *= f0; out[j][1] *= f0;
            out[j][2] *= f1; out[j][3] *= f1;
        }

        // ---- PV ----
        #pragma unroll
        for (int t = 0; t < 4; t++) {
            uint32_t pf[4];
            pf[0] = pack_h2(s[2 * t][0], s[2 * t][1]);
            pf[1] = pack_h2(s[2 * t][2], s[2 * t][3]);
            pf[2] = pack_h2(s[2 * t + 1][0], s[2 * t + 1][1]);
            pf[3] = pack_h2(s[2 * t + 1][2], s[2 * t + 1][3]);
            const int bk = t * 16 + bka;
            #pragma unroll
            for (int j = 0; j < 4; j++) {
                uint32_t vf[4];
                ldsm_x4(vf, sb + TILE + (j * 16 + bn) * ROWB + bk * 2);
                mma16816(out[2 * j], pf, vf[0], vf[1]);
                mma16816(out[2 * j + 1], pf, vf[2], vf[3]);
            }
        }
        __syncthreads();
    }

    // ---- epilogue ----
    float inv0 = 1.f / l_[0];
    float inv1 = 1.f / l_[1];
    #pragma unroll
    for (int j = 0; j < 8; j++) {
        const int d = h * 64 + j * 8 + (lane & 3) * 2;
        *(uint32_t*)(g_attno + ((size_t)(b * SS + qrow0)) * DD + d) =
            pack_h2(out[j][0] * inv0, out[j][1] * inv0);
        *(uint32_t*)(g_attno + ((size_t)(b * SS + qrow0 + 8)) * DD + d) =
            pack_h2(out[j][2] * inv1, out[j][3] * inv1);
    }
}

// ---------------- fp32 -> fp16 ----------------
__global__ void cvt_kernel(const float* __restrict__ src,
                           __half* __restrict__ h, long n4)
{
    long i = (long)blockIdx.x * blockDim.x + threadIdx.x;
    if (i >= n4) return;
    float4 v = *(const float4*)(src + i * 4);
    uint2 hv;
    hv.x = pack_h2(v.x, v.y);
    hv.y = pack_h2(v.z, v.w);
    *(uint2*)(h + i * 4) = hv;
}

// ---------------- V transpose: qkv -> vT [b][h][d][t] ----------------
__global__ void vT_kernel()
{
    __shared__ __half th[32][33];
    int z = blockIdx.z;
    int b = z / NH, h = z % NH;
    int t0 = blockIdx.x * 32;
    int d0 = blockIdx.y * 32;
    int tx = threadIdx.x, ty = threadIdx.y;  // 32 x 8
    #pragma unroll
    for (int i = 0; i < 4; i++) {
        int t = t0 + ty + i * 8;
        th[ty + i * 8][tx] = g_qkv[((size_t)(b * SS + t)) * (3 * DD) + 2 * DD + h * 64 + d0 + tx];
    }
    __syncthreads();
    #pragma unroll
    for (int i = 0; i < 4; i++) {
        int d = d0 + ty + i * 8;
        g_vT[((size_t)((b * NH + h) * HD + d)) * SS + t0 + tx] = th[tx][ty + i * 8];
    }
}

// ---------------- embedding: x tokens ----------------
__global__ void embed_x_kernel(const float* __restrict__ x,
                               const float* __restrict__ W_nail,
                               const float* __restrict__ b_nail)
{
    const float RSC = 0.99995000374968753f;
    int row = blockIdx.x;
    int b = row / LX;
    const float* xr = x + (long)row * 64;
    __shared__ float xn[63];
    __shared__ float t_sh;
    int tid = threadIdx.x;
    if (tid == 0) {
        float t0 = xr[0];
        g_xmask[row] = isnan(t0) ? 1 : 0;
        t_sh = isnan(t0) ? 0.f : t0;
    }
    if (tid < 63) {
        float v = xr[tid + 1];
        if (isnan(v)) v = 0.f;
        v *= RSC;
        xn[tid] = fminf(fmaxf(v, -5.f), 5.f);
    }
    __syncthreads();
    float t = t_sh;
    const float kfac = -logf(1000.f) / 1024.f;
    for (int d = tid; d < DD; d += 256) {
        const float* wr = W_nail + d * 63;
        float acc = b_nail[d];
        #pragma unroll 7
        for (int c = 0; c < 63; c++) acc = fmaf(xn[c], wr[c], acc);
        int i = d >> 1;
        float ang = t * expf((float)i * kfac);
        acc += (d & 1) ? cosf(ang) : sinf(ang);
        size_t idx = ((size_t)b * SS + (row % LX)) * DD + d;
        g_tgt[idx] = acc;
        g_tgt_s[idx] = __float2half_rn(acc);
    }
}

// ---------------- embedding: w tokens + global PE ----------------
__global__ void embed_w_kernel(const float* __restrict__ w,
                               const float* __restrict__ W_cond,
                               const float* __restrict__ b_cond)
{
    const float RSC = 0.99995000374968753f;
    int row = blockIdx.x;
    int b = row / NWTOK, r = row % NWTOK;
    const float* wr6 = w + (long)b * (NWTOK * 6) + r * 6;
    __shared__ float wn[6];
    int tid = threadIdx.x;
    if (tid < 6) {
        float v = wr6[tid];
        if (isnan(v)) v = 0.f;
        v *= RSC;
        wn[tid] = fminf(fmaxf(v, -5.f), 5.f);
    }
    __syncthreads();
    int spos = LX + r;
    const float kfac = -logf(1000.f) / 1024.f;
    for (int d = tid; d < DD; d += 256) {
        const float* wc = W_cond + d * 6;
        float acc = b_cond[d];
        #pragma unroll
        for (int c = 0; c < 6; c++) acc = fmaf(wn[c], wc[c], acc);
        int i = d >> 1;
        float ang = (float)spos * expf((float)i * kfac);
        acc += (d & 1) ? cosf(ang) : sinf(ang);
        size_t idx = ((size_t)b * SS + spos) * DD + d;
        g_tgt[idx] = acc;
        g_tgt_s[idx] = __float2half_rn(acc);
    }
}

// ---------------- residual add + LayerNorm (in-place, emits fp16) ----------------
__global__ void resid_ln_kernel(const float* __restrict__ delta,
                                const float* __restrict__ g,
                                const float* __restrict__ beta)
{
    size_t row = blockIdx.x;
    float* t = g_tgt + row * DD;
    const float* dl = delta + row * DD;
    int tid = threadIdx.x;
    float v[4];
    float s = 0.f;
    #pragma unroll
    for (int i = 0; i < 4; i++) { int idx = tid + i * 256; v[i] = t[idx] + dl[idx]; s += v[i]; }
    __shared__ float red[256];
    red[tid] = s; __syncthreads();
    #pragma unroll
    for (int o = 128; o > 0; o >>= 1) { if (tid < o) red[tid] += red[tid + o]; __syncthreads(); }
    float mean = red[0] * (1.f / 1024.f);
    __syncthreads();
    float s2 = 0.f;
    #pragma unroll
    for (int i = 0; i < 4; i++) { float d = v[i] - mean; s2 += d * d; }
    red[tid] = s2; __syncthreads();
    #pragma unroll
    for (int o = 128; o > 0; o >>= 1) { if (tid < o) red[tid] += red[tid + o]; __syncthreads(); }
    float inv = rsqrtf(red[0] * (1.f / 1024.f) + 1e-5f);
    #pragma unroll
    for (int i = 0; i < 4; i++) {
        int idx = tid + i * 256;
        float out = (v[i] - mean) * inv * g[idx] + beta[idx];
        t[idx] = out;
        g_tgt_s[row * DD + idx] = __float2half_rn(out);
    }
}

// ---------------- head + loss ----------------
__global__ void loss_kernel(const float* __restrict__ W_ham, const float* __restrict__ b_ham,
                            const float* __restrict__ y, const float* __restrict__ w,
                            float* __restrict__ out)
{
    __shared__ float red[256];
    int tid = threadIdx.x;
    float acc = 0.f;
    for (int idx = tid; idx < BB * 144; idx += 256) {
        int b = idx / 144;
        int j = idx % 144;
        const float* row = g_tgt + ((size_t)b * SS + (SS - 1)) * DD;
        const float* wr = W_ham + (size_t)j * DD;
        float dot = b_ham[j];
        for (int k = 0; k < DD; k++) dot = fmaf(row[k], wr[k], dot);
        float yr = y[b * 144 + j] - w[(size_t)b * 2304 + 2160 + j];
        float d = dot - yr;
        acc += d * d;
    }
    red[tid] = acc; __syncthreads();
    #pragma unroll
    for (int o = 128; o > 0; o >>= 1) { if (tid < o) red[tid] += red[tid + o]; __syncthreads(); }
    if (tid == 0) out[0] = red[0] / (float)(BB * 144);
}

// ---------------- launch ----------------
extern "C" void kernel_launch(void* const* d_in, const int* in_sizes, int n_in,
                              void* d_out, int out_size)
{
    const float* x      = (const float*)d_in[0];
    const float* w      = (const float*)d_in[1];
    const float* y      = (const float*)d_in[2];
    const float* W_nail = (const float*)d_in[3];
    const float* b_nail = (const float*)d_in[4];
    const float* W_cond = (const float*)d_in[5];
    const float* b_cond = (const float*)d_in[6];
    const float* Wqkv   = (const float*)d_in[7];
    const float* bqkv   = (const float*)d_in[8];
    const float* Wo     = (const float*)d_in[9];
    const float* bo     = (const float*)d_in[10];
    const float* ln1_g  = (const float*)d_in[11];
    const float* ln1_b  = (const float*)d_in[12];
    const float* ln2_g  = (const float*)d_in[13];
    const float* ln2_b  = (const float*)d_in[14];
    const float* W1     = (const float*)d_in[15];
    const float* b1     = (const float*)d_in[16];
    const float* W2     = (const float*)d_in[17];
    const float* b2     = (const float*)d_in[18];
    const float* W_ham  = (const float*)d_in[19];
    const float* b_ham  = (const float*)d_in[20];

    float *p_tgt, *p_tmp;
    __half *p_tgt_s, *p_qkv, *p_attno, *p_hid;
    __half *p_wqkv, *p_wo, *p_w1, *p_w2;
    cudaGetSymbolAddress((void**)&p_tgt,   g_tgt);
    cudaGetSymbolAddress((void**)&p_tmp,   g_tmp);
    cudaGetSymbolAddress((void**)&p_tgt_s, g_tgt_s);
    cudaGetSymbolAddress((void**)&p_qkv,   g_qkv);
    cudaGetSymbolAddress((void**)&p_attno, g_attno);
    cudaGetSymbolAddress((void**)&p_hid,   g_hid);
    cudaGetSymbolAddress((void**)&p_wqkv,  g_wqkv);
    cudaGetSymbolAddress((void**)&p_wo,    g_wo);
    cudaGetSymbolAddress((void**)&p_w1,    g_w1);
    cudaGetSymbolAddress((void**)&p_w2,    g_w2);

    static const int SMG = 256 * 144 * 2;                 // 73728
    static const int SMF = 128 * 144 + 2 * 2 * 64 * 144;  // 55296
    cudaFuncSetAttribute(mma_gemm<0, 0>, cudaFuncAttributeMaxDynamicSharedMemorySize, SMG);
    cudaFuncSetAttribute(mma_gemm<0, 1>, cudaFuncAttributeMaxDynamicSharedMemorySize, SMG);
    cudaFuncSetAttribute(mma_gemm<1, 1>, cudaFuncAttributeMaxDynamicSharedMemorySize, SMG);
    cudaFuncSetAttribute(flash_kernel,   cudaFuncAttributeMaxDynamicSharedMemorySize, SMF);

    const int M = BB * SS;   // 7168
    dim3 blk(256);

    // weight conversions
    {
        long n;
        n = (long)NLAYER * 3 * DD * DD / 4;
        cvt_kernel<<<(unsigned)((n + 255) / 256), blk>>>(Wqkv, p_wqkv, n);
        n = (long)NLAYER * DD * DD / 4;
        cvt_kernel<<<(unsigned)((n + 255) / 256), blk>>>(Wo, p_wo, n);
        n = (long)NLAYER * FFD * DD / 4;
        cvt_kernel<<<(unsigned)((n + 255) / 256), blk>>>(W1, p_w1, n);
        n = (long)NLAYER * DD * FFD / 4;
        cvt_kernel<<<(unsigned)((n + 255) / 256), blk>>>(W2, p_w2, n);
    }

    embed_x_kernel<<<BB * LX, blk>>>(x, W_nail, b_nail);
    embed_w_kernel<<<BB * NWTOK, blk>>>(w, W_cond, b_cond);

    for (int l = 0; l < NLAYER; l++) {
        const __half* wqkv_l = p_wqkv + (size_t)l * 3 * DD * DD;
        const __half* wo_l   = p_wo + (size_t)l * DD * DD;
        const __half* w1_l   = p_w1 + (size_t)l * FFD * DD;
        const __half* w2_l   = p_w2 + (size_t)l * DD * FFD;

        // QKV: (7168 x 3072 x 1024) -> fp16
        mma_gemm<0, 1><<<dim3(M / 128, 3 * DD / 128), blk, SMG>>>(
            p_tgt_s, wqkv_l, bqkv + (size_t)l * 3 * DD,
            nullptr, p_qkv, DD, DD, DD, 3 * DD);

        // V transpose
        vT_kernel<<<dim3(SS / 32, HD / 32, BB * NH), dim3(32, 8)>>>();

        // flash attention -> attno (fp16, token-major)
        flash_kernel<<<dim3(SS / 128, BB * NH), blk, SMF>>>();

        // tmp = attno @ Wo^T + bo  -> fp32
        mma_gemm<0, 0><<<dim3(M / 128, DD / 128), blk, SMG>>>(
            p_attno, wo_l, bo + (size_t)l * DD,
            p_tmp, nullptr, DD, DD, DD, DD);

        resid_ln_kernel<<<M, blk>>>(p_tmp, ln1_g + (size_t)l * DD, ln1_b + (size_t)l * DD);

        // hid = gelu(tgt @ W1^T + b1) -> fp16
        mma_gemm<1, 1><<<dim3(M / 128, FFD / 128), blk, SMG>>>(
            p_tgt_s, w1_l, b1 + (size_t)l * FFD,
            nullptr, p_hid, DD, DD, DD, FFD);

        // tmp = hid @ W2^T + b2 -> fp32
        mma_gemm<0, 0><<<dim3(M / 128, DD / 128), blk, SMG>>>(
            p_hid, w2_l, b2 + (size_t)l * DD,
            p_tmp, nullptr, FFD, FFD, FFD, DD);

        resid_ln_kernel<<<M, blk>>>(p_tmp, ln2_g + (size_t)l * DD, ln2_b + (size_t)l * DD);
    }

    loss_kernel<<<1, blk>>>(W_ham, b_ham, y, w, (float*)d_out);
}

// round 6
// speedup vs baseline: 9.1097x; 1.0144x over previous
#include <cuda_runtime.h>
#include <cuda_fp16.h>
#include <math.h>
#include <stdint.h>

// Problem dims (fixed by setup_inputs)
#define BB 8
#define LX 512
#define NWTOK 384
#define SS 896
#define DD 1024
#define NH 16
#define HD 64
#define FFD 4096
#define NLAYER 4

// ---------------- scratch (device globals) ----------------
__device__ float g_tgt[BB * SS * DD];
__device__ __half g_tgt_s[BB * SS * DD];
__device__ __half g_qkv[(size_t)BB * SS * 3 * DD];
__device__ __half g_attno[(size_t)BB * SS * DD];
__device__ __half g_hid[(size_t)BB * SS * FFD];
__device__ float g_tmp[BB * SS * DD];
__device__ int   g_xmask[BB * LX];
// weights fp16
__device__ __half g_wqkv[(size_t)NLAYER * 3 * DD * DD];
__device__ __half g_wo[(size_t)NLAYER * DD * DD];
__device__ __half g_w1[(size_t)NLAYER * FFD * DD];
__device__ __half g_w2[(size_t)NLAYER * DD * FFD];

// ---------------- helpers ----------------
__device__ __forceinline__ uint32_t smem_u32(const void* p) {
    uint32_t a;
    asm("{ .reg .u64 t; cvta.to.shared.u64 t, %1; cvt.u32.u64 %0, t; }" : "=r"(a) : "l"(p));
    return a;
}
__device__ __forceinline__ void cp_async16(uint32_t saddr, const void* gaddr) {
    asm volatile("cp.async.cg.shared.global [%0], [%1], 16;" :: "r"(saddr), "l"(gaddr));
}
__device__ __forceinline__ void cp_commit() {
    asm volatile("cp.async.commit_group;" ::: "memory");
}
template<int N>
__device__ __forceinline__ void cp_wait() {
    asm volatile("cp.async.wait_group %0;" :: "n"(N) : "memory");
}
__device__ __forceinline__ void ldsm_x4(uint32_t (&r)[4], uint32_t addr) {
    asm volatile("ldmatrix.sync.aligned.m8n8.x4.shared.b16 {%0,%1,%2,%3}, [%4];"
        : "=r"(r[0]), "=r"(r[1]), "=r"(r[2]), "=r"(r[3]) : "r"(addr));
}
__device__ __forceinline__ void ldsm_x4_trans(uint32_t (&r)[4], uint32_t addr) {
    asm volatile("ldmatrix.sync.aligned.m8n8.x4.trans.shared.b16 {%0,%1,%2,%3}, [%4];"
        : "=r"(r[0]), "=r"(r[1]), "=r"(r[2]), "=r"(r[3]) : "r"(addr));
}
__device__ __forceinline__ void mma16816(float (&d)[4], const uint32_t (&a)[4],
                                         uint32_t b0, uint32_t b1) {
    asm volatile("mma.sync.aligned.m16n8k16.row.col.f32.f16.f16.f32 "
        "{%0,%1,%2,%3}, {%4,%5,%6,%7}, {%8,%9}, {%0,%1,%2,%3};"
        : "+f"(d[0]), "+f"(d[1]), "+f"(d[2]), "+f"(d[3])
        : "r"(a[0]), "r"(a[1]), "r"(a[2]), "r"(a[3]), "r"(b0), "r"(b1));
}
__device__ __forceinline__ float gelu_exact(float x) {
    return 0.5f * x * (1.0f + erff(x * 0.70710678118654752f));
}
__device__ __forceinline__ uint32_t pack_h2(float f0, float f1) {
    __half2 h = __floats2half2_rn(f0, f1);
    return *(uint32_t*)&h;
}

// =====================================================================
// Dense fp16 GEMM: C = act(A @ B^T + bias)
// A (M,K) half row-major; B (N,K) half row-major. BM=128, BN=128, BK=64.
// 3-stage cp.async pipeline, one __syncthreads per chunk.
// OUTMODE 0: fp32 C; 1: half C.
// =====================================================================
template<int ACT, int OUTMODE>
__global__ void __launch_bounds__(256, 2)
mma_gemm(const __half* __restrict__ A, const __half* __restrict__ B,
         const float* __restrict__ bias,
         float* __restrict__ Cf, __half* __restrict__ Ch,
         int K, int lda, int ldb, int ldc)
{
    extern __shared__ __align__(16) char sm[];
    constexpr int ROWB = 144;              // 64 half + 16B pad
    constexpr int B_OFF = 128 * ROWB;
    constexpr int STAGE = 256 * ROWB;      // 36864

    const int tid = threadIdx.x;
    const int wid = tid >> 5, lane = tid & 31;
    const int warp_m = wid >> 1, warp_n = wid & 1;
    const int m0 = blockIdx.x * 128;
    const int n0 = blockIdx.y * 128;
    const uint32_t smem_base = smem_u32(sm);
    const int nch = K >> 6;

    float acc[2][8][4];
    #pragma unroll
    for (int a = 0; a < 2; a++)
        #pragma unroll
        for (int b = 0; b < 8; b++)
            #pragma unroll
            for (int c = 0; c < 4; c++) acc[a][b][c] = 0.f;

    auto load_stage = [&](int stage, int ch) {
        const int k0 = ch << 6;
        const uint32_t sbase = smem_base + stage * STAGE;
        #pragma unroll
        for (int i = tid; i < 1024; i += 256) {
            int row = i >> 3, seg = i & 7;
            cp_async16(sbase + row * ROWB + seg * 16,
                       A + (long)(m0 + row) * lda + k0 + seg * 8);
        }
        #pragma unroll
        for (int i = tid; i < 1024; i += 256) {
            int row = i >> 3, seg = i & 7;
            cp_async16(sbase + B_OFF + row * ROWB + seg * 16,
                       B + (long)(n0 + row) * ldb + k0 + seg * 8);
        }
        cp_commit();
    };

    auto compute = [&](int stage) {
        const uint32_t sbase = smem_base + stage * STAGE;
        const int arow = warp_m * 32 + (lane & 15);
        const int bn   = (lane & 7) + (lane >> 4) * 8;
        const int bka  = ((lane >> 3) & 1) * 8;
        #pragma unroll
        for (int kk = 0; kk < 4; kk++) {
            const int acol = kk * 16 + (lane >> 4) * 8;
            uint32_t af[2][4];
            #pragma unroll
            for (int mt = 0; mt < 2; mt++)
                ldsm_x4(af[mt], sbase + (arow + mt * 16) * ROWB + acol * 2);
            const int bk = kk * 16 + bka;
            #pragma unroll
            for (int nt2 = 0; nt2 < 4; nt2++) {
                uint32_t bf[4];
                ldsm_x4(bf, sbase + B_OFF + (warp_n * 64 + nt2 * 16 + bn) * ROWB + bk * 2);
                #pragma unroll
                for (int mt = 0; mt < 2; mt++) {
                    #pragma unroll
                    for (int j = 0; j < 2; j++)
                        mma16816(acc[mt][nt2 * 2 + j], af[mt], bf[2 * j], bf[2 * j + 1]);
                }
            }
        }
    };

    load_stage(0, 0);
    load_stage(1, 1);
    // stage s holds chunk ch with s = ch % 3
    for (int ch = 0; ch < nch; ch++) {
        if (ch + 1 < nch) cp_wait<1>(); else cp_wait<0>();
        __syncthreads();                       // data for ch ready; stage (ch+2)%3 free
        if (ch + 2 < nch) load_stage((ch + 2) % 3, ch + 2);
        compute(ch % 3);
    }

    const int r0 = lane >> 2, c0 = (lane & 3) * 2;
    #pragma unroll
    for (int mt = 0; mt < 2; mt++) {
        #pragma unroll
        for (int nt = 0; nt < 8; nt++) {
            const int n = n0 + warp_n * 64 + nt * 8 + c0;
            float bv0 = bias ? bias[n] : 0.f;
            float bv1 = bias ? bias[n + 1] : 0.f;
            #pragma unroll
            for (int hrow = 0; hrow < 2; hrow++) {
                const int m = m0 + warp_m * 32 + mt * 16 + r0 + hrow * 8;
                float f0 = acc[mt][nt][hrow * 2 + 0] + bv0;
                float f1 = acc[mt][nt][hrow * 2 + 1] + bv1;
                if (ACT == 1) { f0 = gelu_exact(f0); f1 = gelu_exact(f1); }
                const long off = (long)m * ldc + n;
                if (OUTMODE == 0) *(float2*)(Cf + off) = make_float2(f0, f1);
                else              *(uint32_t*)(Ch + off) = pack_h2(f0, f1);
            }
        }
    }
}

// =====================================================================
// Flash attention (fp16): per CTA = (q-tile 128, one (b,h)). 8 warps x 16 rows.
// 64-key chunks, 3-stage pipeline, V loaded row-major + ldmatrix.trans.
// keys<LX gated by x_mask; keys>=LX causal.
// =====================================================================
__global__ void __launch_bounds__(256, 2)
flash_kernel()
{
    extern __shared__ __align__(16) char fsm[];
    __shared__ uint32_t maskbits[16];
    constexpr int ROWB = 144;
    constexpr int KV_OFF = 128 * ROWB;     // after Q
    constexpr int TILE = 64 * ROWB;        // 9216
    constexpr int KSTAGE = 2 * TILE;       // K,V

    const int bh = blockIdx.y;
    const int b = bh >> 4, h = bh & 15;
    const int q0 = blockIdx.x * 128;
    const int tid = threadIdx.x;
    const int wid = tid >> 5, lane = tid & 31;
    const uint32_t smem = smem_u32(fsm);

    if (tid < 16) {
        uint32_t m = 0;
        const int* xm = g_xmask + b * LX + tid * 32;
        #pragma unroll
        for (int i = 0; i < 32; i++) m |= (xm[i] ? 1u : 0u) << i;
        maskbits[tid] = m;
    }

    // load Q (own cp group)
    #pragma unroll
    for (int i = tid; i < 1024; i += 256) {
        int row = i >> 3, seg = i & 7;
        cp_async16(smem + row * ROWB + seg * 16,
                   g_qkv + ((size_t)(b * SS + q0 + row)) * (3 * DD) + h * 64 + seg * 8);
    }
    cp_commit();

    const int nch = (q0 < LX) ? 8 : ((q0 + 128) >> 6);

    auto load_kv = [&](int c, int s) {
        const int k0 = c << 6;
        const uint32_t sb = smem + KV_OFF + s * KSTAGE;
        #pragma unroll
        for (int i = tid; i < 512; i += 256) {
            int row = i >> 3, seg = i & 7;
            cp_async16(sb + row * ROWB + seg * 16,
                       g_qkv + ((size_t)(b * SS + k0 + row)) * (3 * DD) + DD + h * 64 + seg * 8);
        }
        #pragma unroll
        for (int i = tid; i < 512; i += 256) {
            int row = i >> 3, seg = i & 7;
            cp_async16(sb + TILE + row * ROWB + seg * 16,
                       g_qkv + ((size_t)(b * SS + k0 + row)) * (3 * DD) + 2 * DD + h * 64 + seg * 8);
        }
        cp_commit();
    };

    load_kv(0, 0);
    load_kv(1, 1);

    float m_[2] = {-1e30f, -1e30f}, l_[2] = {0.f, 0.f};
    float out[8][4];
    #pragma unroll
    for (int j = 0; j < 8; j++)
        #pragma unroll
        for (int e = 0; e < 4; e++) out[j][e] = 0.f;

    const int r0 = lane >> 2;
    const int qrow0 = q0 + wid * 16 + r0;
    const int arow = wid * 16 + (lane & 15);
    const int bn   = (lane & 7) + (lane >> 4) * 8;
    const int bka  = ((lane >> 3) & 1) * 8;
    const int trow = (lane & 7) + ((lane >> 3) & 1) * 8;   // key row for trans V
    const int tcol = (lane >> 4) * 8;                      // d col half for trans V

    for (int c = 0; c < nch; c++) {
        if (c + 1 < nch) cp_wait<1>(); else cp_wait<0>();
        __syncthreads();
        if (c + 2 < nch) load_kv(c + 2, (c + 2) % 3);
        const uint32_t sb = smem + KV_OFF + (c % 3) * KSTAGE;

        // ---- QK ----
        float s[8][4];
        #pragma unroll
        for (int j = 0; j < 8; j++)
            #pragma unroll
            for (int e = 0; e < 4; e++) s[j][e] = 0.f;
        #pragma unroll
        for (int t = 0; t < 4; t++) {
            const int acol = t * 16 + (lane >> 4) * 8;
            uint32_t qf[4];
            ldsm_x4(qf, smem + arow * ROWB + acol * 2);
            const int bk = t * 16 + bka;
            #pragma unroll
            for (int j = 0; j < 4; j++) {
                uint32_t kf[4];
                ldsm_x4(kf, sb + (j * 16 + bn) * ROWB + bk * 2);
                mma16816(s[2 * j], qf, kf[0], kf[1]);
                mma16816(s[2 * j + 1], qf, kf[2], kf[3]);
            }
        }

        // ---- mask + online softmax ----
        const int k0 = c << 6;
        uint32_t vmask = 0;
        float cmax[2] = {-1e30f, -1e30f};
        #pragma unroll
        for (int j = 0; j < 8; j++) {
            #pragma unroll
            for (int e = 0; e < 4; e++) {
                int col = k0 + j * 8 + (lane & 3) * 2 + (e & 1);
                int row = (e < 2) ? qrow0 : (qrow0 + 8);
                bool valid = (col < LX) ? !((maskbits[col >> 5] >> (col & 31)) & 1)
                                        : (col <= row);
                float sv = s[j][e] * 0.125f;
                s[j][e] = sv;
                if (valid) {
                    vmask |= 1u << (j * 4 + e);
                    cmax[e >> 1] = fmaxf(cmax[e >> 1], sv);
                }
            }
        }
        #pragma unroll
        for (int o = 1; o <= 2; o <<= 1) {
            cmax[0] = fmaxf(cmax[0], __shfl_xor_sync(0xffffffffu, cmax[0], o));
            cmax[1] = fmaxf(cmax[1], __shfl_xor_sync(0xffffffffu, cmax[1], o));
        }
        float mn0 = fmaxf(m_[0], cmax[0]);
        float mn1 = fmaxf(m_[1], cmax[1]);
        float f0 = __expf(m_[0] - mn0);
        float f1 = __expf(m_[1] - mn1);
        float rs[2] = {0.f, 0.f};
        #pragma unroll
        for (int j = 0; j < 8; j++) {
            #pragma unroll
            for (int e = 0; e < 4; e++) {
                float mn = (e < 2) ? mn0 : mn1;
                float p = ((vmask >> (j * 4 + e)) & 1) ? __expf(s[j][e] - mn) : 0.f;
                s[j][e] = p;
                rs[e >> 1] += p;
            }
        }
        #pragma unroll
        for (int o = 1; o <= 2; o <<= 1) {
            rs[0] += __shfl_xor_sync(0xffffffffu, rs[0], o);
            rs[1] += __shfl_xor_sync(0xffffffffu, rs[1], o);
        }
        l_[0] = l_[0] * f0 + rs[0];
        l_[1] = l_[1] * f1 + rs[1];
        m_[0] = mn0; m_[1] = mn1;
        #pragma unroll
        for (int j = 0; j < 8; j++) {
            out[j][0] *= f0; out[j][1] *= f0;
            out[j][2] *= f1; out[j][3] *= f1;
        }

        // ---- PV: V row-major (keys x d), B frags via ldmatrix.trans ----
        #pragma unroll
        for (int t = 0; t < 4; t++) {
            uint32_t pf[4];
            pf[0] = pack_h2(s[2 * t][0], s[2 * t][1]);
            pf[1] = pack_h2(s[2 * t][2], s[2 * t][3]);
            pf[2] = pack_h2(s[2 * t + 1][0], s[2 * t + 1][1]);
            pf[3] = pack_h2(s[2 * t + 1][2], s[2 * t + 1][3]);
            #pragma unroll
            for (int j = 0; j < 4; j++) {
                uint32_t vf[4];
                ldsm_x4_trans(vf, sb + TILE + (t * 16 + trow) * ROWB + (j * 16 + tcol) * 2);
                mma16816(out[2 * j], pf, vf[0], vf[1]);
                mma16816(out[2 * j + 1], pf, vf[2], vf[3]);
            }
        }
    }

    // ---- epilogue ----
    float inv0 = 1.f / l_[0];
    float inv1 = 1.f / l_[1];
    #pragma unroll
    for (int j = 0; j < 8; j++) {
        const int d = h * 64 + j * 8 + (lane & 3) * 2;
        *(uint32_t*)(g_attno + ((size_t)(b * SS + qrow0)) * DD + d) =
            pack_h2(out[j][0] * inv0, out[j][1] * inv0);
        *(uint32_t*)(g_attno + ((size_t)(b * SS + qrow0 + 8)) * DD + d) =
            pack_h2(out[j][2] * inv1, out[j][3] * inv1);
    }
}

// ---------------- fp32 -> fp16 ----------------
__global__ void cvt_kernel(const float* __restrict__ src,
                           __half* __restrict__ h, long n4)
{
    long i = (long)blockIdx.x * blockDim.x + threadIdx.x;
    if (i >= n4) return;
    float4 v = *(const float4*)(src + i * 4);
    uint2 hv;
    hv.x = pack_h2(v.x, v.y);
    hv.y = pack_h2(v.z, v.w);
    *(uint2*)(h + i * 4) = hv;
}

// ---------------- embedding: x tokens ----------------
__global__ void embed_x_kernel(const float* __restrict__ x,
                               const float* __restrict__ W_nail,
                               const float* __restrict__ b_nail)
{
    const float RSC = 0.99995000374968753f;
    int row = blockIdx.x;
    int b = row / LX;
    const float* xr = x + (long)row * 64;
    __shared__ float xn[63];
    __shared__ float t_sh;
    int tid = threadIdx.x;
    if (tid == 0) {
        float t0 = xr[0];
        g_xmask[row] = isnan(t0) ? 1 : 0;
        t_sh = isnan(t0) ? 0.f : t0;
    }
    if (tid < 63) {
        float v = xr[tid + 1];
        if (isnan(v)) v = 0.f;
        v *= RSC;
        xn[tid] = fminf(fmaxf(v, -5.f), 5.f);
    }
    __syncthreads();
    float t = t_sh;
    const float kfac = -logf(1000.f) / 1024.f;
    for (int d = tid; d < DD; d += 256) {
        const float* wr = W_nail + d * 63;
        float acc = b_nail[d];
        #pragma unroll 7
        for (int c = 0; c < 63; c++) acc = fmaf(xn[c], wr[c], acc);
        int i = d >> 1;
        float ang = t * expf((float)i * kfac);
        acc += (d & 1) ? cosf(ang) : sinf(ang);
        size_t idx = ((size_t)b * SS + (row % LX)) * DD + d;
        g_tgt[idx] = acc;
        g_tgt_s[idx] = __float2half_rn(acc);
    }
}

// ---------------- embedding: w tokens + global PE ----------------
__global__ void embed_w_kernel(const float* __restrict__ w,
                               const float* __restrict__ W_cond,
                               const float* __restrict__ b_cond)
{
    const float RSC = 0.99995000374968753f;
    int row = blockIdx.x;
    int b = row / NWTOK, r = row % NWTOK;
    const float* wr6 = w + (long)b * (NWTOK * 6) + r * 6;
    __shared__ float wn[6];
    int tid = threadIdx.x;
    if (tid < 6) {
        float v = wr6[tid];
        if (isnan(v)) v = 0.f;
        v *= RSC;
        wn[tid] = fminf(fmaxf(v, -5.f), 5.f);
    }
    __syncthreads();
    int spos = LX + r;
    const float kfac = -logf(1000.f) / 1024.f;
    for (int d = tid; d < DD; d += 256) {
        const float* wc = W_cond + d * 6;
        float acc = b_cond[d];
        #pragma unroll
        for (int c = 0; c < 6; c++) acc = fmaf(wn[c], wc[c], acc);
        int i = d >> 1;
        float ang = (float)spos * expf((float)i * kfac);
        acc += (d & 1) ? cosf(ang) : sinf(ang);
        size_t idx = ((size_t)b * SS + spos) * DD + d;
        g_tgt[idx] = acc;
        g_tgt_s[idx] = __float2half_rn(acc);
    }
}

// ---------------- residual add + LayerNorm (in-place, emits fp16) ----------------
__global__ void resid_ln_kernel(const float* __restrict__ delta,
                                const float* __restrict__ g,
                                const float* __restrict__ beta)
{
    size_t row = blockIdx.x;
    float* t = g_tgt + row * DD;
    const float* dl = delta + row * DD;
    int tid = threadIdx.x;
    float v[4];
    float s = 0.f;
    #pragma unroll
    for (int i = 0; i < 4; i++) { int idx = tid + i * 256; v[i] = t[idx] + dl[idx]; s += v[i]; }
    __shared__ float red[256];
    red[tid] = s; __syncthreads();
    #pragma unroll
    for (int o = 128; o > 0; o >>= 1) { if (tid < o) red[tid] += red[tid + o]; __syncthreads(); }
    float mean = red[0] * (1.f / 1024.f);
    __syncthreads();
    float s2 = 0.f;
    #pragma unroll
    for (int i = 0; i < 4; i++) { float d = v[i] - mean; s2 += d * d; }
    red[tid] = s2; __syncthreads();
    #pragma unroll
    for (int o = 128; o > 0; o >>= 1) { if (tid < o) red[tid] += red[tid + o]; __syncthreads(); }
    float inv = rsqrtf(red[0] * (1.f / 1024.f) + 1e-5f);
    #pragma unroll
    for (int i = 0; i < 4; i++) {
        int idx = tid + i * 256;
        float out = (v[i] - mean) * inv * g[idx] + beta[idx];
        t[idx] = out;
        g_tgt_s[row * DD + idx] = __float2half_rn(out);
    }
}

// ---------------- head + loss ----------------
__global__ void loss_kernel(const float* __restrict__ W_ham, const float* __restrict__ b_ham,
                            const float* __restrict__ y, const float* __restrict__ w,
                            float* __restrict__ out)
{
    __shared__ float red[256];
    int tid = threadIdx.x;
    float acc = 0.f;
    for (int idx = tid; idx < BB * 144; idx += 256) {
        int b = idx / 144;
        int j = idx % 144;
        const float* row = g_tgt + ((size_t)b * SS + (SS - 1)) * DD;
        const float* wr = W_ham + (size_t)j * DD;
        float dot = b_ham[j];
        for (int k = 0; k < DD; k++) dot = fmaf(row[k], wr[k], dot);
        float yr = y[b * 144 + j] - w[(size_t)b * 2304 + 2160 + j];
        float d = dot - yr;
        acc += d * d;
    }
    red[tid] = acc; __syncthreads();
    #pragma unroll
    for (int o = 128; o > 0; o >>= 1) { if (tid < o) red[tid] += red[tid + o]; __syncthreads(); }
    if (tid == 0) out[0] = red[0] / (float)(BB * 144);
}

// ---------------- launch ----------------
extern "C" void kernel_launch(void* const* d_in, const int* in_sizes, int n_in,
                              void* d_out, int out_size)
{
    const float* x      = (const float*)d_in[0];
    const float* w      = (const float*)d_in[1];
    const float* y      = (const float*)d_in[2];
    const float* W_nail = (const float*)d_in[3];
    const float* b_nail = (const float*)d_in[4];
    const float* W_cond = (const float*)d_in[5];
    const float* b_cond = (const float*)d_in[6];
    const float* Wqkv   = (const float*)d_in[7];
    const float* bqkv   = (const float*)d_in[8];
    const float* Wo     = (const float*)d_in[9];
    const float* bo     = (const float*)d_in[10];
    const float* ln1_g  = (const float*)d_in[11];
    const float* ln1_b  = (const float*)d_in[12];
    const float* ln2_g  = (const float*)d_in[13];
    const float* ln2_b  = (const float*)d_in[14];
    const float* W1     = (const float*)d_in[15];
    const float* b1     = (const float*)d_in[16];
    const float* W2     = (const float*)d_in[17];
    const float* b2     = (const float*)d_in[18];
    const float* W_ham  = (const float*)d_in[19];
    const float* b_ham  = (const float*)d_in[20];

    float *p_tgt, *p_tmp;
    __half *p_tgt_s, *p_qkv, *p_attno, *p_hid;
    __half *p_wqkv, *p_wo, *p_w1, *p_w2;
    cudaGetSymbolAddress((void**)&p_tgt,   g_tgt);
    cudaGetSymbolAddress((void**)&p_tmp,   g_tmp);
    cudaGetSymbolAddress((void**)&p_tgt_s, g_tgt_s);
    cudaGetSymbolAddress((void**)&p_qkv,   g_qkv);
    cudaGetSymbolAddress((void**)&p_attno, g_attno);
    cudaGetSymbolAddress((void**)&p_hid,   g_hid);
    cudaGetSymbolAddress((void**)&p_wqkv,  g_wqkv);
    cudaGetSymbolAddress((void**)&p_wo,    g_wo);
    cudaGetSymbolAddress((void**)&p_w1,    g_w1);
    cudaGetSymbolAddress((void**)&p_w2,    g_w2);

    static const int SMG = 256 * 144 * 3;                 // 110592 (3 stages)
    static const int SMF = 128 * 144 + 3 * 2 * 64 * 144;  // 73728  (3 KV stages)
    cudaFuncSetAttribute(mma_gemm<0, 0>, cudaFuncAttributeMaxDynamicSharedMemorySize, SMG);
    cudaFuncSetAttribute(mma_gemm<0, 1>, cudaFuncAttributeMaxDynamicSharedMemorySize, SMG);
    cudaFuncSetAttribute(mma_gemm<1, 1>, cudaFuncAttributeMaxDynamicSharedMemorySize, SMG);
    cudaFuncSetAttribute(flash_kernel,   cudaFuncAttributeMaxDynamicSharedMemorySize, SMF);

    const int M = BB * SS;   // 7168
    dim3 blk(256);

    // weight conversions
    {
        long n;
        n = (long)NLAYER * 3 * DD * DD / 4;
        cvt_kernel<<<(unsigned)((n + 255) / 256), blk>>>(Wqkv, p_wqkv, n);
        n = (long)NLAYER * DD * DD / 4;
        cvt_kernel<<<(unsigned)((n + 255) / 256), blk>>>(Wo, p_wo, n);
        n = (long)NLAYER * FFD * DD / 4;
        cvt_kernel<<<(unsigned)((n + 255) / 256), blk>>>(W1, p_w1, n);
        n = (long)NLAYER * DD * FFD / 4;
        cvt_kernel<<<(unsigned)((n + 255) / 256), blk>>>(W2, p_w2, n);
    }

    embed_x_kernel<<<BB * LX, blk>>>(x, W_nail, b_nail);
    embed_w_kernel<<<BB * NWTOK, blk>>>(w, W_cond, b_cond);

    for (int l = 0; l < NLAYER; l++) {
        const __half* wqkv_l = p_wqkv + (size_t)l * 3 * DD * DD;
        const __half* wo_l   = p_wo + (size_t)l * DD * DD;
        const __half* w1_l   = p_w1 + (size_t)l * FFD * DD;
        const __half* w2_l   = p_w2 + (size_t)l * DD * FFD;

        // QKV: (7168 x 3072 x 1024) -> fp16
        mma_gemm<0, 1><<<dim3(M / 128, 3 * DD / 128), blk, SMG>>>(
            p_tgt_s, wqkv_l, bqkv + (size_t)l * 3 * DD,
            nullptr, p_qkv, DD, DD, DD, 3 * DD);

        // flash attention -> attno (fp16, token-major)
        flash_kernel<<<dim3(SS / 128, BB * NH), blk, SMF>>>();

        // tmp = attno @ Wo^T + bo  -> fp32
        mma_gemm<0, 0><<<dim3(M / 128, DD / 128), blk, SMG>>>(
            p_attno, wo_l, bo + (size_t)l * DD,
            p_tmp, nullptr, DD, DD, DD, DD);

        resid_ln_kernel<<<M, blk>>>(p_tmp, ln1_g + (size_t)l * DD, ln1_b + (size_t)l * DD);

        // hid = gelu(tgt @ W1^T + b1) -> fp16
        mma_gemm<1, 1><<<dim3(M / 128, FFD / 128), blk, SMG>>>(
            p_tgt_s, w1_l, b1 + (size_t)l * FFD,
            nullptr, p_hid, DD, DD, DD, FFD);

        // tmp = hid @ W2^T + b2 -> fp32
        mma_gemm<0, 0><<<dim3(M / 128, DD / 128), blk, SMG>>>(
            p_hid, w2_l, b2 + (size_t)l * DD,
            p_tmp, nullptr, FFD, FFD, FFD, DD);

        resid_ln_kernel<<<M, blk>>>(p_tmp, ln2_g + (size_t)l * DD, ln2_b + (size_t)l * DD);
    }

    loss_kernel<<<1, blk>>>(W_ham, b_ham, y, w, (float*)d_out);
}

// round 7
// speedup vs baseline: 10.5707x; 1.1604x over previous
#include <cuda_runtime.h>
#include <cuda_fp16.h>
#include <math.h>
#include <stdint.h>

// Problem dims (fixed by setup_inputs)
#define BB 8
#define LX 512
#define NWTOK 384
#define SS 896
#define DD 1024
#define NH 16
#define HD 64
#define FFD 4096
#define NLAYER 4

// ---------------- scratch (device globals) ----------------
__device__ float g_tgt[BB * SS * DD];
__device__ __half g_tgt_s[BB * SS * DD];
__device__ __half g_qkv[(size_t)BB * SS * 3 * DD];
__device__ __half g_attno[(size_t)BB * SS * DD];
__device__ __half g_hid[(size_t)BB * SS * FFD];
__device__ float g_tmp[BB * SS * DD];
__device__ int   g_xmask[BB * LX];
// weights fp16
__device__ __half g_wqkv[(size_t)NLAYER * 3 * DD * DD];
__device__ __half g_wo[(size_t)NLAYER * DD * DD];
__device__ __half g_w1[(size_t)NLAYER * FFD * DD];
__device__ __half g_w2[(size_t)NLAYER * DD * FFD];

// ---------------- helpers ----------------
__device__ __forceinline__ uint32_t smem_u32(const void* p) {
    uint32_t a;
    asm("{ .reg .u64 t; cvta.to.shared.u64 t, %1; cvt.u32.u64 %0, t; }" : "=r"(a) : "l"(p));
    return a;
}
// XOR-swizzled smem address: 128B rows, 16B segments, seg ^= (row & 7)
__device__ __forceinline__ uint32_t swz(uint32_t base, int row, int byteoff) {
    return base + row * 128 + (((byteoff >> 4) ^ (row & 7)) << 4);
}
__device__ __forceinline__ void cp_async16(uint32_t saddr, const void* gaddr) {
    asm volatile("cp.async.cg.shared.global [%0], [%1], 16;" :: "r"(saddr), "l"(gaddr));
}
__device__ __forceinline__ void cp_commit() {
    asm volatile("cp.async.commit_group;" ::: "memory");
}
template<int N>
__device__ __forceinline__ void cp_wait() {
    asm volatile("cp.async.wait_group %0;" :: "n"(N) : "memory");
}
__device__ __forceinline__ void ldsm_x4(uint32_t (&r)[4], uint32_t addr) {
    asm volatile("ldmatrix.sync.aligned.m8n8.x4.shared.b16 {%0,%1,%2,%3}, [%4];"
        : "=r"(r[0]), "=r"(r[1]), "=r"(r[2]), "=r"(r[3]) : "r"(addr));
}
__device__ __forceinline__ void ldsm_x4_trans(uint32_t (&r)[4], uint32_t addr) {
    asm volatile("ldmatrix.sync.aligned.m8n8.x4.trans.shared.b16 {%0,%1,%2,%3}, [%4];"
        : "=r"(r[0]), "=r"(r[1]), "=r"(r[2]), "=r"(r[3]) : "r"(addr));
}
__device__ __forceinline__ void mma16816(float (&d)[4], const uint32_t (&a)[4],
                                         uint32_t b0, uint32_t b1) {
    asm volatile("mma.sync.aligned.m16n8k16.row.col.f32.f16.f16.f32 "
        "{%0,%1,%2,%3}, {%4,%5,%6,%7}, {%8,%9}, {%0,%1,%2,%3};"
        : "+f"(d[0]), "+f"(d[1]), "+f"(d[2]), "+f"(d[3])
        : "r"(a[0]), "r"(a[1]), "r"(a[2]), "r"(a[3]), "r"(b0), "r"(b1));
}
__device__ __forceinline__ float gelu_exact(float x) {
    return 0.5f * x * (1.0f + erff(x * 0.70710678118654752f));
}
__device__ __forceinline__ uint32_t pack_h2(float f0, float f1) {
    __half2 h = __floats2half2_rn(f0, f1);
    return *(uint32_t*)&h;
}

// =====================================================================
// Dense fp16 GEMM: C = act(A @ B^T + bias)
// A (M,K) half row-major; B (N,K) half row-major. BM=128, BN=128, BK=64.
// XOR-swizzled smem (no padding). 3-stage cp.async pipeline.
// OUTMODE 0: fp32 C; 1: half C.
// =====================================================================
template<int ACT, int OUTMODE>
__global__ void __launch_bounds__(256, 2)
mma_gemm(const __half* __restrict__ A, const __half* __restrict__ B,
         const float* __restrict__ bias,
         float* __restrict__ Cf, __half* __restrict__ Ch,
         int K, int lda, int ldb, int ldc)
{
    extern __shared__ __align__(16) char sm[];
    constexpr int B_OFF = 128 * 128;       // 16384
    constexpr int STAGE = 2 * B_OFF;       // 32768

    const int tid = threadIdx.x;
    const int wid = tid >> 5, lane = tid & 31;
    const int warp_m = wid >> 1, warp_n = wid & 1;
    const int m0 = blockIdx.x * 128;
    const int n0 = blockIdx.y * 128;
    const uint32_t smem_base = smem_u32(sm);
    const int nch = K >> 6;

    float acc[2][8][4];
    #pragma unroll
    for (int a = 0; a < 2; a++)
        #pragma unroll
        for (int b = 0; b < 8; b++)
            #pragma unroll
            for (int c = 0; c < 4; c++) acc[a][b][c] = 0.f;

    auto load_stage = [&](int stage, int ch) {
        const int k0 = ch << 6;
        const uint32_t sbase = smem_base + stage * STAGE;
        #pragma unroll
        for (int i = tid; i < 1024; i += 256) {
            int row = i >> 3, seg = i & 7;
            cp_async16(sbase + row * 128 + ((seg ^ (row & 7)) << 4),
                       A + (long)(m0 + row) * lda + k0 + seg * 8);
        }
        #pragma unroll
        for (int i = tid; i < 1024; i += 256) {
            int row = i >> 3, seg = i & 7;
            cp_async16(sbase + B_OFF + row * 128 + ((seg ^ (row & 7)) << 4),
                       B + (long)(n0 + row) * ldb + k0 + seg * 8);
        }
        cp_commit();
    };

    auto compute = [&](int stage) {
        const uint32_t sbase = smem_base + stage * STAGE;
        const int arow = warp_m * 32 + (lane & 15);
        const int bn   = (lane & 7) + (lane >> 4) * 8;
        const int bka  = ((lane >> 3) & 1) * 8;
        #pragma unroll
        for (int kk = 0; kk < 4; kk++) {
            const int acol = kk * 16 + (lane >> 4) * 8;
            uint32_t af[2][4];
            #pragma unroll
            for (int mt = 0; mt < 2; mt++)
                ldsm_x4(af[mt], swz(sbase, arow + mt * 16, acol * 2));
            const int bk = kk * 16 + bka;
            #pragma unroll
            for (int nt2 = 0; nt2 < 4; nt2++) {
                uint32_t bf[4];
                ldsm_x4(bf, swz(sbase + B_OFF, warp_n * 64 + nt2 * 16 + bn, bk * 2));
                #pragma unroll
                for (int mt = 0; mt < 2; mt++) {
                    #pragma unroll
                    for (int j = 0; j < 2; j++)
                        mma16816(acc[mt][nt2 * 2 + j], af[mt], bf[2 * j], bf[2 * j + 1]);
                }
            }
        }
    };

    load_stage(0, 0);
    load_stage(1, 1);
    for (int ch = 0; ch < nch; ch++) {
        if (ch + 1 < nch) cp_wait<1>(); else cp_wait<0>();
        __syncthreads();
        if (ch + 2 < nch) load_stage((ch + 2) % 3, ch + 2);
        compute(ch % 3);
    }

    const int r0 = lane >> 2, c0 = (lane & 3) * 2;
    #pragma unroll
    for (int mt = 0; mt < 2; mt++) {
        #pragma unroll
        for (int nt = 0; nt < 8; nt++) {
            const int n = n0 + warp_n * 64 + nt * 8 + c0;
            float bv0 = bias ? bias[n] : 0.f;
            float bv1 = bias ? bias[n + 1] : 0.f;
            #pragma unroll
            for (int hrow = 0; hrow < 2; hrow++) {
                const int m = m0 + warp_m * 32 + mt * 16 + r0 + hrow * 8;
                float f0 = acc[mt][nt][hrow * 2 + 0] + bv0;
                float f1 = acc[mt][nt][hrow * 2 + 1] + bv1;
                if (ACT == 1) { f0 = gelu_exact(f0); f1 = gelu_exact(f1); }
                const long off = (long)m * ldc + n;
                if (OUTMODE == 0) *(float2*)(Cf + off) = make_float2(f0, f1);
                else              *(uint32_t*)(Ch + off) = pack_h2(f0, f1);
            }
        }
    }
}

// =====================================================================
// Flash attention (fp16): per CTA = (q-tile 128, one (b,h)). 8 warps x 16 rows.
// 64-key chunks, 3-stage pipeline, swizzled smem, V row-major + ldmatrix.trans.
// Mask fast paths: x-chunks (column-only), fully-causal-valid (no mask),
// diagonal (causal compare).
// =====================================================================
__global__ void __launch_bounds__(256, 2)
flash_kernel()
{
    extern __shared__ __align__(16) char fsm[];
    __shared__ uint32_t maskbits[16];
    constexpr int KV_OFF = 128 * 128;      // after Q (16384)
    constexpr int TILE = 64 * 128;         // 8192
    constexpr int KSTAGE = 2 * TILE;       // 16384

    const int bh = blockIdx.y;
    const int b = bh >> 4, h = bh & 15;
    const int q0 = blockIdx.x * 128;
    const int tid = threadIdx.x;
    const int wid = tid >> 5, lane = tid & 31;
    const uint32_t smem = smem_u32(fsm);

    if (tid < 16) {
        uint32_t m = 0;
        const int* xm = g_xmask + b * LX + tid * 32;
        #pragma unroll
        for (int i = 0; i < 32; i++) m |= (xm[i] ? 1u : 0u) << i;
        maskbits[tid] = m;
    }

    // load Q (own cp group)
    #pragma unroll
    for (int i = tid; i < 1024; i += 256) {
        int row = i >> 3, seg = i & 7;
        cp_async16(smem + row * 128 + ((seg ^ (row & 7)) << 4),
                   g_qkv + ((size_t)(b * SS + q0 + row)) * (3 * DD) + h * 64 + seg * 8);
    }
    cp_commit();

    const int nch = (q0 < LX) ? 8 : ((q0 + 128) >> 6);

    auto load_kv = [&](int c, int s) {
        const int k0 = c << 6;
        const uint32_t sb = smem + KV_OFF + s * KSTAGE;
        #pragma unroll
        for (int i = tid; i < 512; i += 256) {
            int row = i >> 3, seg = i & 7;
            cp_async16(sb + row * 128 + ((seg ^ (row & 7)) << 4),
                       g_qkv + ((size_t)(b * SS + k0 + row)) * (3 * DD) + DD + h * 64 + seg * 8);
        }
        #pragma unroll
        for (int i = tid; i < 512; i += 256) {
            int row = i >> 3, seg = i & 7;
            cp_async16(sb + TILE + row * 128 + ((seg ^ (row & 7)) << 4),
                       g_qkv + ((size_t)(b * SS + k0 + row)) * (3 * DD) + 2 * DD + h * 64 + seg * 8);
        }
        cp_commit();
    };

    load_kv(0, 0);
    load_kv(1, 1);

    float m_[2] = {-1e30f, -1e30f}, l_[2] = {0.f, 0.f};
    float out[8][4];
    #pragma unroll
    for (int j = 0; j < 8; j++)
        #pragma unroll
        for (int e = 0; e < 4; e++) out[j][e] = 0.f;

    const int r0 = lane >> 2;
    const int qrow0 = q0 + wid * 16 + r0;
    const int arow = wid * 16 + (lane & 15);
    const int bn   = (lane & 7) + (lane >> 4) * 8;
    const int bka  = ((lane >> 3) & 1) * 8;
    const int trow = (lane & 7) + ((lane >> 3) & 1) * 8;   // key row for trans V
    const int tcol = (lane >> 4) * 8;                      // d col half for trans V

    for (int c = 0; c < nch; c++) {
        if (c + 1 < nch) cp_wait<1>(); else cp_wait<0>();
        __syncthreads();
        if (c + 2 < nch) load_kv(c + 2, (c + 2) % 3);
        const uint32_t sb = smem + KV_OFF + (c % 3) * KSTAGE;

        // ---- QK ----
        float s[8][4];
        #pragma unroll
        for (int j = 0; j < 8; j++)
            #pragma unroll
            for (int e = 0; e < 4; e++) s[j][e] = 0.f;
        #pragma unroll
        for (int t = 0; t < 4; t++) {
            const int acol = t * 16 + (lane >> 4) * 8;
            uint32_t qf[4];
            ldsm_x4(qf, swz(smem, arow, acol * 2));
            const int bk = t * 16 + bka;
            #pragma unroll
            for (int j = 0; j < 4; j++) {
                uint32_t kf[4];
                ldsm_x4(kf, swz(sb, j * 16 + bn, bk * 2));
                mma16816(s[2 * j], qf, kf[0], kf[1]);
                mma16816(s[2 * j + 1], qf, kf[2], kf[3]);
            }
        }

        // ---- mask (fast paths) + online softmax ----
        const int k0 = c << 6;
        uint32_t vmask;
        float cmax[2] = {-1e30f, -1e30f};
        if (k0 + 64 <= LX) {
            // x-region chunk: validity depends on column only
            vmask = 0;
            #pragma unroll
            for (int j = 0; j < 8; j++) {
                #pragma unroll
                for (int e = 0; e < 4; e++) {
                    int col = k0 + j * 8 + (lane & 3) * 2 + (e & 1);
                    bool valid = !((maskbits[col >> 5] >> (col & 31)) & 1);
                    float sv = s[j][e] * 0.125f;
                    s[j][e] = sv;
                    if (valid) {
                        vmask |= 1u << (j * 4 + e);
                        cmax[e >> 1] = fmaxf(cmax[e >> 1], sv);
                    }
                }
            }
        } else if (k0 + 64 <= q0 + wid * 16) {
            // fully below the diagonal for this warp: all valid
            vmask = 0xffffffffu;
            #pragma unroll
            for (int j = 0; j < 8; j++) {
                #pragma unroll
                for (int e = 0; e < 4; e++) {
                    float sv = s[j][e] * 0.125f;
                    s[j][e] = sv;
                    cmax[e >> 1] = fmaxf(cmax[e >> 1], sv);
                }
            }
        } else {
            // diagonal chunk: causal compare
            vmask = 0;
            #pragma unroll
            for (int j = 0; j < 8; j++) {
                #pragma unroll
                for (int e = 0; e < 4; e++) {
                    int col = k0 + j * 8 + (lane & 3) * 2 + (e & 1);
                    int row = (e < 2) ? qrow0 : (qrow0 + 8);
                    float sv = s[j][e] * 0.125f;
                    s[j][e] = sv;
                    if (col <= row) {
                        vmask |= 1u << (j * 4 + e);
                        cmax[e >> 1] = fmaxf(cmax[e >> 1], sv);
                    }
                }
            }
        }
        #pragma unroll
        for (int o = 1; o <= 2; o <<= 1) {
            cmax[0] = fmaxf(cmax[0], __shfl_xor_sync(0xffffffffu, cmax[0], o));
            cmax[1] = fmaxf(cmax[1], __shfl_xor_sync(0xffffffffu, cmax[1], o));
        }
        float mn0 = fmaxf(m_[0], cmax[0]);
        float mn1 = fmaxf(m_[1], cmax[1]);
        float f0 = __expf(m_[0] - mn0);
        float f1 = __expf(m_[1] - mn1);
        float rs[2] = {0.f, 0.f};
        #pragma unroll
        for (int j = 0; j < 8; j++) {
            #pragma unroll
            for (int e = 0; e < 4; e++) {
                float mn = (e < 2) ? mn0 : mn1;
                float p = ((vmask >> (j * 4 + e)) & 1) ? __expf(s[j][e] - mn) : 0.f;
                s[j][e] = p;
                rs[e >> 1] += p;
            }
        }
        #pragma unroll
        for (int o = 1; o <= 2; o <<= 1) {
            rs[0] += __shfl_xor_sync(0xffffffffu, rs[0], o);
            rs[1] += __shfl_xor_sync(0xffffffffu, rs[1], o);
        }
        l_[0] = l_[0] * f0 + rs[0];
        l_[1] = l_[1] * f1 + rs[1];
        m_[0] = mn0; m_[1] = mn1;
        #pragma unroll
        for (int j = 0; j < 8; j++) {
            out[j][0] *= f0; out[j][1] *= f0;
            out[j][2] *= f1; out[j][3] *= f1;
        }

        // ---- PV: V row-major (keys x d), B frags via ldmatrix.trans ----
        #pragma unroll
        for (int t = 0; t < 4; t++) {
            uint32_t pf[4];
            pf[0] = pack_h2(s[2 * t][0], s[2 * t][1]);
            pf[1] = pack_h2(s[2 * t][2], s[2 * t][3]);
            pf[2] = pack_h2(s[2 * t + 1][0], s[2 * t + 1][1]);
            pf[3] = pack_h2(s[2 * t + 1][2], s[2 * t + 1][3]);
            #pragma unroll
            for (int j = 0; j < 4; j++) {
                uint32_t vf[4];
                ldsm_x4_trans(vf, swz(sb + TILE, t * 16 + trow, (j * 16 + tcol) * 2));
                mma16816(out[2 * j], pf, vf[0], vf[1]);
                mma16816(out[2 * j + 1], pf, vf[2], vf[3]);
            }
        }
    }

    // ---- epilogue ----
    float inv0 = 1.f / l_[0];
    float inv1 = 1.f / l_[1];
    #pragma unroll
    for (int j = 0; j < 8; j++) {
        const int d = h * 64 + j * 8 + (lane & 3) * 2;
        *(uint32_t*)(g_attno + ((size_t)(b * SS + qrow0)) * DD + d) =
            pack_h2(out[j][0] * inv0, out[j][1] * inv0);
        *(uint32_t*)(g_attno + ((size_t)(b * SS + qrow0 + 8)) * DD + d) =
            pack_h2(out[j][2] * inv1, out[j][3] * inv1);
    }
}

// ---------------- fp32 -> fp16 ----------------
__global__ void cvt_kernel(const float* __restrict__ src,
                           __half* __restrict__ h, long n4)
{
    long i = (long)blockIdx.x * blockDim.x + threadIdx.x;
    if (i >= n4) return;
    float4 v = *(const float4*)(src + i * 4);
    uint2 hv;
    hv.x = pack_h2(v.x, v.y);
    hv.y = pack_h2(v.z, v.w);
    *(uint2*)(h + i * 4) = hv;
}

// ---------------- embedding: x tokens ----------------
__global__ void embed_x_kernel(const float* __restrict__ x,
                               const float* __restrict__ W_nail,
                               const float* __restrict__ b_nail)
{
    const float RSC = 0.99995000374968753f;
    int row = blockIdx.x;
    int b = row / LX;
    const float* xr = x + (long)row * 64;
    __shared__ float xn[63];
    __shared__ float t_sh;
    int tid = threadIdx.x;
    if (tid == 0) {
        float t0 = xr[0];
        g_xmask[row] = isnan(t0) ? 1 : 0;
        t_sh = isnan(t0) ? 0.f : t0;
    }
    if (tid < 63) {
        float v = xr[tid + 1];
        if (isnan(v)) v = 0.f;
        v *= RSC;
        xn[tid] = fminf(fmaxf(v, -5.f), 5.f);
    }
    __syncthreads();
    float t = t_sh;
    const float kfac = -logf(1000.f) / 1024.f;
    for (int d = tid; d < DD; d += 256) {
        const float* wr = W_nail + d * 63;
        float acc = b_nail[d];
        #pragma unroll 7
        for (int c = 0; c < 63; c++) acc = fmaf(xn[c], wr[c], acc);
        int i = d >> 1;
        float ang = t * expf((float)i * kfac);
        acc += (d & 1) ? cosf(ang) : sinf(ang);
        size_t idx = ((size_t)b * SS + (row % LX)) * DD + d;
        g_tgt[idx] = acc;
        g_tgt_s[idx] = __float2half_rn(acc);
    }
}

// ---------------- embedding: w tokens + global PE ----------------
__global__ void embed_w_kernel(const float* __restrict__ w,
                               const float* __restrict__ W_cond,
                               const float* __restrict__ b_cond)
{
    const float RSC = 0.99995000374968753f;
    int row = blockIdx.x;
    int b = row / NWTOK, r = row % NWTOK;
    const float* wr6 = w + (long)b * (NWTOK * 6) + r * 6;
    __shared__ float wn[6];
    int tid = threadIdx.x;
    if (tid < 6) {
        float v = wr6[tid];
        if (isnan(v)) v = 0.f;
        v *= RSC;
        wn[tid] = fminf(fmaxf(v, -5.f), 5.f);
    }
    __syncthreads();
    int spos = LX + r;
    const float kfac = -logf(1000.f) / 1024.f;
    for (int d = tid; d < DD; d += 256) {
        const float* wc = W_cond + d * 6;
        float acc = b_cond[d];
        #pragma unroll
        for (int c = 0; c < 6; c++) acc = fmaf(wn[c], wc[c], acc);
        int i = d >> 1;
        float ang = (float)spos * expf((float)i * kfac);
        acc += (d & 1) ? cosf(ang) : sinf(ang);
        size_t idx = ((size_t)b * SS + spos) * DD + d;
        g_tgt[idx] = acc;
        g_tgt_s[idx] = __float2half_rn(acc);
    }
}

// ---------------- residual add + LayerNorm (in-place, emits fp16) ----------------
__global__ void resid_ln_kernel(const float* __restrict__ delta,
                                const float* __restrict__ g,
                                const float* __restrict__ beta)
{
    size_t row = blockIdx.x;
    float* t = g_tgt + row * DD;
    const float* dl = delta + row * DD;
    int tid = threadIdx.x;
    float v[4];
    float s = 0.f;
    #pragma unroll
    for (int i = 0; i < 4; i++) { int idx = tid + i * 256; v[i] = t[idx] + dl[idx]; s += v[i]; }
    __shared__ float red[256];
    red[tid] = s; __syncthreads();
    #pragma unroll
    for (int o = 128; o > 0; o >>= 1) { if (tid < o) red[tid] += red[tid + o]; __syncthreads(); }
    float mean = red[0] * (1.f / 1024.f);
    __syncthreads();
    float s2 = 0.f;
    #pragma unroll
    for (int i = 0; i < 4; i++) { float d = v[i] - mean; s2 += d * d; }
    red[tid] = s2; __syncthreads();
    #pragma unroll
    for (int o = 128; o > 0; o >>= 1) { if (tid < o) red[tid] += red[tid + o]; __syncthreads(); }
    float inv = rsqrtf(red[0] * (1.f / 1024.f) + 1e-5f);
    #pragma unroll
    for (int i = 0; i < 4; i++) {
        int idx = tid + i * 256;
        float out = (v[i] - mean) * inv * g[idx] + beta[idx];
        t[idx] = out;
        g_tgt_s[row * DD + idx] = __float2half_rn(out);
    }
}

// ---------------- head + loss ----------------
__global__ void loss_kernel(const float* __restrict__ W_ham, const float* __restrict__ b_ham,
                            const float* __restrict__ y, const float* __restrict__ w,
                            float* __restrict__ out)
{
    __shared__ float red[256];
    int tid = threadIdx.x;
    float acc = 0.f;
    for (int idx = tid; idx < BB * 144; idx += 256) {
        int b = idx / 144;
        int j = idx % 144;
        const float* row = g_tgt + ((size_t)b * SS + (SS - 1)) * DD;
        const float* wr = W_ham + (size_t)j * DD;
        float dot = b_ham[j];
        for (int k = 0; k < DD; k++) dot = fmaf(row[k], wr[k], dot);
        float yr = y[b * 144 + j] - w[(size_t)b * 2304 + 2160 + j];
        float d = dot - yr;
        acc += d * d;
    }
    red[tid] = acc; __syncthreads();
    #pragma unroll
    for (int o = 128; o > 0; o >>= 1) { if (tid < o) red[tid] += red[tid + o]; __syncthreads(); }
    if (tid == 0) out[0] = red[0] / (float)(BB * 144);
}

// ---------------- launch ----------------
extern "C" void kernel_launch(void* const* d_in, const int* in_sizes, int n_in,
                              void* d_out, int out_size)
{
    const float* x      = (const float*)d_in[0];
    const float* w      = (const float*)d_in[1];
    const float* y      = (const float*)d_in[2];
    const float* W_nail = (const float*)d_in[3];
    const float* b_nail = (const float*)d_in[4];
    const float* W_cond = (const float*)d_in[5];
    const float* b_cond = (const float*)d_in[6];
    const float* Wqkv   = (const float*)d_in[7];
    const float* bqkv   = (const float*)d_in[8];
    const float* Wo     = (const float*)d_in[9];
    const float* bo     = (const float*)d_in[10];
    const float* ln1_g  = (const float*)d_in[11];
    const float* ln1_b  = (const float*)d_in[12];
    const float* ln2_g  = (const float*)d_in[13];
    const float* ln2_b  = (const float*)d_in[14];
    const float* W1     = (const float*)d_in[15];
    const float* b1     = (const float*)d_in[16];
    const float* W2     = (const float*)d_in[17];
    const float* b2     = (const float*)d_in[18];
    const float* W_ham  = (const float*)d_in[19];
    const float* b_ham  = (const float*)d_in[20];

    float *p_tgt, *p_tmp;
    __half *p_tgt_s, *p_qkv, *p_attno, *p_hid;
    __half *p_wqkv, *p_wo, *p_w1, *p_w2;
    cudaGetSymbolAddress((void**)&p_tgt,   g_tgt);
    cudaGetSymbolAddress((void**)&p_tmp,   g_tmp);
    cudaGetSymbolAddress((void**)&p_tgt_s, g_tgt_s);
    cudaGetSymbolAddress((void**)&p_qkv,   g_qkv);
    cudaGetSymbolAddress((void**)&p_attno, g_attno);
    cudaGetSymbolAddress((void**)&p_hid,   g_hid);
    cudaGetSymbolAddress((void**)&p_wqkv,  g_wqkv);
    cudaGetSymbolAddress((void**)&p_wo,    g_wo);
    cudaGetSymbolAddress((void**)&p_w1,    g_w1);
    cudaGetSymbolAddress((void**)&p_w2,    g_w2);

    static const int SMG = 32768 * 3;              // 98304 (3 stages, swizzled)
    static const int SMF = 16384 + 3 * 16384;      // 65536 (Q + 3 KV stages)
    cudaFuncSetAttribute(mma_gemm<0, 0>, cudaFuncAttributeMaxDynamicSharedMemorySize, SMG);
    cudaFuncSetAttribute(mma_gemm<0, 1>, cudaFuncAttributeMaxDynamicSharedMemorySize, SMG);
    cudaFuncSetAttribute(mma_gemm<1, 1>, cudaFuncAttributeMaxDynamicSharedMemorySize, SMG);
    cudaFuncSetAttribute(flash_kernel,   cudaFuncAttributeMaxDynamicSharedMemorySize, SMF);

    const int M = BB * SS;   // 7168
    dim3 blk(256);

    // weight conversions
    {
        long n;
        n = (long)NLAYER * 3 * DD * DD / 4;
        cvt_kernel<<<(unsigned)((n + 255) / 256), blk>>>(Wqkv, p_wqkv, n);
        n = (long)NLAYER * DD * DD / 4;
        cvt_kernel<<<(unsigned)((n + 255) / 256), blk>>>(Wo, p_wo, n);
        n = (long)NLAYER * FFD * DD / 4;
        cvt_kernel<<<(unsigned)((n + 255) / 256), blk>>>(W1, p_w1, n);
        n = (long)NLAYER * DD * FFD / 4;
        cvt_kernel<<<(unsigned)((n + 255) / 256), blk>>>(W2, p_w2, n);
    }

    embed_x_kernel<<<BB * LX, blk>>>(x, W_nail, b_nail);
    embed_w_kernel<<<BB * NWTOK, blk>>>(w, W_cond, b_cond);

    for (int l = 0; l < NLAYER; l++) {
        const __half* wqkv_l = p_wqkv + (size_t)l * 3 * DD * DD;
        const __half* wo_l   = p_wo + (size_t)l * DD * DD;
        const __half* w1_l   = p_w1 + (size_t)l * FFD * DD;
        const __half* w2_l   = p_w2 + (size_t)l * DD * FFD;

        // QKV: (7168 x 3072 x 1024) -> fp16
        mma_gemm<0, 1><<<dim3(M / 128, 3 * DD / 128), blk, SMG>>>(
            p_tgt_s, wqkv_l, bqkv + (size_t)l * 3 * DD,
            nullptr, p_qkv, DD, DD, DD, 3 * DD);

        // flash attention -> attno (fp16, token-major)
        flash_kernel<<<dim3(SS / 128, BB * NH), blk, SMF>>>();

        // tmp = attno @ Wo^T + bo  -> fp32
        mma_gemm<0, 0><<<dim3(M / 128, DD / 128), blk, SMG>>>(
            p_attno, wo_l, bo + (size_t)l * DD,
            p_tmp, nullptr, DD, DD, DD, DD);

        resid_ln_kernel<<<M, blk>>>(p_tmp, ln1_g + (size_t)l * DD, ln1_b + (size_t)l * DD);

        // hid = gelu(tgt @ W1^T + b1) -> fp16
        mma_gemm<1, 1><<<dim3(M / 128, FFD / 128), blk, SMG>>>(
            p_tgt_s, w1_l, b1 + (size_t)l * FFD,
            nullptr, p_hid, DD, DD, DD, FFD);

        // tmp = hid @ W2^T + b2 -> fp32
        mma_gemm<0, 0><<<dim3(M / 128, DD / 128), blk, SMG>>>(
            p_hid, w2_l, b2 + (size_t)l * DD,
            p_tmp, nullptr, FFD, FFD, FFD, DD);

        resid_ln_kernel<<<M, blk>>>(p_tmp, ln2_g + (size_t)l * DD, ln2_b + (size_t)l * DD);
    }

    loss_kernel<<<1, blk>>>(W_ham, b_ham, y, w, (float*)d_out);
}

// round 8
// speedup vs baseline: 10.7404x; 1.0160x over previous
#include <cuda_runtime.h>
#include <cuda_fp16.h>
#include <math.h>
#include <stdint.h>

// Problem dims (fixed by setup_inputs)
#define BB 8
#define LX 512
#define NWTOK 384
#define SS 896
#define DD 1024
#define NH 16
#define HD 64
#define FFD 4096
#define NLAYER 4

// ---------------- scratch (device globals) ----------------
__device__ float g_tgt[BB * SS * DD];
__device__ __half g_tgt_s[BB * SS * DD];
__device__ __half g_qkv[(size_t)BB * SS * 3 * DD];
__device__ __half g_attno[(size_t)BB * SS * DD];
__device__ __half g_hid[(size_t)BB * SS * FFD];
__device__ __half g_tmp_h[BB * SS * DD];
__device__ int   g_xmask[BB * LX];
// weights fp16
__device__ __half g_wqkv[(size_t)NLAYER * 3 * DD * DD];
__device__ __half g_wo[(size_t)NLAYER * DD * DD];
__device__ __half g_w1[(size_t)NLAYER * FFD * DD];
__device__ __half g_w2[(size_t)NLAYER * DD * FFD];

// scores arrive pre-multiplied by 0.125*log2(e); softmax works in log2 domain
#define QSCALE 0.18033688011112042f

// ---------------- helpers ----------------
__device__ __forceinline__ uint32_t smem_u32(const void* p) {
    uint32_t a;
    asm("{ .reg .u64 t; cvta.to.shared.u64 t, %1; cvt.u32.u64 %0, t; }" : "=r"(a) : "l"(p));
    return a;
}
__device__ __forceinline__ uint32_t swz(uint32_t base, int row, int byteoff) {
    return base + row * 128 + (((byteoff >> 4) ^ (row & 7)) << 4);
}
__device__ __forceinline__ void cp_async16(uint32_t saddr, const void* gaddr) {
    asm volatile("cp.async.cg.shared.global [%0], [%1], 16;" :: "r"(saddr), "l"(gaddr));
}
__device__ __forceinline__ void cp_commit() {
    asm volatile("cp.async.commit_group;" ::: "memory");
}
template<int N>
__device__ __forceinline__ void cp_wait() {
    asm volatile("cp.async.wait_group %0;" :: "n"(N) : "memory");
}
__device__ __forceinline__ void ldsm_x4(uint32_t (&r)[4], uint32_t addr) {
    asm volatile("ldmatrix.sync.aligned.m8n8.x4.shared.b16 {%0,%1,%2,%3}, [%4];"
        : "=r"(r[0]), "=r"(r[1]), "=r"(r[2]), "=r"(r[3]) : "r"(addr));
}
__device__ __forceinline__ void ldsm_x4_trans(uint32_t (&r)[4], uint32_t addr) {
    asm volatile("ldmatrix.sync.aligned.m8n8.x4.trans.shared.b16 {%0,%1,%2,%3}, [%4];"
        : "=r"(r[0]), "=r"(r[1]), "=r"(r[2]), "=r"(r[3]) : "r"(addr));
}
__device__ __forceinline__ void mma16816(float (&d)[4], const uint32_t (&a)[4],
                                         uint32_t b0, uint32_t b1) {
    asm volatile("mma.sync.aligned.m16n8k16.row.col.f32.f16.f16.f32 "
        "{%0,%1,%2,%3}, {%4,%5,%6,%7}, {%8,%9}, {%0,%1,%2,%3};"
        : "+f"(d[0]), "+f"(d[1]), "+f"(d[2]), "+f"(d[3])
        : "r"(a[0]), "r"(a[1]), "r"(a[2]), "r"(a[3]), "r"(b0), "r"(b1));
}
__device__ __forceinline__ float gelu_exact(float x) {
    return 0.5f * x * (1.0f + erff(x * 0.70710678118654752f));
}
__device__ __forceinline__ uint32_t pack_h2(float f0, float f1) {
    __half2 h = __floats2half2_rn(f0, f1);
    return *(uint32_t*)&h;
}
__device__ __forceinline__ uint32_t ex2_h2(uint32_t t) {
    uint32_t r;
    asm("ex2.approx.f16x2 %0, %1;" : "=r"(r) : "r"(t));
    return r;
}
__device__ __forceinline__ float ex2f(float x) {
    float r;
    asm("ex2.approx.f32 %0, %1;" : "=f"(r) : "f"(x));
    return r;
}

// =====================================================================
// Dense fp16 GEMM: C = act(A @ B^T + bias) [optionally scale cols<1024 by QSCALE]
// A (M,K) half row-major; B (N,K) half row-major. BM=128, BN=128, BK=64.
// XOR-swizzled smem, 3-stage cp.async pipeline. Output: half C.
// =====================================================================
template<int ACT, int SCALEQ>
__global__ void __launch_bounds__(256, 2)
mma_gemm(const __half* __restrict__ A, const __half* __restrict__ B,
         const float* __restrict__ bias, __half* __restrict__ Ch,
         int K, int lda, int ldb, int ldc)
{
    extern __shared__ __align__(16) char sm[];
    constexpr int B_OFF = 128 * 128;
    constexpr int STAGE = 2 * B_OFF;

    const int tid = threadIdx.x;
    const int wid = tid >> 5, lane = tid & 31;
    const int warp_m = wid >> 1, warp_n = wid & 1;
    const int m0 = blockIdx.x * 128;
    const int n0 = blockIdx.y * 128;
    const uint32_t smem_base = smem_u32(sm);
    const int nch = K >> 6;

    float acc[2][8][4];
    #pragma unroll
    for (int a = 0; a < 2; a++)
        #pragma unroll
        for (int b = 0; b < 8; b++)
            #pragma unroll
            for (int c = 0; c < 4; c++) acc[a][b][c] = 0.f;

    auto load_stage = [&](int stage, int ch) {
        const int k0 = ch << 6;
        const uint32_t sbase = smem_base + stage * STAGE;
        #pragma unroll
        for (int i = tid; i < 1024; i += 256) {
            int row = i >> 3, seg = i & 7;
            cp_async16(sbase + row * 128 + ((seg ^ (row & 7)) << 4),
                       A + (long)(m0 + row) * lda + k0 + seg * 8);
        }
        #pragma unroll
        for (int i = tid; i < 1024; i += 256) {
            int row = i >> 3, seg = i & 7;
            cp_async16(sbase + B_OFF + row * 128 + ((seg ^ (row & 7)) << 4),
                       B + (long)(n0 + row) * ldb + k0 + seg * 8);
        }
        cp_commit();
    };

    auto compute = [&](int stage) {
        const uint32_t sbase = smem_base + stage * STAGE;
        const int arow = warp_m * 32 + (lane & 15);
        const int bn   = (lane & 7) + (lane >> 4) * 8;
        const int bka  = ((lane >> 3) & 1) * 8;
        #pragma unroll
        for (int kk = 0; kk < 4; kk++) {
            const int acol = kk * 16 + (lane >> 4) * 8;
            uint32_t af[2][4];
            #pragma unroll
            for (int mt = 0; mt < 2; mt++)
                ldsm_x4(af[mt], swz(sbase, arow + mt * 16, acol * 2));
            const int bk = kk * 16 + bka;
            #pragma unroll
            for (int nt2 = 0; nt2 < 4; nt2++) {
                uint32_t bf[4];
                ldsm_x4(bf, swz(sbase + B_OFF, warp_n * 64 + nt2 * 16 + bn, bk * 2));
                #pragma unroll
                for (int mt = 0; mt < 2; mt++) {
                    #pragma unroll
                    for (int j = 0; j < 2; j++)
                        mma16816(acc[mt][nt2 * 2 + j], af[mt], bf[2 * j], bf[2 * j + 1]);
                }
            }
        }
    };

    load_stage(0, 0);
    load_stage(1, 1);
    for (int ch = 0; ch < nch; ch++) {
        if (ch + 1 < nch) cp_wait<1>(); else cp_wait<0>();
        __syncthreads();
        if (ch + 2 < nch) load_stage((ch + 2) % 3, ch + 2);
        compute(ch % 3);
    }

    const int r0 = lane >> 2, c0 = (lane & 3) * 2;
    #pragma unroll
    for (int mt = 0; mt < 2; mt++) {
        #pragma unroll
        for (int nt = 0; nt < 8; nt++) {
            const int n = n0 + warp_n * 64 + nt * 8 + c0;
            float bv0 = bias ? bias[n] : 0.f;
            float bv1 = bias ? bias[n + 1] : 0.f;
            #pragma unroll
            for (int hrow = 0; hrow < 2; hrow++) {
                const int m = m0 + warp_m * 32 + mt * 16 + r0 + hrow * 8;
                float f0 = acc[mt][nt][hrow * 2 + 0] + bv0;
                float f1 = acc[mt][nt][hrow * 2 + 1] + bv1;
                if (ACT == 1) { f0 = gelu_exact(f0); f1 = gelu_exact(f1); }
                if (SCALEQ && n < DD) { f0 *= QSCALE; f1 *= QSCALE; }
                *(uint32_t*)(Ch + (long)m * ldc + n) = pack_h2(f0, f1);
            }
        }
    }
}

// =====================================================================
// Flash attention (fp16): per CTA = (q-tile 128, one (b,h)). 8 warps x 16 rows.
// Q pre-scaled by 0.125*log2e -> softmax in log2 domain with ex2.approx.f16x2.
// 64-key chunks, 3-stage pipeline, swizzled smem, V row-major + ldmatrix.trans.
// =====================================================================
__global__ void __launch_bounds__(256, 2)
flash_kernel()
{
    extern __shared__ __align__(16) char fsm[];
    __shared__ uint32_t maskbits[16];
    constexpr int KV_OFF = 128 * 128;
    constexpr int TILE = 64 * 128;
    constexpr int KSTAGE = 2 * TILE;

    const int bh = blockIdx.y;
    const int b = bh >> 4, h = bh & 15;
    const int q0 = (gridDim.x - 1 - blockIdx.x) * 128;   // long CTAs first
    const int tid = threadIdx.x;
    const int wid = tid >> 5, lane = tid & 31;
    const uint32_t smem = smem_u32(fsm);

    if (tid < 16) {
        uint32_t m = 0;
        const int* xm = g_xmask + b * LX + tid * 32;
        #pragma unroll
        for (int i = 0; i < 32; i++) m |= (xm[i] ? 1u : 0u) << i;
        maskbits[tid] = m;
    }

    // load Q
    #pragma unroll
    for (int i = tid; i < 1024; i += 256) {
        int row = i >> 3, seg = i & 7;
        cp_async16(smem + row * 128 + ((seg ^ (row & 7)) << 4),
                   g_qkv + ((size_t)(b * SS + q0 + row)) * (3 * DD) + h * 64 + seg * 8);
    }
    cp_commit();

    const int nch = (q0 < LX) ? 8 : ((q0 + 128) >> 6);

    auto load_kv = [&](int c, int s) {
        const int k0 = c << 6;
        const uint32_t sb = smem + KV_OFF + s * KSTAGE;
        #pragma unroll
        for (int i = tid; i < 512; i += 256) {
            int row = i >> 3, seg = i & 7;
            cp_async16(sb + row * 128 + ((seg ^ (row & 7)) << 4),
                       g_qkv + ((size_t)(b * SS + k0 + row)) * (3 * DD) + DD + h * 64 + seg * 8);
        }
        #pragma unroll
        for (int i = tid; i < 512; i += 256) {
            int row = i >> 3, seg = i & 7;
            cp_async16(sb + TILE + row * 128 + ((seg ^ (row & 7)) << 4),
                       g_qkv + ((size_t)(b * SS + k0 + row)) * (3 * DD) + 2 * DD + h * 64 + seg * 8);
        }
        cp_commit();
    };

    load_kv(0, 0);
    load_kv(1, 1);

    float m_[2] = {-1e30f, -1e30f}, l_[2] = {0.f, 0.f};
    float out[8][4];
    #pragma unroll
    for (int j = 0; j < 8; j++)
        #pragma unroll
        for (int e = 0; e < 4; e++) out[j][e] = 0.f;

    const int r0 = lane >> 2;
    const int qrow0 = q0 + wid * 16 + r0;
    const int arow = wid * 16 + (lane & 15);
    const int bn   = (lane & 7) + (lane >> 4) * 8;
    const int bka  = ((lane >> 3) & 1) * 8;
    const int trow = (lane & 7) + ((lane >> 3) & 1) * 8;
    const int tcol = (lane >> 4) * 8;

    for (int c = 0; c < nch; c++) {
        if (c + 1 < nch) cp_wait<1>(); else cp_wait<0>();
        __syncthreads();
        if (c + 2 < nch) load_kv(c + 2, (c + 2) % 3);
        const uint32_t sb = smem + KV_OFF + (c % 3) * KSTAGE;

        // ---- QK (scores already in log2 units via Q pre-scale) ----
        float s[8][4];
        #pragma unroll
        for (int j = 0; j < 8; j++)
            #pragma unroll
            for (int e = 0; e < 4; e++) s[j][e] = 0.f;
        #pragma unroll
        for (int t = 0; t < 4; t++) {
            const int acol = t * 16 + (lane >> 4) * 8;
            uint32_t qf[4];
            ldsm_x4(qf, swz(smem, arow, acol * 2));
            const int bk = t * 16 + bka;
            #pragma unroll
            for (int j = 0; j < 4; j++) {
                uint32_t kf[4];
                ldsm_x4(kf, swz(sb, j * 16 + bn, bk * 2));
                mma16816(s[2 * j], qf, kf[0], kf[1]);
                mma16816(s[2 * j + 1], qf, kf[2], kf[3]);
            }
        }

        // ---- mask (fast paths): build vmask + per-row max ----
        const int k0 = c << 6;
        uint32_t vmask;
        float cmax[2] = {-1e30f, -1e30f};
        if (k0 + 64 <= LX) {
            vmask = 0;
            #pragma unroll
            for (int j = 0; j < 8; j++) {
                #pragma unroll
                for (int e = 0; e < 4; e++) {
                    int col = k0 + j * 8 + (lane & 3) * 2 + (e & 1);
                    if (!((maskbits[col >> 5] >> (col & 31)) & 1)) {
                        vmask |= 1u << (j * 4 + e);
                        cmax[e >> 1] = fmaxf(cmax[e >> 1], s[j][e]);
                    }
                }
            }
        } else if (k0 + 64 <= q0 + wid * 16) {
            vmask = 0xffffffffu;
            #pragma unroll
            for (int j = 0; j < 8; j++) {
                #pragma unroll
                for (int e = 0; e < 4; e++)
                    cmax[e >> 1] = fmaxf(cmax[e >> 1], s[j][e]);
            }
        } else {
            vmask = 0;
            #pragma unroll
            for (int j = 0; j < 8; j++) {
                #pragma unroll
                for (int e = 0; e < 4; e++) {
                    int col = k0 + j * 8 + (lane & 3) * 2 + (e & 1);
                    int row = (e < 2) ? qrow0 : (qrow0 + 8);
                    if (col <= row) {
                        vmask |= 1u << (j * 4 + e);
                        cmax[e >> 1] = fmaxf(cmax[e >> 1], s[j][e]);
                    }
                }
            }
        }
        #pragma unroll
        for (int o = 1; o <= 2; o <<= 1) {
            cmax[0] = fmaxf(cmax[0], __shfl_xor_sync(0xffffffffu, cmax[0], o));
            cmax[1] = fmaxf(cmax[1], __shfl_xor_sync(0xffffffffu, cmax[1], o));
        }
        float mn0 = fmaxf(m_[0], cmax[0]);
        float mn1 = fmaxf(m_[1], cmax[1]);
        float f0 = ex2f(m_[0] - mn0);
        float f1 = ex2f(m_[1] - mn1);

        // ---- probabilities via ex2.f16x2; results ARE the PV fragments ----
        uint32_t ph01[8], ph23[8];
        __half2 a01 = __floats2half2_rn(0.f, 0.f);
        __half2 a23 = a01;
        #pragma unroll
        for (int j = 0; j < 8; j++) {
            float t0 = ((vmask >> (j * 4 + 0)) & 1) ? (s[j][0] - mn0) : -100.f;
            float t1 = ((vmask >> (j * 4 + 1)) & 1) ? (s[j][1] - mn0) : -100.f;
            float t2 = ((vmask >> (j * 4 + 2)) & 1) ? (s[j][2] - mn1) : -100.f;
            float t3 = ((vmask >> (j * 4 + 3)) & 1) ? (s[j][3] - mn1) : -100.f;
            ph01[j] = ex2_h2(pack_h2(t0, t1));
            ph23[j] = ex2_h2(pack_h2(t2, t3));
            a01 = __hadd2(a01, *(__half2*)&ph01[j]);
            a23 = __hadd2(a23, *(__half2*)&ph23[j]);
        }
        float2 s01 = __half22float2(a01);
        float2 s23 = __half22float2(a23);
        float rs0 = s01.x + s01.y;
        float rs1 = s23.x + s23.y;
        #pragma unroll
        for (int o = 1; o <= 2; o <<= 1) {
            rs0 += __shfl_xor_sync(0xffffffffu, rs0, o);
            rs1 += __shfl_xor_sync(0xffffffffu, rs1, o);
        }
        l_[0] = l_[0] * f0 + rs0;
        l_[1] = l_[1] * f1 + rs1;
        m_[0] = mn0; m_[1] = mn1;
        if (f0 != 1.f) {
            #pragma unroll
            for (int j = 0; j < 8; j++) { out[j][0] *= f0; out[j][1] *= f0; }
        }
        if (f1 != 1.f) {
            #pragma unroll
            for (int j = 0; j < 8; j++) { out[j][2] *= f1; out[j][3] *= f1; }
        }

        // ---- PV ----
        #pragma unroll
        for (int t = 0; t < 4; t++) {
            uint32_t pf[4] = { ph01[2 * t], ph23[2 * t], ph01[2 * t + 1], ph23[2 * t + 1] };
            #pragma unroll
            for (int j = 0; j < 4; j++) {
                uint32_t vf[4];
                ldsm_x4_trans(vf, swz(sb + TILE, t * 16 + trow, (j * 16 + tcol) * 2));
                mma16816(out[2 * j], pf, vf[0], vf[1]);
                mma16816(out[2 * j + 1], pf, vf[2], vf[3]);
            }
        }
    }

    // ---- epilogue ----
    float inv0 = 1.f / l_[0];
    float inv1 = 1.f / l_[1];
    #pragma unroll
    for (int j = 0; j < 8; j++) {
        const int d = h * 64 + j * 8 + (lane & 3) * 2;
        *(uint32_t*)(g_attno + ((size_t)(b * SS + qrow0)) * DD + d) =
            pack_h2(out[j][0] * inv0, out[j][1] * inv0);
        *(uint32_t*)(g_attno + ((size_t)(b * SS + qrow0 + 8)) * DD + d) =
            pack_h2(out[j][2] * inv1, out[j][3] * inv1);
    }
}

// ---------------- fp32 -> fp16 ----------------
__global__ void cvt_kernel(const float* __restrict__ src,
                           __half* __restrict__ h, long n4)
{
    long i = (long)blockIdx.x * blockDim.x + threadIdx.x;
    if (i >= n4) return;
    float4 v = *(const float4*)(src + i * 4);
    uint2 hv;
    hv.x = pack_h2(v.x, v.y);
    hv.y = pack_h2(v.z, v.w);
    *(uint2*)(h + i * 4) = hv;
}

// ---------------- embedding: x tokens ----------------
__global__ void embed_x_kernel(const float* __restrict__ x,
                               const float* __restrict__ W_nail,
                               const float* __restrict__ b_nail)
{
    const float RSC = 0.99995000374968753f;
    int row = blockIdx.x;
    int b = row / LX;
    const float* xr = x + (long)row * 64;
    __shared__ float xn[63];
    __shared__ float t_sh;
    int tid = threadIdx.x;
    if (tid == 0) {
        float t0 = xr[0];
        g_xmask[row] = isnan(t0) ? 1 : 0;
        t_sh = isnan(t0) ? 0.f : t0;
    }
    if (tid < 63) {
        float v = xr[tid + 1];
        if (isnan(v)) v = 0.f;
        v *= RSC;
        xn[tid] = fminf(fmaxf(v, -5.f), 5.f);
    }
    __syncthreads();
    float t = t_sh;
    const float kfac = -logf(1000.f) / 1024.f;
    for (int d = tid; d < DD; d += 256) {
        const float* wr = W_nail + d * 63;
        float acc = b_nail[d];
        #pragma unroll 7
        for (int c = 0; c < 63; c++) acc = fmaf(xn[c], wr[c], acc);
        int i = d >> 1;
        float ang = t * expf((float)i * kfac);
        acc += (d & 1) ? cosf(ang) : sinf(ang);
        size_t idx = ((size_t)b * SS + (row % LX)) * DD + d;
        g_tgt[idx] = acc;
        g_tgt_s[idx] = __float2half_rn(acc);
    }
}

// ---------------- embedding: w tokens + global PE ----------------
__global__ void embed_w_kernel(const float* __restrict__ w,
                               const float* __restrict__ W_cond,
                               const float* __restrict__ b_cond)
{
    const float RSC = 0.99995000374968753f;
    int row = blockIdx.x;
    int b = row / NWTOK, r = row % NWTOK;
    const float* wr6 = w + (long)b * (NWTOK * 6) + r * 6;
    __shared__ float wn[6];
    int tid = threadIdx.x;
    if (tid < 6) {
        float v = wr6[tid];
        if (isnan(v)) v = 0.f;
        v *= RSC;
        wn[tid] = fminf(fmaxf(v, -5.f), 5.f);
    }
    __syncthreads();
    int spos = LX + r;
    const float kfac = -logf(1000.f) / 1024.f;
    for (int d = tid; d < DD; d += 256) {
        const float* wc = W_cond + d * 6;
        float acc = b_cond[d];
        #pragma unroll
        for (int c = 0; c < 6; c++) acc = fmaf(wn[c], wc[c], acc);
        int i = d >> 1;
        float ang = (float)spos * expf((float)i * kfac);
        acc += (d & 1) ? cosf(ang) : sinf(ang);
        size_t idx = ((size_t)b * SS + spos) * DD + d;
        g_tgt[idx] = acc;
        g_tgt_s[idx] = __float2half_rn(acc);
    }
}

// ---------------- residual add + LayerNorm (in-place, half delta, emits fp16) ----------------
__global__ void resid_ln_kernel(const __half* __restrict__ delta,
                                const float* __restrict__ g,
                                const float* __restrict__ beta)
{
    size_t row = blockIdx.x;
    float* t = g_tgt + row * DD;
    const __half* dl = delta + row * DD;
    int tid = threadIdx.x;
    float v[4];
    float s = 0.f;
    #pragma unroll
    for (int i = 0; i < 4; i++) {
        int idx = tid + i * 256;
        v[i] = t[idx] + __half2float(dl[idx]);
        s += v[i];
    }
    __shared__ float red[256];
    red[tid] = s; __syncthreads();
    #pragma unroll
    for (int o = 128; o > 0; o >>= 1) { if (tid < o) red[tid] += red[tid + o]; __syncthreads(); }
    float mean = red[0] * (1.f / 1024.f);
    __syncthreads();
    float s2 = 0.f;
    #pragma unroll
    for (int i = 0; i < 4; i++) { float d = v[i] - mean; s2 += d * d; }
    red[tid] = s2; __syncthreads();
    #pragma unroll
    for (int o = 128; o > 0; o >>= 1) { if (tid < o) red[tid] += red[tid + o]; __syncthreads(); }
    float inv = rsqrtf(red[0] * (1.f / 1024.f) + 1e-5f);
    #pragma unroll
    for (int i = 0; i < 4; i++) {
        int idx = tid + i * 256;
        float out = (v[i] - mean) * inv * g[idx] + beta[idx];
        t[idx] = out;
        g_tgt_s[row * DD + idx] = __float2half_rn(out);
    }
}

// ---------------- head + loss ----------------
__global__ void loss_kernel(const float* __restrict__ W_ham, const float* __restrict__ b_ham,
                            const float* __restrict__ y, const float* __restrict__ w,
                            float* __restrict__ out)
{
    __shared__ float red[256];
    int tid = threadIdx.x;
    float acc = 0.f;
    for (int idx = tid; idx < BB * 144; idx += 256) {
        int b = idx / 144;
        int j = idx % 144;
        const float* row = g_tgt + ((size_t)b * SS + (SS - 1)) * DD;
        const float* wr = W_ham + (size_t)j * DD;
        float dot = b_ham[j];
        for (int k = 0; k < DD; k++) dot = fmaf(row[k], wr[k], dot);
        float yr = y[b * 144 + j] - w[(size_t)b * 2304 + 2160 + j];
        float d = dot - yr;
        acc += d * d;
    }
    red[tid] = acc; __syncthreads();
    #pragma unroll
    for (int o = 128; o > 0; o >>= 1) { if (tid < o) red[tid] += red[tid + o]; __syncthreads(); }
    if (tid == 0) out[0] = red[0] / (float)(BB * 144);
}

// ---------------- launch ----------------
extern "C" void kernel_launch(void* const* d_in, const int* in_sizes, int n_in,
                              void* d_out, int out_size)
{
    const float* x      = (const float*)d_in[0];
    const float* w      = (const float*)d_in[1];
    const float* y      = (const float*)d_in[2];
    const float* W_nail = (const float*)d_in[3];
    const float* b_nail = (const float*)d_in[4];
    const float* W_cond = (const float*)d_in[5];
    const float* b_cond = (const float*)d_in[6];
    const float* Wqkv   = (const float*)d_in[7];
    const float* bqkv   = (const float*)d_in[8];
    const float* Wo     = (const float*)d_in[9];
    const float* bo     = (const float*)d_in[10];
    const float* ln1_g  = (const float*)d_in[11];
    const float* ln1_b  = (const float*)d_in[12];
    const float* ln2_g  = (const float*)d_in[13];
    const float* ln2_b  = (const float*)d_in[14];
    const float* W1     = (const float*)d_in[15];
    const float* b1     = (const float*)d_in[16];
    const float* W2     = (const float*)d_in[17];
    const float* b2     = (const float*)d_in[18];
    const float* W_ham  = (const float*)d_in[19];
    const float* b_ham  = (const float*)d_in[20];

    float* p_tgt;
    __half *p_tgt_s, *p_qkv, *p_attno, *p_hid, *p_tmp_h;
    __half *p_wqkv, *p_wo, *p_w1, *p_w2;
    cudaGetSymbolAddress((void**)&p_tgt,   g_tgt);
    cudaGetSymbolAddress((void**)&p_tgt_s, g_tgt_s);
    cudaGetSymbolAddress((void**)&p_qkv,   g_qkv);
    cudaGetSymbolAddress((void**)&p_attno, g_attno);
    cudaGetSymbolAddress((void**)&p_hid,   g_hid);
    cudaGetSymbolAddress((void**)&p_tmp_h, g_tmp_h);
    cudaGetSymbolAddress((void**)&p_wqkv,  g_wqkv);
    cudaGetSymbolAddress((void**)&p_wo,    g_wo);
    cudaGetSymbolAddress((void**)&p_w1,    g_w1);
    cudaGetSymbolAddress((void**)&p_w2,    g_w2);

    static const int SMG = 32768 * 3;              // 98304
    static const int SMF = 16384 + 3 * 16384;      // 65536
    cudaFuncSetAttribute(mma_gemm<0, 0>, cudaFuncAttributeMaxDynamicSharedMemorySize, SMG);
    cudaFuncSetAttribute(mma_gemm<0, 1>, cudaFuncAttributeMaxDynamicSharedMemorySize, SMG);
    cudaFuncSetAttribute(mma_gemm<1, 0>, cudaFuncAttributeMaxDynamicSharedMemorySize, SMG);
    cudaFuncSetAttribute(flash_kernel,   cudaFuncAttributeMaxDynamicSharedMemorySize, SMF);

    const int M = BB * SS;   // 7168
    dim3 blk(256);

    // weight conversions
    {
        long n;
        n = (long)NLAYER * 3 * DD * DD / 4;
        cvt_kernel<<<(unsigned)((n + 255) / 256), blk>>>(Wqkv, p_wqkv, n);
        n = (long)NLAYER * DD * DD / 4;
        cvt_kernel<<<(unsigned)((n + 255) / 256), blk>>>(Wo, p_wo, n);
        n = (long)NLAYER * FFD * DD / 4;
        cvt_kernel<<<(unsigned)((n + 255) / 256), blk>>>(W1, p_w1, n);
        n = (long)NLAYER * DD * FFD / 4;
        cvt_kernel<<<(unsigned)((n + 255) / 256), blk>>>(W2, p_w2, n);
    }

    embed_x_kernel<<<BB * LX, blk>>>(x, W_nail, b_nail);
    embed_w_kernel<<<BB * NWTOK, blk>>>(w, W_cond, b_cond);

    for (int l = 0; l < NLAYER; l++) {
        const __half* wqkv_l = p_wqkv + (size_t)l * 3 * DD * DD;
        const __half* wo_l   = p_wo + (size_t)l * DD * DD;
        const __half* w1_l   = p_w1 + (size_t)l * FFD * DD;
        const __half* w2_l   = p_w2 + (size_t)l * DD * FFD;

        // QKV -> fp16 (Q columns pre-scaled by 0.125*log2e)
        mma_gemm<0, 1><<<dim3(M / 128, 3 * DD / 128), blk, SMG>>>(
            p_tgt_s, wqkv_l, bqkv + (size_t)l * 3 * DD,
            p_qkv, DD, DD, DD, 3 * DD);

        // flash attention -> attno (fp16, token-major)
        flash_kernel<<<dim3(SS / 128, BB * NH), blk, SMF>>>();

        // tmp = attno @ Wo^T + bo  -> fp16
        mma_gemm<0, 0><<<dim3(M / 128, DD / 128), blk, SMG>>>(
            p_attno, wo_l, bo + (size_t)l * DD,
            p_tmp_h, DD, DD, DD, DD);

        resid_ln_kernel<<<M, blk>>>(p_tmp_h, ln1_g + (size_t)l * DD, ln1_b + (size_t)l * DD);

        // hid = gelu(tgt @ W1^T + b1) -> fp16
        mma_gemm<1, 0><<<dim3(M / 128, FFD / 128), blk, SMG>>>(
            p_tgt_s, w1_l, b1 + (size_t)l * FFD,
            p_hid, DD, DD, DD, FFD);

        // tmp = hid @ W2^T + b2 -> fp16
        mma_gemm<0, 0><<<dim3(M / 128, DD / 128), blk, SMG>>>(
            p_hid, w2_l, b2 + (size_t)l * DD,
            p_tmp_h, FFD, FFD, FFD, DD);

        resid_ln_kernel<<<M, blk>>>(p_tmp_h, ln2_g + (size_t)l * DD, ln2_b + (size_t)l * DD);
    }

    loss_kernel<<<1, blk>>>(W_ham, b_ham, y, w, (float*)d_out);
}

// round 9
// speedup vs baseline: 10.7513x; 1.0010x over previous
#include <cuda_runtime.h>
#include <cuda_fp16.h>
#include <math.h>
#include <stdint.h>

// Problem dims (fixed by setup_inputs)
#define BB 8
#define LX 512
#define NWTOK 384
#define SS 896
#define DD 1024
#define NH 16
#define HD 64
#define FFD 4096
#define NLAYER 4

// ---------------- scratch (device globals) ----------------
__device__ float g_tgt[BB * SS * DD];
__device__ __half g_tgt_s[BB * SS * DD];
__device__ __half g_qkv[(size_t)BB * SS * 3 * DD];
__device__ __half g_attno[(size_t)BB * SS * DD];
__device__ __half g_hid[(size_t)BB * SS * FFD];
__device__ __half g_tmp_h[BB * SS * DD];
__device__ int   g_xmask[BB * LX];
// weights fp16
__device__ __half g_wqkv[(size_t)NLAYER * 3 * DD * DD];
__device__ __half g_wo[(size_t)NLAYER * DD * DD];
__device__ __half g_w1[(size_t)NLAYER * FFD * DD];
__device__ __half g_w2[(size_t)NLAYER * DD * FFD];

// scores arrive pre-multiplied by 0.125*log2(e); softmax works in log2 domain
#define QSCALE 0.18033688011112042f

// ---------------- helpers ----------------
__device__ __forceinline__ uint32_t smem_u32(const void* p) {
    uint32_t a;
    asm("{ .reg .u64 t; cvta.to.shared.u64 t, %1; cvt.u32.u64 %0, t; }" : "=r"(a) : "l"(p));
    return a;
}
__device__ __forceinline__ uint32_t swz(uint32_t base, int row, int byteoff) {
    return base + row * 128 + (((byteoff >> 4) ^ (row & 7)) << 4);
}
__device__ __forceinline__ void cp_async16(uint32_t saddr, const void* gaddr) {
    asm volatile("cp.async.cg.shared.global [%0], [%1], 16;" :: "r"(saddr), "l"(gaddr));
}
__device__ __forceinline__ void cp_commit() {
    asm volatile("cp.async.commit_group;" ::: "memory");
}
template<int N>
__device__ __forceinline__ void cp_wait() {
    asm volatile("cp.async.wait_group %0;" :: "n"(N) : "memory");
}
__device__ __forceinline__ void ldsm_x4(uint32_t (&r)[4], uint32_t addr) {
    asm volatile("ldmatrix.sync.aligned.m8n8.x4.shared.b16 {%0,%1,%2,%3}, [%4];"
        : "=r"(r[0]), "=r"(r[1]), "=r"(r[2]), "=r"(r[3]) : "r"(addr));
}
__device__ __forceinline__ void ldsm_x4_trans(uint32_t (&r)[4], uint32_t addr) {
    asm volatile("ldmatrix.sync.aligned.m8n8.x4.trans.shared.b16 {%0,%1,%2,%3}, [%4];"
        : "=r"(r[0]), "=r"(r[1]), "=r"(r[2]), "=r"(r[3]) : "r"(addr));
}
__device__ __forceinline__ void mma16816(float (&d)[4], const uint32_t (&a)[4],
                                         uint32_t b0, uint32_t b1) {
    asm volatile("mma.sync.aligned.m16n8k16.row.col.f32.f16.f16.f32 "
        "{%0,%1,%2,%3}, {%4,%5,%6,%7}, {%8,%9}, {%0,%1,%2,%3};"
        : "+f"(d[0]), "+f"(d[1]), "+f"(d[2]), "+f"(d[3])
        : "r"(a[0]), "r"(a[1]), "r"(a[2]), "r"(a[3]), "r"(b0), "r"(b1));
}
__device__ __forceinline__ float gelu_exact(float x) {
    return 0.5f * x * (1.0f + erff(x * 0.70710678118654752f));
}
__device__ __forceinline__ uint32_t pack_h2(float f0, float f1) {
    __half2 h = __floats2half2_rn(f0, f1);
    return *(uint32_t*)&h;
}
__device__ __forceinline__ uint32_t ex2_h2(uint32_t t) {
    uint32_t r;
    asm("ex2.approx.f16x2 %0, %1;" : "=r"(r) : "r"(t));
    return r;
}
__device__ __forceinline__ float ex2f(float x) {
    float r;
    asm("ex2.approx.f32 %0, %1;" : "=f"(r) : "f"(x));
    return r;
}

// =====================================================================
// Dense fp16 GEMM: C = act(A @ B^T + bias) [optionally scale cols<1024 by QSCALE]
// A (M,K) half row-major; B (N,K) half row-major. BM=128, BN=128, BK=64.
// XOR-swizzled smem, 3-stage cp.async pipeline. Output: half C.
// =====================================================================
template<int ACT, int SCALEQ>
__global__ void __launch_bounds__(256, 2)
mma_gemm(const __half* __restrict__ A, const __half* __restrict__ B,
         const float* __restrict__ bias, __half* __restrict__ Ch,
         int K, int lda, int ldb, int ldc)
{
    extern __shared__ __align__(16) char sm[];
    constexpr int B_OFF = 128 * 128;
    constexpr int STAGE = 2 * B_OFF;

    const int tid = threadIdx.x;
    const int wid = tid >> 5, lane = tid & 31;
    const int warp_m = wid >> 1, warp_n = wid & 1;
    const int m0 = blockIdx.x * 128;
    const int n0 = blockIdx.y * 128;
    const uint32_t smem_base = smem_u32(sm);
    const int nch = K >> 6;

    float acc[2][8][4];
    #pragma unroll
    for (int a = 0; a < 2; a++)
        #pragma unroll
        for (int b = 0; b < 8; b++)
            #pragma unroll
            for (int c = 0; c < 4; c++) acc[a][b][c] = 0.f;

    auto load_stage = [&](int stage, int ch) {
        const int k0 = ch << 6;
        const uint32_t sbase = smem_base + stage * STAGE;
        #pragma unroll
        for (int i = tid; i < 1024; i += 256) {
            int row = i >> 3, seg = i & 7;
            cp_async16(sbase + row * 128 + ((seg ^ (row & 7)) << 4),
                       A + (long)(m0 + row) * lda + k0 + seg * 8);
        }
        #pragma unroll
        for (int i = tid; i < 1024; i += 256) {
            int row = i >> 3, seg = i & 7;
            cp_async16(sbase + B_OFF + row * 128 + ((seg ^ (row & 7)) << 4),
                       B + (long)(n0 + row) * ldb + k0 + seg * 8);
        }
        cp_commit();
    };

    auto compute = [&](int stage) {
        const uint32_t sbase = smem_base + stage * STAGE;
        const int arow = warp_m * 32 + (lane & 15);
        const int bn   = (lane & 7) + (lane >> 4) * 8;
        const int bka  = ((lane >> 3) & 1) * 8;
        #pragma unroll
        for (int kk = 0; kk < 4; kk++) {
            const int acol = kk * 16 + (lane >> 4) * 8;
            uint32_t af[2][4];
            #pragma unroll
            for (int mt = 0; mt < 2; mt++)
                ldsm_x4(af[mt], swz(sbase, arow + mt * 16, acol * 2));
            const int bk = kk * 16 + bka;
            #pragma unroll
            for (int nt2 = 0; nt2 < 4; nt2++) {
                uint32_t bf[4];
                ldsm_x4(bf, swz(sbase + B_OFF, warp_n * 64 + nt2 * 16 + bn, bk * 2));
                #pragma unroll
                for (int mt = 0; mt < 2; mt++) {
                    #pragma unroll
                    for (int j = 0; j < 2; j++)
                        mma16816(acc[mt][nt2 * 2 + j], af[mt], bf[2 * j], bf[2 * j + 1]);
                }
            }
        }
    };

    load_stage(0, 0);
    load_stage(1, 1);
    for (int ch = 0; ch < nch; ch++) {
        if (ch + 1 < nch) cp_wait<1>(); else cp_wait<0>();
        __syncthreads();
        if (ch + 2 < nch) load_stage((ch + 2) % 3, ch + 2);
        compute(ch % 3);
    }

    const int r0 = lane >> 2, c0 = (lane & 3) * 2;
    #pragma unroll
    for (int mt = 0; mt < 2; mt++) {
        #pragma unroll
        for (int nt = 0; nt < 8; nt++) {
            const int n = n0 + warp_n * 64 + nt * 8 + c0;
            float bv0 = bias ? bias[n] : 0.f;
            float bv1 = bias ? bias[n + 1] : 0.f;
            #pragma unroll
            for (int hrow = 0; hrow < 2; hrow++) {
                const int m = m0 + warp_m * 32 + mt * 16 + r0 + hrow * 8;
                float f0 = acc[mt][nt][hrow * 2 + 0] + bv0;
                float f1 = acc[mt][nt][hrow * 2 + 1] + bv1;
                if (ACT == 1) { f0 = gelu_exact(f0); f1 = gelu_exact(f1); }
                if (SCALEQ && n < DD) { f0 *= QSCALE; f1 *= QSCALE; }
                *(uint32_t*)(Ch + (long)m * ldc + n) = pack_h2(f0, f1);
            }
        }
    }
}

// =====================================================================
// Flash attention (fp16): per CTA = (q-tile 128, one (b,h)). 8 warps x 16 rows.
// Q pre-scaled by 0.125*log2e -> softmax in log2 domain with ex2.approx.f16x2.
// 64-key chunks, 3-stage pipeline, swizzled smem, V row-major + ldmatrix.trans.
// =====================================================================
__global__ void __launch_bounds__(256, 2)
flash_kernel()
{
    extern __shared__ __align__(16) char fsm[];
    __shared__ uint32_t maskbits[16];
    constexpr int KV_OFF = 128 * 128;
    constexpr int TILE = 64 * 128;
    constexpr int KSTAGE = 2 * TILE;

    const int bh = blockIdx.y;
    const int b = bh >> 4, h = bh & 15;
    const int q0 = (gridDim.x - 1 - blockIdx.x) * 128;   // long CTAs first
    const int tid = threadIdx.x;
    const int wid = tid >> 5, lane = tid & 31;
    const uint32_t smem = smem_u32(fsm);

    if (tid < 16) {
        uint32_t m = 0;
        const int* xm = g_xmask + b * LX + tid * 32;
        #pragma unroll
        for (int i = 0; i < 32; i++) m |= (xm[i] ? 1u : 0u) << i;
        maskbits[tid] = m;
    }

    // load Q
    #pragma unroll
    for (int i = tid; i < 1024; i += 256) {
        int row = i >> 3, seg = i & 7;
        cp_async16(smem + row * 128 + ((seg ^ (row & 7)) << 4),
                   g_qkv + ((size_t)(b * SS + q0 + row)) * (3 * DD) + h * 64 + seg * 8);
    }
    cp_commit();

    const int nch = (q0 < LX) ? 8 : ((q0 + 128) >> 6);

    auto load_kv = [&](int c, int s) {
        const int k0 = c << 6;
        const uint32_t sb = smem + KV_OFF + s * KSTAGE;
        #pragma unroll
        for (int i = tid; i < 512; i += 256) {
            int row = i >> 3, seg = i & 7;
            cp_async16(sb + row * 128 + ((seg ^ (row & 7)) << 4),
                       g_qkv + ((size_t)(b * SS + k0 + row)) * (3 * DD) + DD + h * 64 + seg * 8);
        }
        #pragma unroll
        for (int i = tid; i < 512; i += 256) {
            int row = i >> 3, seg = i & 7;
            cp_async16(sb + TILE + row * 128 + ((seg ^ (row & 7)) << 4),
                       g_qkv + ((size_t)(b * SS + k0 + row)) * (3 * DD) + 2 * DD + h * 64 + seg * 8);
        }
        cp_commit();
    };

    load_kv(0, 0);
    load_kv(1, 1);

    float m_[2] = {-1e30f, -1e30f}, l_[2] = {0.f, 0.f};
    float out[8][4];
    #pragma unroll
    for (int j = 0; j < 8; j++)
        #pragma unroll
        for (int e = 0; e < 4; e++) out[j][e] = 0.f;

    const int r0 = lane >> 2;
    const int qrow0 = q0 + wid * 16 + r0;
    const int arow = wid * 16 + (lane & 15);
    const int bn   = (lane & 7) + (lane >> 4) * 8;
    const int bka  = ((lane >> 3) & 1) * 8;
    const int trow = (lane & 7) + ((lane >> 3) & 1) * 8;
    const int tcol = (lane >> 4) * 8;

    for (int c = 0; c < nch; c++) {
        if (c + 1 < nch) cp_wait<1>(); else cp_wait<0>();
        __syncthreads();
        if (c + 2 < nch) load_kv(c + 2, (c + 2) % 3);
        const uint32_t sb = smem + KV_OFF + (c % 3) * KSTAGE;

        // ---- QK (scores already in log2 units via Q pre-scale) ----
        float s[8][4];
        #pragma unroll
        for (int j = 0; j < 8; j++)
            #pragma unroll
            for (int e = 0; e < 4; e++) s[j][e] = 0.f;
        #pragma unroll
        for (int t = 0; t < 4; t++) {
            const int acol = t * 16 + (lane >> 4) * 8;
            uint32_t qf[4];
            ldsm_x4(qf, swz(smem, arow, acol * 2));
            const int bk = t * 16 + bka;
            #pragma unroll
            for (int j = 0; j < 4; j++) {
                uint32_t kf[4];
                ldsm_x4(kf, swz(sb, j * 16 + bn, bk * 2));
                mma16816(s[2 * j], qf, kf[0], kf[1]);
                mma16816(s[2 * j + 1], qf, kf[2], kf[3]);
            }
        }

        // ---- mask (fast paths): build vmask + per-row max ----
        const int k0 = c << 6;
        uint32_t vmask;
        float cmax[2] = {-1e30f, -1e30f};
        if (k0 + 64 <= LX) {
            vmask = 0;
            #pragma unroll
            for (int j = 0; j < 8; j++) {
                #pragma unroll
                for (int e = 0; e < 4; e++) {
                    int col = k0 + j * 8 + (lane & 3) * 2 + (e & 1);
                    if (!((maskbits[col >> 5] >> (col & 31)) & 1)) {
                        vmask |= 1u << (j * 4 + e);
                        cmax[e >> 1] = fmaxf(cmax[e >> 1], s[j][e]);
                    }
                }
            }
        } else if (k0 + 64 <= q0 + wid * 16) {
            vmask = 0xffffffffu;
            #pragma unroll
            for (int j = 0; j < 8; j++) {
                #pragma unroll
                for (int e = 0; e < 4; e++)
                    cmax[e >> 1] = fmaxf(cmax[e >> 1], s[j][e]);
            }
        } else {
            vmask = 0;
            #pragma unroll
            for (int j = 0; j < 8; j++) {
                #pragma unroll
                for (int e = 0; e < 4; e++) {
                    int col = k0 + j * 8 + (lane & 3) * 2 + (e & 1);
                    int row = (e < 2) ? qrow0 : (qrow0 + 8);
                    if (col <= row) {
                        vmask |= 1u << (j * 4 + e);
                        cmax[e >> 1] = fmaxf(cmax[e >> 1], s[j][e]);
                    }
                }
            }
        }
        #pragma unroll
        for (int o = 1; o <= 2; o <<= 1) {
            cmax[0] = fmaxf(cmax[0], __shfl_xor_sync(0xffffffffu, cmax[0], o));
            cmax[1] = fmaxf(cmax[1], __shfl_xor_sync(0xffffffffu, cmax[1], o));
        }
        float mn0 = fmaxf(m_[0], cmax[0]);
        float mn1 = fmaxf(m_[1], cmax[1]);
        float f0 = ex2f(m_[0] - mn0);
        float f1 = ex2f(m_[1] - mn1);

        // ---- probabilities via ex2.f16x2; results ARE the PV fragments ----
        uint32_t ph01[8], ph23[8];
        __half2 a01 = __floats2half2_rn(0.f, 0.f);
        __half2 a23 = a01;
        #pragma unroll
        for (int j = 0; j < 8; j++) {
            float t0 = ((vmask >> (j * 4 + 0)) & 1) ? (s[j][0] - mn0) : -100.f;
            float t1 = ((vmask >> (j * 4 + 1)) & 1) ? (s[j][1] - mn0) : -100.f;
            float t2 = ((vmask >> (j * 4 + 2)) & 1) ? (s[j][2] - mn1) : -100.f;
            float t3 = ((vmask >> (j * 4 + 3)) & 1) ? (s[j][3] - mn1) : -100.f;
            ph01[j] = ex2_h2(pack_h2(t0, t1));
            ph23[j] = ex2_h2(pack_h2(t2, t3));
            a01 = __hadd2(a01, *(__half2*)&ph01[j]);
            a23 = __hadd2(a23, *(__half2*)&ph23[j]);
        }
        float2 s01 = __half22float2(a01);
        float2 s23 = __half22float2(a23);
        float rs0 = s01.x + s01.y;
        float rs1 = s23.x + s23.y;
        #pragma unroll
        for (int o = 1; o <= 2; o <<= 1) {
            rs0 += __shfl_xor_sync(0xffffffffu, rs0, o);
            rs1 += __shfl_xor_sync(0xffffffffu, rs1, o);
        }
        l_[0] = l_[0] * f0 + rs0;
        l_[1] = l_[1] * f1 + rs1;
        m_[0] = mn0; m_[1] = mn1;
        if (f0 != 1.f) {
            #pragma unroll
            for (int j = 0; j < 8; j++) { out[j][0] *= f0; out[j][1] *= f0; }
        }
        if (f1 != 1.f) {
            #pragma unroll
            for (int j = 0; j < 8; j++) { out[j][2] *= f1; out[j][3] *= f1; }
        }

        // ---- PV ----
        #pragma unroll
        for (int t = 0; t < 4; t++) {
            uint32_t pf[4] = { ph01[2 * t], ph23[2 * t], ph01[2 * t + 1], ph23[2 * t + 1] };
            #pragma unroll
            for (int j = 0; j < 4; j++) {
                uint32_t vf[4];
                ldsm_x4_trans(vf, swz(sb + TILE, t * 16 + trow, (j * 16 + tcol) * 2));
                mma16816(out[2 * j], pf, vf[0], vf[1]);
                mma16816(out[2 * j + 1], pf, vf[2], vf[3]);
            }
        }
    }

    // ---- epilogue ----
    float inv0 = 1.f / l_[0];
    float inv1 = 1.f / l_[1];
    #pragma unroll
    for (int j = 0; j < 8; j++) {
        const int d = h * 64 + j * 8 + (lane & 3) * 2;
        *(uint32_t*)(g_attno + ((size_t)(b * SS + qrow0)) * DD + d) =
            pack_h2(out[j][0] * inv0, out[j][1] * inv0);
        *(uint32_t*)(g_attno + ((size_t)(b * SS + qrow0 + 8)) * DD + d) =
            pack_h2(out[j][2] * inv1, out[j][3] * inv1);
    }
}

// ---------------- fp32 -> fp16 ----------------
__global__ void cvt_kernel(const float* __restrict__ src,
                           __half* __restrict__ h, long n4)
{
    long i = (long)blockIdx.x * blockDim.x + threadIdx.x;
    if (i >= n4) return;
    float4 v = *(const float4*)(src + i * 4);
    uint2 hv;
    hv.x = pack_h2(v.x, v.y);
    hv.y = pack_h2(v.z, v.w);
    *(uint2*)(h + i * 4) = hv;
}

// ---------------- embedding: x tokens ----------------
__global__ void embed_x_kernel(const float* __restrict__ x,
                               const float* __restrict__ W_nail,
                               const float* __restrict__ b_nail)
{
    const float RSC = 0.99995000374968753f;
    int row = blockIdx.x;
    int b = row / LX;
    const float* xr = x + (long)row * 64;
    __shared__ float xn[63];
    __shared__ float t_sh;
    int tid = threadIdx.x;
    if (tid == 0) {
        float t0 = xr[0];
        g_xmask[row] = isnan(t0) ? 1 : 0;
        t_sh = isnan(t0) ? 0.f : t0;
    }
    if (tid < 63) {
        float v = xr[tid + 1];
        if (isnan(v)) v = 0.f;
        v *= RSC;
        xn[tid] = fminf(fmaxf(v, -5.f), 5.f);
    }
    __syncthreads();
    float t = t_sh;
    const float kfac = -logf(1000.f) / 1024.f;
    for (int d = tid; d < DD; d += 256) {
        const float* wr = W_nail + d * 63;
        float acc = b_nail[d];
        #pragma unroll 7
        for (int c = 0; c < 63; c++) acc = fmaf(xn[c], wr[c], acc);
        int i = d >> 1;
        float ang = t * expf((float)i * kfac);
        acc += (d & 1) ? cosf(ang) : sinf(ang);
        size_t idx = ((size_t)b * SS + (row % LX)) * DD + d;
        g_tgt[idx] = acc;
        g_tgt_s[idx] = __float2half_rn(acc);
    }
}

// ---------------- embedding: w tokens + global PE ----------------
__global__ void embed_w_kernel(const float* __restrict__ w,
                               const float* __restrict__ W_cond,
                               const float* __restrict__ b_cond)
{
    const float RSC = 0.99995000374968753f;
    int row = blockIdx.x;
    int b = row / NWTOK, r = row % NWTOK;
    const float* wr6 = w + (long)b * (NWTOK * 6) + r * 6;
    __shared__ float wn[6];
    int tid = threadIdx.x;
    if (tid < 6) {
        float v = wr6[tid];
        if (isnan(v)) v = 0.f;
        v *= RSC;
        wn[tid] = fminf(fmaxf(v, -5.f), 5.f);
    }
    __syncthreads();
    int spos = LX + r;
    const float kfac = -logf(1000.f) / 1024.f;
    for (int d = tid; d < DD; d += 256) {
        const float* wc = W_cond + d * 6;
        float acc = b_cond[d];
        #pragma unroll
        for (int c = 0; c < 6; c++) acc = fmaf(wn[c], wc[c], acc);
        int i = d >> 1;
        float ang = (float)spos * expf((float)i * kfac);
        acc += (d & 1) ? cosf(ang) : sinf(ang);
        size_t idx = ((size_t)b * SS + spos) * DD + d;
        g_tgt[idx] = acc;
        g_tgt_s[idx] = __float2half_rn(acc);
    }
}

// ---------------- residual add + LayerNorm (in-place, half delta, emits fp16) ----------------
__global__ void resid_ln_kernel(const __half* __restrict__ delta,
                                const float* __restrict__ g,
                                const float* __restrict__ beta)
{
    size_t row = blockIdx.x;
    float* t = g_tgt + row * DD;
    const __half* dl = delta + row * DD;
    int tid = threadIdx.x;
    float v[4];
    float s = 0.f;
    #pragma unroll
    for (int i = 0; i < 4; i++) {
        int idx = tid + i * 256;
        v[i] = t[idx] + __half2float(dl[idx]);
        s += v[i];
    }
    __shared__ float red[256];
    red[tid] = s; __syncthreads();
    #pragma unroll
    for (int o = 128; o > 0; o >>= 1) { if (tid < o) red[tid] += red[tid + o]; __syncthreads(); }
    float mean = red[0] * (1.f / 1024.f);
    __syncthreads();
    float s2 = 0.f;
    #pragma unroll
    for (int i = 0; i < 4; i++) { float d = v[i] - mean; s2 += d * d; }
    red[tid] = s2; __syncthreads();
    #pragma unroll
    for (int o = 128; o > 0; o >>= 1) { if (tid < o) red[tid] += red[tid + o]; __syncthreads(); }
    float inv = rsqrtf(red[0] * (1.f / 1024.f) + 1e-5f);
    #pragma unroll
    for (int i = 0; i < 4; i++) {
        int idx = tid + i * 256;
        float out = (v[i] - mean) * inv * g[idx] + beta[idx];
        t[idx] = out;
        g_tgt_s[row * DD + idx] = __float2half_rn(out);
    }
}

// ---------------- head + loss ----------------
__global__ void loss_kernel(const float* __restrict__ W_ham, const float* __restrict__ b_ham,
                            const float* __restrict__ y, const float* __restrict__ w,
                            float* __restrict__ out)
{
    __shared__ float red[256];
    int tid = threadIdx.x;
    float acc = 0.f;
    for (int idx = tid; idx < BB * 144; idx += 256) {
        int b = idx / 144;
        int j = idx % 144;
        const float* row = g_tgt + ((size_t)b * SS + (SS - 1)) * DD;
        const float* wr = W_ham + (size_t)j * DD;
        float dot = b_ham[j];
        for (int k = 0; k < DD; k++) dot = fmaf(row[k], wr[k], dot);
        float yr = y[b * 144 + j] - w[(size_t)b * 2304 + 2160 + j];
        float d = dot - yr;
        acc += d * d;
    }
    red[tid] = acc; __syncthreads();
    #pragma unroll
    for (int o = 128; o > 0; o >>= 1) { if (tid < o) red[tid] += red[tid + o]; __syncthreads(); }
    if (tid == 0) out[0] = red[0] / (float)(BB * 144);
}

// ---------------- launch ----------------
extern "C" void kernel_launch(void* const* d_in, const int* in_sizes, int n_in,
                              void* d_out, int out_size)
{
    const float* x      = (const float*)d_in[0];
    const float* w      = (const float*)d_in[1];
    const float* y      = (const float*)d_in[2];
    const float* W_nail = (const float*)d_in[3];
    const float* b_nail = (const float*)d_in[4];
    const float* W_cond = (const float*)d_in[5];
    const float* b_cond = (const float*)d_in[6];
    const float* Wqkv   = (const float*)d_in[7];
    const float* bqkv   = (const float*)d_in[8];
    const float* Wo     = (const float*)d_in[9];
    const float* bo     = (const float*)d_in[10];
    const float* ln1_g  = (const float*)d_in[11];
    const float* ln1_b  = (const float*)d_in[12];
    const float* ln2_g  = (const float*)d_in[13];
    const float* ln2_b  = (const float*)d_in[14];
    const float* W1     = (const float*)d_in[15];
    const float* b1     = (const float*)d_in[16];
    const float* W2     = (const float*)d_in[17];
    const float* b2     = (const float*)d_in[18];
    const float* W_ham  = (const float*)d_in[19];
    const float* b_ham  = (const float*)d_in[20];

    float* p_tgt;
    __half *p_tgt_s, *p_qkv, *p_attno, *p_hid, *p_tmp_h;
    __half *p_wqkv, *p_wo, *p_w1, *p_w2;
    cudaGetSymbolAddress((void**)&p_tgt,   g_tgt);
    cudaGetSymbolAddress((void**)&p_tgt_s, g_tgt_s);
    cudaGetSymbolAddress((void**)&p_qkv,   g_qkv);
    cudaGetSymbolAddress((void**)&p_attno, g_attno);
    cudaGetSymbolAddress((void**)&p_hid,   g_hid);
    cudaGetSymbolAddress((void**)&p_tmp_h, g_tmp_h);
    cudaGetSymbolAddress((void**)&p_wqkv,  g_wqkv);
    cudaGetSymbolAddress((void**)&p_wo,    g_wo);
    cudaGetSymbolAddress((void**)&p_w1,    g_w1);
    cudaGetSymbolAddress((void**)&p_w2,    g_w2);

    static const int SMG = 32768 * 3;              // 98304
    static const int SMF = 16384 + 3 * 16384;      // 65536
    cudaFuncSetAttribute(mma_gemm<0, 0>, cudaFuncAttributeMaxDynamicSharedMemorySize, SMG);
    cudaFuncSetAttribute(mma_gemm<0, 1>, cudaFuncAttributeMaxDynamicSharedMemorySize, SMG);
    cudaFuncSetAttribute(mma_gemm<1, 0>, cudaFuncAttributeMaxDynamicSharedMemorySize, SMG);
    cudaFuncSetAttribute(flash_kernel,   cudaFuncAttributeMaxDynamicSharedMemorySize, SMF);

    const int M = BB * SS;   // 7168
    dim3 blk(256);

    // weight conversions
    {
        long n;
        n = (long)NLAYER * 3 * DD * DD / 4;
        cvt_kernel<<<(unsigned)((n + 255) / 256), blk>>>(Wqkv, p_wqkv, n);
        n = (long)NLAYER * DD * DD / 4;
        cvt_kernel<<<(unsigned)((n + 255) / 256), blk>>>(Wo, p_wo, n);
        n = (long)NLAYER * FFD * DD / 4;
        cvt_kernel<<<(unsigned)((n + 255) / 256), blk>>>(W1, p_w1, n);
        n = (long)NLAYER * DD * FFD / 4;
        cvt_kernel<<<(unsigned)((n + 255) / 256), blk>>>(W2, p_w2, n);
    }

    embed_x_kernel<<<BB * LX, blk>>>(x, W_nail, b_nail);
    embed_w_kernel<<<BB * NWTOK, blk>>>(w, W_cond, b_cond);

    for (int l = 0; l < NLAYER; l++) {
        const __half* wqkv_l = p_wqkv + (size_t)l * 3 * DD * DD;
        const __half* wo_l   = p_wo + (size_t)l * DD * DD;
        const __half* w1_l   = p_w1 + (size_t)l * FFD * DD;
        const __half* w2_l   = p_w2 + (size_t)l * DD * FFD;

        // QKV -> fp16 (Q columns pre-scaled by 0.125*log2e)
        mma_gemm<0, 1><<<dim3(M / 128, 3 * DD / 128), blk, SMG>>>(
            p_tgt_s, wqkv_l, bqkv + (size_t)l * 3 * DD,
            p_qkv, DD, DD, DD, 3 * DD);

        // flash attention -> attno (fp16, token-major)
        flash_kernel<<<dim3(SS / 128, BB * NH), blk, SMF>>>();

        // tmp = attno @ Wo^T + bo  -> fp16
        mma_gemm<0, 0><<<dim3(M / 128, DD / 128), blk, SMG>>>(
            p_attno, wo_l, bo + (size_t)l * DD,
            p_tmp_h, DD, DD, DD, DD);

        resid_ln_kernel<<<M, blk>>>(p_tmp_h, ln1_g + (size_t)l * DD, ln1_b + (size_t)l * DD);

        // hid = gelu(tgt @ W1^T + b1) -> fp16
        mma_gemm<1, 0><<<dim3(M / 128, FFD / 128), blk, SMG>>>(
            p_tgt_s, w1_l, b1 + (size_t)l * FFD,
            p_hid, DD, DD, DD, FFD);

        // tmp = hid @ W2^T + b2 -> fp16
        mma_gemm<0, 0><<<dim3(M / 128, DD / 128), blk, SMG>>>(
            p_hid, w2_l, b2 + (size_t)l * DD,
            p_tmp_h, FFD, FFD, FFD, DD);

        resid_ln_kernel<<<M, blk>>>(p_tmp_h, ln2_g + (size_t)l * DD, ln2_b + (size_t)l * DD);
    }

    loss_kernel<<<1, blk>>>(W_ham, b_ham, y, w, (float*)d_out);
}

// round 10
// speedup vs baseline: 12.2547x; 1.1398x over previous
#include <cuda_runtime.h>
#include <cuda_fp16.h>
#include <math.h>
#include <stdint.h>

// Problem dims (fixed by setup_inputs)
#define BB 8
#define LX 512
#define NWTOK 384
#define SS 896
#define DD 1024
#define NH 16
#define HD 64
#define FFD 4096
#define NLAYER 4

// ---------------- scratch (device globals) ----------------
__device__ float g_tgt[BB * SS * DD];
__device__ __half g_tgt_s[BB * SS * DD];
__device__ __half g_qkv[(size_t)BB * SS * 3 * DD];
__device__ __half g_attno[(size_t)BB * SS * DD];
__device__ __half g_hid[(size_t)BB * SS * FFD];
__device__ __half g_tmp_h[BB * SS * DD];
__device__ int   g_xmask[BB * LX];
// weights fp16
__device__ __half g_wqkv[(size_t)NLAYER * 3 * DD * DD];
__device__ __half g_wo[(size_t)NLAYER * DD * DD];
__device__ __half g_w1[(size_t)NLAYER * FFD * DD];
__device__ __half g_w2[(size_t)NLAYER * DD * FFD];
// compact last-layer buffers (fp32, 8 rows)
__device__ float g_c_attn[BB * DD];
__device__ float g_c_t2[BB * DD];
__device__ float g_c_x[BB * DD];
__device__ float g_c_hid[BB * FFD];

// scores arrive pre-multiplied by 0.125*log2(e); softmax works in log2 domain
#define QSCALE 0.18033688011112042f

// ---------------- helpers ----------------
__device__ __forceinline__ uint32_t smem_u32(const void* p) {
    uint32_t a;
    asm("{ .reg .u64 t; cvta.to.shared.u64 t, %1; cvt.u32.u64 %0, t; }" : "=r"(a) : "l"(p));
    return a;
}
__device__ __forceinline__ uint32_t swz(uint32_t base, int row, int byteoff) {
    return base + row * 128 + (((byteoff >> 4) ^ (row & 7)) << 4);
}
__device__ __forceinline__ void cp_async16(uint32_t saddr, const void* gaddr) {
    asm volatile("cp.async.cg.shared.global [%0], [%1], 16;" :: "r"(saddr), "l"(gaddr));
}
__device__ __forceinline__ void cp_commit() {
    asm volatile("cp.async.commit_group;" ::: "memory");
}
template<int N>
__device__ __forceinline__ void cp_wait() {
    asm volatile("cp.async.wait_group %0;" :: "n"(N) : "memory");
}
__device__ __forceinline__ void ldsm_x4(uint32_t (&r)[4], uint32_t addr) {
    asm volatile("ldmatrix.sync.aligned.m8n8.x4.shared.b16 {%0,%1,%2,%3}, [%4];"
        : "=r"(r[0]), "=r"(r[1]), "=r"(r[2]), "=r"(r[3]) : "r"(addr));
}
__device__ __forceinline__ void ldsm_x4_trans(uint32_t (&r)[4], uint32_t addr) {
    asm volatile("ldmatrix.sync.aligned.m8n8.x4.trans.shared.b16 {%0,%1,%2,%3}, [%4];"
        : "=r"(r[0]), "=r"(r[1]), "=r"(r[2]), "=r"(r[3]) : "r"(addr));
}
__device__ __forceinline__ void mma16816(float (&d)[4], const uint32_t (&a)[4],
                                         uint32_t b0, uint32_t b1) {
    asm volatile("mma.sync.aligned.m16n8k16.row.col.f32.f16.f16.f32 "
        "{%0,%1,%2,%3}, {%4,%5,%6,%7}, {%8,%9}, {%0,%1,%2,%3};"
        : "+f"(d[0]), "+f"(d[1]), "+f"(d[2]), "+f"(d[3])
        : "r"(a[0]), "r"(a[1]), "r"(a[2]), "r"(a[3]), "r"(b0), "r"(b1));
}
__device__ __forceinline__ float gelu_exact(float x) {
    return 0.5f * x * (1.0f + erff(x * 0.70710678118654752f));
}
__device__ __forceinline__ uint32_t pack_h2(float f0, float f1) {
    __half2 h = __floats2half2_rn(f0, f1);
    return *(uint32_t*)&h;
}
__device__ __forceinline__ uint32_t ex2_h2(uint32_t t) {
    uint32_t r;
    asm("ex2.approx.f16x2 %0, %1;" : "=r"(r) : "r"(t));
    return r;
}
__device__ __forceinline__ float ex2f(float x) {
    float r;
    asm("ex2.approx.f32 %0, %1;" : "=f"(r) : "f"(x));
    return r;
}

// =====================================================================
// Dense fp16 GEMM: C = act(A @ B^T + bias) [optionally scale cols<1024 by QSCALE]
// =====================================================================
template<int ACT, int SCALEQ>
__global__ void __launch_bounds__(256, 2)
mma_gemm(const __half* __restrict__ A, const __half* __restrict__ B,
         const float* __restrict__ bias, __half* __restrict__ Ch,
         int K, int lda, int ldb, int ldc)
{
    extern __shared__ __align__(16) char sm[];
    constexpr int B_OFF = 128 * 128;
    constexpr int STAGE = 2 * B_OFF;

    const int tid = threadIdx.x;
    const int wid = tid >> 5, lane = tid & 31;
    const int warp_m = wid >> 1, warp_n = wid & 1;
    const int m0 = blockIdx.x * 128;
    const int n0 = blockIdx.y * 128;
    const uint32_t smem_base = smem_u32(sm);
    const int nch = K >> 6;

    float acc[2][8][4];
    #pragma unroll
    for (int a = 0; a < 2; a++)
        #pragma unroll
        for (int b = 0; b < 8; b++)
            #pragma unroll
            for (int c = 0; c < 4; c++) acc[a][b][c] = 0.f;

    auto load_stage = [&](int stage, int ch) {
        const int k0 = ch << 6;
        const uint32_t sbase = smem_base + stage * STAGE;
        #pragma unroll
        for (int i = tid; i < 1024; i += 256) {
            int row = i >> 3, seg = i & 7;
            cp_async16(sbase + row * 128 + ((seg ^ (row & 7)) << 4),
                       A + (long)(m0 + row) * lda + k0 + seg * 8);
        }
        #pragma unroll
        for (int i = tid; i < 1024; i += 256) {
            int row = i >> 3, seg = i & 7;
            cp_async16(sbase + B_OFF + row * 128 + ((seg ^ (row & 7)) << 4),
                       B + (long)(n0 + row) * ldb + k0 + seg * 8);
        }
        cp_commit();
    };

    auto compute = [&](int stage) {
        const uint32_t sbase = smem_base + stage * STAGE;
        const int arow = warp_m * 32 + (lane & 15);
        const int bn   = (lane & 7) + (lane >> 4) * 8;
        const int bka  = ((lane >> 3) & 1) * 8;
        #pragma unroll
        for (int kk = 0; kk < 4; kk++) {
            const int acol = kk * 16 + (lane >> 4) * 8;
            uint32_t af[2][4];
            #pragma unroll
            for (int mt = 0; mt < 2; mt++)
                ldsm_x4(af[mt], swz(sbase, arow + mt * 16, acol * 2));
            const int bk = kk * 16 + bka;
            #pragma unroll
            for (int nt2 = 0; nt2 < 4; nt2++) {
                uint32_t bf[4];
                ldsm_x4(bf, swz(sbase + B_OFF, warp_n * 64 + nt2 * 16 + bn, bk * 2));
                #pragma unroll
                for (int mt = 0; mt < 2; mt++) {
                    #pragma unroll
                    for (int j = 0; j < 2; j++)
                        mma16816(acc[mt][nt2 * 2 + j], af[mt], bf[2 * j], bf[2 * j + 1]);
                }
            }
        }
    };

    load_stage(0, 0);
    load_stage(1, 1);
    for (int ch = 0; ch < nch; ch++) {
        if (ch + 1 < nch) cp_wait<1>(); else cp_wait<0>();
        __syncthreads();
        if (ch + 2 < nch) load_stage((ch + 2) % 3, ch + 2);
        compute(ch % 3);
    }

    const int r0 = lane >> 2, c0 = (lane & 3) * 2;
    #pragma unroll
    for (int mt = 0; mt < 2; mt++) {
        #pragma unroll
        for (int nt = 0; nt < 8; nt++) {
            const int n = n0 + warp_n * 64 + nt * 8 + c0;
            float bv0 = bias ? bias[n] : 0.f;
            float bv1 = bias ? bias[n + 1] : 0.f;
            #pragma unroll
            for (int hrow = 0; hrow < 2; hrow++) {
                const int m = m0 + warp_m * 32 + mt * 16 + r0 + hrow * 8;
                float f0 = acc[mt][nt][hrow * 2 + 0] + bv0;
                float f1 = acc[mt][nt][hrow * 2 + 1] + bv1;
                if (ACT == 1) { f0 = gelu_exact(f0); f1 = gelu_exact(f1); }
                if (SCALEQ && n < DD) { f0 *= QSCALE; f1 *= QSCALE; }
                *(uint32_t*)(Ch + (long)m * ldc + n) = pack_h2(f0, f1);
            }
        }
    }
}

// =====================================================================
// Flash attention (fp16), layers 0..2 (full query set)
// =====================================================================
__global__ void __launch_bounds__(256, 2)
flash_kernel()
{
    extern __shared__ __align__(16) char fsm[];
    __shared__ uint32_t maskbits[16];
    constexpr int KV_OFF = 128 * 128;
    constexpr int TILE = 64 * 128;
    constexpr int KSTAGE = 2 * TILE;

    const int bh = blockIdx.y;
    const int b = bh >> 4, h = bh & 15;
    const int q0 = (gridDim.x - 1 - blockIdx.x) * 128;
    const int tid = threadIdx.x;
    const int wid = tid >> 5, lane = tid & 31;
    const uint32_t smem = smem_u32(fsm);

    if (tid < 16) {
        uint32_t m = 0;
        const int* xm = g_xmask + b * LX + tid * 32;
        #pragma unroll
        for (int i = 0; i < 32; i++) m |= (xm[i] ? 1u : 0u) << i;
        maskbits[tid] = m;
    }

    #pragma unroll
    for (int i = tid; i < 1024; i += 256) {
        int row = i >> 3, seg = i & 7;
        cp_async16(smem + row * 128 + ((seg ^ (row & 7)) << 4),
                   g_qkv + ((size_t)(b * SS + q0 + row)) * (3 * DD) + h * 64 + seg * 8);
    }
    cp_commit();

    const int nch = (q0 < LX) ? 8 : ((q0 + 128) >> 6);

    auto load_kv = [&](int c, int s) {
        const int k0 = c << 6;
        const uint32_t sb = smem + KV_OFF + s * KSTAGE;
        #pragma unroll
        for (int i = tid; i < 512; i += 256) {
            int row = i >> 3, seg = i & 7;
            cp_async16(sb + row * 128 + ((seg ^ (row & 7)) << 4),
                       g_qkv + ((size_t)(b * SS + k0 + row)) * (3 * DD) + DD + h * 64 + seg * 8);
        }
        #pragma unroll
        for (int i = tid; i < 512; i += 256) {
            int row = i >> 3, seg = i & 7;
            cp_async16(sb + TILE + row * 128 + ((seg ^ (row & 7)) << 4),
                       g_qkv + ((size_t)(b * SS + k0 + row)) * (3 * DD) + 2 * DD + h * 64 + seg * 8);
        }
        cp_commit();
    };

    load_kv(0, 0);
    load_kv(1, 1);

    float m_[2] = {-1e30f, -1e30f}, l_[2] = {0.f, 0.f};
    float out[8][4];
    #pragma unroll
    for (int j = 0; j < 8; j++)
        #pragma unroll
        for (int e = 0; e < 4; e++) out[j][e] = 0.f;

    const int r0 = lane >> 2;
    const int qrow0 = q0 + wid * 16 + r0;
    const int arow = wid * 16 + (lane & 15);
    const int bn   = (lane & 7) + (lane >> 4) * 8;
    const int bka  = ((lane >> 3) & 1) * 8;
    const int trow = (lane & 7) + ((lane >> 3) & 1) * 8;
    const int tcol = (lane >> 4) * 8;

    for (int c = 0; c < nch; c++) {
        if (c + 1 < nch) cp_wait<1>(); else cp_wait<0>();
        __syncthreads();
        if (c + 2 < nch) load_kv(c + 2, (c + 2) % 3);
        const uint32_t sb = smem + KV_OFF + (c % 3) * KSTAGE;

        float s[8][4];
        #pragma unroll
        for (int j = 0; j < 8; j++)
            #pragma unroll
            for (int e = 0; e < 4; e++) s[j][e] = 0.f;
        #pragma unroll
        for (int t = 0; t < 4; t++) {
            const int acol = t * 16 + (lane >> 4) * 8;
            uint32_t qf[4];
            ldsm_x4(qf, swz(smem, arow, acol * 2));
            const int bk = t * 16 + bka;
            #pragma unroll
            for (int j = 0; j < 4; j++) {
                uint32_t kf[4];
                ldsm_x4(kf, swz(sb, j * 16 + bn, bk * 2));
                mma16816(s[2 * j], qf, kf[0], kf[1]);
                mma16816(s[2 * j + 1], qf, kf[2], kf[3]);
            }
        }

        const int k0 = c << 6;
        uint32_t vmask;
        float cmax[2] = {-1e30f, -1e30f};
        if (k0 + 64 <= LX) {
            vmask = 0;
            #pragma unroll
            for (int j = 0; j < 8; j++) {
                #pragma unroll
                for (int e = 0; e < 4; e++) {
                    int col = k0 + j * 8 + (lane & 3) * 2 + (e & 1);
                    if (!((maskbits[col >> 5] >> (col & 31)) & 1)) {
                        vmask |= 1u << (j * 4 + e);
                        cmax[e >> 1] = fmaxf(cmax[e >> 1], s[j][e]);
                    }
                }
            }
        } else if (k0 + 64 <= q0 + wid * 16) {
            vmask = 0xffffffffu;
            #pragma unroll
            for (int j = 0; j < 8; j++) {
                #pragma unroll
                for (int e = 0; e < 4; e++)
                    cmax[e >> 1] = fmaxf(cmax[e >> 1], s[j][e]);
            }
        } else {
            vmask = 0;
            #pragma unroll
            for (int j = 0; j < 8; j++) {
                #pragma unroll
                for (int e = 0; e < 4; e++) {
                    int col = k0 + j * 8 + (lane & 3) * 2 + (e & 1);
                    int row = (e < 2) ? qrow0 : (qrow0 + 8);
                    if (col <= row) {
                        vmask |= 1u << (j * 4 + e);
                        cmax[e >> 1] = fmaxf(cmax[e >> 1], s[j][e]);
                    }
                }
            }
        }
        #pragma unroll
        for (int o = 1; o <= 2; o <<= 1) {
            cmax[0] = fmaxf(cmax[0], __shfl_xor_sync(0xffffffffu, cmax[0], o));
            cmax[1] = fmaxf(cmax[1], __shfl_xor_sync(0xffffffffu, cmax[1], o));
        }
        float mn0 = fmaxf(m_[0], cmax[0]);
        float mn1 = fmaxf(m_[1], cmax[1]);
        float f0 = ex2f(m_[0] - mn0);
        float f1 = ex2f(m_[1] - mn1);

        uint32_t ph01[8], ph23[8];
        __half2 a01 = __floats2half2_rn(0.f, 0.f);
        __half2 a23 = a01;
        #pragma unroll
        for (int j = 0; j < 8; j++) {
            float t0 = ((vmask >> (j * 4 + 0)) & 1) ? (s[j][0] - mn0) : -100.f;
            float t1 = ((vmask >> (j * 4 + 1)) & 1) ? (s[j][1] - mn0) : -100.f;
            float t2 = ((vmask >> (j * 4 + 2)) & 1) ? (s[j][2] - mn1) : -100.f;
            float t3 = ((vmask >> (j * 4 + 3)) & 1) ? (s[j][3] - mn1) : -100.f;
            ph01[j] = ex2_h2(pack_h2(t0, t1));
            ph23[j] = ex2_h2(pack_h2(t2, t3));
            a01 = __hadd2(a01, *(__half2*)&ph01[j]);
            a23 = __hadd2(a23, *(__half2*)&ph23[j]);
        }
        float2 s01 = __half22float2(a01);
        float2 s23 = __half22float2(a23);
        float rs0 = s01.x + s01.y;
        float rs1 = s23.x + s23.y;
        #pragma unroll
        for (int o = 1; o <= 2; o <<= 1) {
            rs0 += __shfl_xor_sync(0xffffffffu, rs0, o);
            rs1 += __shfl_xor_sync(0xffffffffu, rs1, o);
        }
        l_[0] = l_[0] * f0 + rs0;
        l_[1] = l_[1] * f1 + rs1;
        m_[0] = mn0; m_[1] = mn1;
        if (f0 != 1.f) {
            #pragma unroll
            for (int j = 0; j < 8; j++) { out[j][0] *= f0; out[j][1] *= f0; }
        }
        if (f1 != 1.f) {
            #pragma unroll
            for (int j = 0; j < 8; j++) { out[j][2] *= f1; out[j][3] *= f1; }
        }

        #pragma unroll
        for (int t = 0; t < 4; t++) {
            uint32_t pf[4] = { ph01[2 * t], ph23[2 * t], ph01[2 * t + 1], ph23[2 * t + 1] };
            #pragma unroll
            for (int j = 0; j < 4; j++) {
                uint32_t vf[4];
                ldsm_x4_trans(vf, swz(sb + TILE, t * 16 + trow, (j * 16 + tcol) * 2));
                mma16816(out[2 * j], pf, vf[0], vf[1]);
                mma16816(out[2 * j + 1], pf, vf[2], vf[3]);
            }
        }
    }

    float inv0 = 1.f / l_[0];
    float inv1 = 1.f / l_[1];
    #pragma unroll
    for (int j = 0; j < 8; j++) {
        const int d = h * 64 + j * 8 + (lane & 3) * 2;
        *(uint32_t*)(g_attno + ((size_t)(b * SS + qrow0)) * DD + d) =
            pack_h2(out[j][0] * inv0, out[j][1] * inv0);
        *(uint32_t*)(g_attno + ((size_t)(b * SS + qrow0 + 8)) * DD + d) =
            pack_h2(out[j][2] * inv1, out[j][3] * inv1);
    }
}

// =====================================================================
// Last layer: attention for ONLY the final token of each batch.
// grid = BB*NH, block = 256. Q computed on the fly from fp32 weights.
// =====================================================================
__global__ void flash_last_kernel(const float* __restrict__ Wq,
                                  const float* __restrict__ bq)
{
    __shared__ float xrow[DD];
    __shared__ float q[HD];
    __shared__ float probs[SS];
    __shared__ float red[256];
    const int bh = blockIdx.x;
    const int b = bh >> 4, h = bh & 15;
    const int tid = threadIdx.x;

    const float* trow = g_tgt + ((size_t)b * SS + SS - 1) * DD;
    for (int i = tid; i < DD; i += 256) xrow[i] = trow[i];
    __syncthreads();

    // q[d] (4 threads per d)
    {
        int d = tid >> 2, part = tid & 3;
        const float* wr = Wq + (size_t)(h * HD + d) * DD;
        float s = 0.f;
        for (int k = part; k < DD; k += 4) s = fmaf(xrow[k], wr[k], s);
        s += __shfl_xor_sync(0xffffffffu, s, 1);
        s += __shfl_xor_sync(0xffffffffu, s, 2);
        if (part == 0) q[d] = (s + bq[h * HD + d]) * 0.125f;
    }
    __syncthreads();

    // scores over 896 keys (query row = SS-1 >= all keys, so causal always true)
    const int* xm = g_xmask + b * LX;
    float lmax = -1e30f;
    for (int k = tid; k < SS; k += 256) {
        bool valid = (k < LX) ? (xm[k] == 0) : true;
        float s = 0.f;
        const __half* krow = g_qkv + ((size_t)(b * SS + k)) * (3 * DD) + DD + h * 64;
        #pragma unroll 16
        for (int d = 0; d < HD; d++) s = fmaf(q[d], __half2float(krow[d]), s);
        probs[k] = valid ? s : -1e30f;
        if (valid) lmax = fmaxf(lmax, s);
    }
    red[tid] = lmax; __syncthreads();
    for (int o = 128; o > 0; o >>= 1) { if (tid < o) red[tid] = fmaxf(red[tid], red[tid + o]); __syncthreads(); }
    float mx = red[0]; __syncthreads();
    float lsum = 0.f;
    for (int k = tid; k < SS; k += 256) {
        float p = (probs[k] > -1e29f) ? __expf(probs[k] - mx) : 0.f;
        probs[k] = p; lsum += p;
    }
    red[tid] = lsum; __syncthreads();
    for (int o = 128; o > 0; o >>= 1) { if (tid < o) red[tid] += red[tid + o]; __syncthreads(); }
    float inv = 1.f / red[0]; __syncthreads();

    // out[d] = sum_k probs[k]*V[k][d] (4 threads per d)
    {
        int d = tid >> 2, part = tid & 3;
        float s = 0.f;
        for (int k = part; k < SS; k += 4) {
            const __half* vrow = g_qkv + ((size_t)(b * SS + k)) * (3 * DD) + 2 * DD + h * 64;
            s = fmaf(probs[k], __half2float(vrow[d]), s);
        }
        s += __shfl_xor_sync(0xffffffffu, s, 1);
        s += __shfl_xor_sync(0xffffffffu, s, 2);
        if (part == 0) g_c_attn[b * DD + h * HD + d] = s * inv;
    }
}

// ---------------- small GEMM on 8 compact rows: out[8][N] = act(in[8][K] @ W^T + bias) ----------------
template<int ACT>
__global__ void small_gemm(const float* __restrict__ in, const float* __restrict__ W,
                           const float* __restrict__ bias, float* __restrict__ out,
                           int N, int K)
{
    int n = blockIdx.x;
    int wid = threadIdx.x >> 5, lane = threadIdx.x & 31;   // 8 warps = 8 batch rows
    const float* wrow = W + (size_t)n * K;
    const float* irow = in + (size_t)wid * K;
    float s = 0.f;
    for (int k = lane; k < K; k += 32) s = fmaf(irow[k], wrow[k], s);
    #pragma unroll
    for (int o = 16; o > 0; o >>= 1) s += __shfl_xor_sync(0xffffffffu, s, o);
    if (lane == 0) {
        float v = s + bias[n];
        if (ACT) v = gelu_exact(v);
        out[(size_t)wid * N + n] = v;
    }
}

// ---------------- compact residual + LN: dst[8][DD] = LN(base + delta) ----------------
__global__ void resid_ln_last(const float* __restrict__ base, long baseStride,
                              const float* __restrict__ delta,
                              const float* __restrict__ g, const float* __restrict__ beta,
                              float* __restrict__ dst)
{
    int b = blockIdx.x;
    int tid = threadIdx.x;
    const float* br = base + (size_t)b * baseStride;
    const float* dr = delta + (size_t)b * DD;
    float v[4];
    float s = 0.f;
    #pragma unroll
    for (int i = 0; i < 4; i++) { int idx = tid + i * 256; v[i] = br[idx] + dr[idx]; s += v[i]; }
    __shared__ float red[256];
    red[tid] = s; __syncthreads();
    #pragma unroll
    for (int o = 128; o > 0; o >>= 1) { if (tid < o) red[tid] += red[tid + o]; __syncthreads(); }
    float mean = red[0] * (1.f / 1024.f);
    __syncthreads();
    float s2 = 0.f;
    #pragma unroll
    for (int i = 0; i < 4; i++) { float d = v[i] - mean; s2 += d * d; }
    red[tid] = s2; __syncthreads();
    #pragma unroll
    for (int o = 128; o > 0; o >>= 1) { if (tid < o) red[tid] += red[tid + o]; __syncthreads(); }
    float inv = rsqrtf(red[0] * (1.f / 1024.f) + 1e-5f);
    #pragma unroll
    for (int i = 0; i < 4; i++) {
        int idx = tid + i * 256;
        dst[(size_t)b * DD + idx] = (v[i] - mean) * inv * g[idx] + beta[idx];
    }
}

// ---------------- fp32 -> fp16 ----------------
__global__ void cvt_kernel(const float* __restrict__ src,
                           __half* __restrict__ h, long n4)
{
    long i = (long)blockIdx.x * blockDim.x + threadIdx.x;
    if (i >= n4) return;
    float4 v = *(const float4*)(src + i * 4);
    uint2 hv;
    hv.x = pack_h2(v.x, v.y);
    hv.y = pack_h2(v.z, v.w);
    *(uint2*)(h + i * 4) = hv;
}

// ---------------- embedding: x tokens ----------------
__global__ void embed_x_kernel(const float* __restrict__ x,
                               const float* __restrict__ W_nail,
                               const float* __restrict__ b_nail)
{
    const float RSC = 0.99995000374968753f;
    int row = blockIdx.x;
    int b = row / LX;
    const float* xr = x + (long)row * 64;
    __shared__ float xn[63];
    __shared__ float t_sh;
    int tid = threadIdx.x;
    if (tid == 0) {
        float t0 = xr[0];
        g_xmask[row] = isnan(t0) ? 1 : 0;
        t_sh = isnan(t0) ? 0.f : t0;
    }
    if (tid < 63) {
        float v = xr[tid + 1];
        if (isnan(v)) v = 0.f;
        v *= RSC;
        xn[tid] = fminf(fmaxf(v, -5.f), 5.f);
    }
    __syncthreads();
    float t = t_sh;
    const float kfac = -logf(1000.f) / 1024.f;
    for (int d = tid; d < DD; d += 256) {
        const float* wr = W_nail + d * 63;
        float acc = b_nail[d];
        #pragma unroll 7
        for (int c = 0; c < 63; c++) acc = fmaf(xn[c], wr[c], acc);
        int i = d >> 1;
        float ang = t * expf((float)i * kfac);
        acc += (d & 1) ? cosf(ang) : sinf(ang);
        size_t idx = ((size_t)b * SS + (row % LX)) * DD + d;
        g_tgt[idx] = acc;
        g_tgt_s[idx] = __float2half_rn(acc);
    }
}

// ---------------- embedding: w tokens + global PE ----------------
__global__ void embed_w_kernel(const float* __restrict__ w,
                               const float* __restrict__ W_cond,
                               const float* __restrict__ b_cond)
{
    const float RSC = 0.99995000374968753f;
    int row = blockIdx.x;
    int b = row / NWTOK, r = row % NWTOK;
    const float* wr6 = w + (long)b * (NWTOK * 6) + r * 6;
    __shared__ float wn[6];
    int tid = threadIdx.x;
    if (tid < 6) {
        float v = wr6[tid];
        if (isnan(v)) v = 0.f;
        v *= RSC;
        wn[tid] = fminf(fmaxf(v, -5.f), 5.f);
    }
    __syncthreads();
    int spos = LX + r;
    const float kfac = -logf(1000.f) / 1024.f;
    for (int d = tid; d < DD; d += 256) {
        const float* wc = W_cond + d * 6;
        float acc = b_cond[d];
        #pragma unroll
        for (int c = 0; c < 6; c++) acc = fmaf(wn[c], wc[c], acc);
        int i = d >> 1;
        float ang = (float)spos * expf((float)i * kfac);
        acc += (d & 1) ? cosf(ang) : sinf(ang);
        size_t idx = ((size_t)b * SS + spos) * DD + d;
        g_tgt[idx] = acc;
        g_tgt_s[idx] = __float2half_rn(acc);
    }
}

// ---------------- residual add + LayerNorm (full rows, in-place, emits fp16) ----------------
__global__ void resid_ln_kernel(const __half* __restrict__ delta,
                                const float* __restrict__ g,
                                const float* __restrict__ beta)
{
    size_t row = blockIdx.x;
    float* t = g_tgt + row * DD;
    const __half* dl = delta + row * DD;
    int tid = threadIdx.x;
    float v[4];
    float s = 0.f;
    #pragma unroll
    for (int i = 0; i < 4; i++) {
        int idx = tid + i * 256;
        v[i] = t[idx] + __half2float(dl[idx]);
        s += v[i];
    }
    __shared__ float red[256];
    red[tid] = s; __syncthreads();
    #pragma unroll
    for (int o = 128; o > 0; o >>= 1) { if (tid < o) red[tid] += red[tid + o]; __syncthreads(); }
    float mean = red[0] * (1.f / 1024.f);
    __syncthreads();
    float s2 = 0.f;
    #pragma unroll
    for (int i = 0; i < 4; i++) { float d = v[i] - mean; s2 += d * d; }
    red[tid] = s2; __syncthreads();
    #pragma unroll
    for (int o = 128; o > 0; o >>= 1) { if (tid < o) red[tid] += red[tid + o]; __syncthreads(); }
    float inv = rsqrtf(red[0] * (1.f / 1024.f) + 1e-5f);
    #pragma unroll
    for (int i = 0; i < 4; i++) {
        int idx = tid + i * 256;
        float out = (v[i] - mean) * inv * g[idx] + beta[idx];
        t[idx] = out;
        g_tgt_s[row * DD + idx] = __float2half_rn(out);
    }
}

// ---------------- head + loss (reads compact final rows) ----------------
__global__ void loss_kernel(const float* __restrict__ W_ham, const float* __restrict__ b_ham,
                            const float* __restrict__ y, const float* __restrict__ w,
                            float* __restrict__ out)
{
    __shared__ float red[256];
    int tid = threadIdx.x;
    float acc = 0.f;
    for (int idx = tid; idx < BB * 144; idx += 256) {
        int b = idx / 144;
        int j = idx % 144;
        const float* row = g_c_x + (size_t)b * DD;
        const float* wr = W_ham + (size_t)j * DD;
        float dot = b_ham[j];
        for (int k = 0; k < DD; k++) dot = fmaf(row[k], wr[k], dot);
        float yr = y[b * 144 + j] - w[(size_t)b * 2304 + 2160 + j];
        float d = dot - yr;
        acc += d * d;
    }
    red[tid] = acc; __syncthreads();
    #pragma unroll
    for (int o = 128; o > 0; o >>= 1) { if (tid < o) red[tid] += red[tid + o]; __syncthreads(); }
    if (tid == 0) out[0] = red[0] / (float)(BB * 144);
}

// ---------------- launch ----------------
extern "C" void kernel_launch(void* const* d_in, const int* in_sizes, int n_in,
                              void* d_out, int out_size)
{
    const float* x      = (const float*)d_in[0];
    const float* w      = (const float*)d_in[1];
    const float* y      = (const float*)d_in[2];
    const float* W_nail = (const float*)d_in[3];
    const float* b_nail = (const float*)d_in[4];
    const float* W_cond = (const float*)d_in[5];
    const float* b_cond = (const float*)d_in[6];
    const float* Wqkv   = (const float*)d_in[7];
    const float* bqkv   = (const float*)d_in[8];
    const float* Wo     = (const float*)d_in[9];
    const float* bo     = (const float*)d_in[10];
    const float* ln1_g  = (const float*)d_in[11];
    const float* ln1_b  = (const float*)d_in[12];
    const float* ln2_g  = (const float*)d_in[13];
    const float* ln2_b  = (const float*)d_in[14];
    const float* W1     = (const float*)d_in[15];
    const float* b1     = (const float*)d_in[16];
    const float* W2     = (const float*)d_in[17];
    const float* b2     = (const float*)d_in[18];
    const float* W_ham  = (const float*)d_in[19];
    const float* b_ham  = (const float*)d_in[20];

    float *p_tgt, *p_c_attn, *p_c_t2, *p_c_x, *p_c_hid;
    __half *p_tgt_s, *p_qkv, *p_attno, *p_hid, *p_tmp_h;
    __half *p_wqkv, *p_wo, *p_w1, *p_w2;
    cudaGetSymbolAddress((void**)&p_tgt,    g_tgt);
    cudaGetSymbolAddress((void**)&p_tgt_s,  g_tgt_s);
    cudaGetSymbolAddress((void**)&p_qkv,    g_qkv);
    cudaGetSymbolAddress((void**)&p_attno,  g_attno);
    cudaGetSymbolAddress((void**)&p_hid,    g_hid);
    cudaGetSymbolAddress((void**)&p_tmp_h,  g_tmp_h);
    cudaGetSymbolAddress((void**)&p_wqkv,   g_wqkv);
    cudaGetSymbolAddress((void**)&p_wo,     g_wo);
    cudaGetSymbolAddress((void**)&p_w1,     g_w1);
    cudaGetSymbolAddress((void**)&p_w2,     g_w2);
    cudaGetSymbolAddress((void**)&p_c_attn, g_c_attn);
    cudaGetSymbolAddress((void**)&p_c_t2,   g_c_t2);
    cudaGetSymbolAddress((void**)&p_c_x,    g_c_x);
    cudaGetSymbolAddress((void**)&p_c_hid,  g_c_hid);

    static const int SMG = 32768 * 3;              // 98304
    static const int SMF = 16384 + 3 * 16384;      // 65536
    cudaFuncSetAttribute(mma_gemm<0, 0>, cudaFuncAttributeMaxDynamicSharedMemorySize, SMG);
    cudaFuncSetAttribute(mma_gemm<0, 1>, cudaFuncAttributeMaxDynamicSharedMemorySize, SMG);
    cudaFuncSetAttribute(mma_gemm<1, 0>, cudaFuncAttributeMaxDynamicSharedMemorySize, SMG);
    cudaFuncSetAttribute(flash_kernel,   cudaFuncAttributeMaxDynamicSharedMemorySize, SMF);

    const int M = BB * SS;   // 7168
    dim3 blk(256);

    // weight conversions (wo/w1/w2 only needed for layers 0..2)
    {
        long n;
        n = (long)NLAYER * 3 * DD * DD / 4;
        cvt_kernel<<<(unsigned)((n + 255) / 256), blk>>>(Wqkv, p_wqkv, n);
        n = (long)(NLAYER - 1) * DD * DD / 4;
        cvt_kernel<<<(unsigned)((n + 255) / 256), blk>>>(Wo, p_wo, n);
        n = (long)(NLAYER - 1) * FFD * DD / 4;
        cvt_kernel<<<(unsigned)((n + 255) / 256), blk>>>(W1, p_w1, n);
        n = (long)(NLAYER - 1) * DD * FFD / 4;
        cvt_kernel<<<(unsigned)((n + 255) / 256), blk>>>(W2, p_w2, n);
    }

    embed_x_kernel<<<BB * LX, blk>>>(x, W_nail, b_nail);
    embed_w_kernel<<<BB * NWTOK, blk>>>(w, W_cond, b_cond);

    // ---- layers 0..2: full pipeline ----
    for (int l = 0; l < NLAYER - 1; l++) {
        const __half* wqkv_l = p_wqkv + (size_t)l * 3 * DD * DD;
        const __half* wo_l   = p_wo + (size_t)l * DD * DD;
        const __half* w1_l   = p_w1 + (size_t)l * FFD * DD;
        const __half* w2_l   = p_w2 + (size_t)l * DD * FFD;

        mma_gemm<0, 1><<<dim3(M / 128, 3 * DD / 128), blk, SMG>>>(
            p_tgt_s, wqkv_l, bqkv + (size_t)l * 3 * DD,
            p_qkv, DD, DD, DD, 3 * DD);

        flash_kernel<<<dim3(SS / 128, BB * NH), blk, SMF>>>();

        mma_gemm<0, 0><<<dim3(M / 128, DD / 128), blk, SMG>>>(
            p_attno, wo_l, bo + (size_t)l * DD,
            p_tmp_h, DD, DD, DD, DD);

        resid_ln_kernel<<<M, blk>>>(p_tmp_h, ln1_g + (size_t)l * DD, ln1_b + (size_t)l * DD);

        mma_gemm<1, 0><<<dim3(M / 128, FFD / 128), blk, SMG>>>(
            p_tgt_s, w1_l, b1 + (size_t)l * FFD,
            p_hid, DD, DD, DD, FFD);

        mma_gemm<0, 0><<<dim3(M / 128, DD / 128), blk, SMG>>>(
            p_hid, w2_l, b2 + (size_t)l * DD,
            p_tmp_h, FFD, FFD, FFD, DD);

        resid_ln_kernel<<<M, blk>>>(p_tmp_h, ln2_g + (size_t)l * DD, ln2_b + (size_t)l * DD);
    }

    // ---- layer 3: only the final token per batch matters downstream ----
    {
        const int l = NLAYER - 1;
        // K,V for all tokens (columns 1024..3071 of the QKV projection)
        mma_gemm<0, 0><<<dim3(M / 128, 2 * DD / 128), blk, SMG>>>(
            p_tgt_s, p_wqkv + (size_t)l * 3 * DD * DD + (size_t)DD * DD,
            bqkv + (size_t)l * 3 * DD + DD,
            p_qkv + DD, DD, DD, DD, 3 * DD);

        // attention for the 8 final tokens (fp32, exact softmax)
        flash_last_kernel<<<BB * NH, blk>>>(
            Wqkv + (size_t)l * 3 * DD * DD, bqkv + (size_t)l * 3 * DD);

        // Wo on 8 rows
        small_gemm<0><<<DD, blk>>>(p_c_attn, Wo + (size_t)l * DD * DD,
                                   bo + (size_t)l * DD, p_c_t2, DD, DD);
        // LN1: base = g_tgt final rows (stride SS*DD, offset to last row)
        resid_ln_last<<<BB, blk>>>(p_tgt + (size_t)(SS - 1) * DD, (long)SS * DD,
                                   p_c_t2, ln1_g + (size_t)l * DD, ln1_b + (size_t)l * DD,
                                   p_c_x);
        // FF1 (gelu)
        small_gemm<1><<<FFD, blk>>>(p_c_x, W1 + (size_t)l * FFD * DD,
                                    b1 + (size_t)l * FFD, p_c_hid, FFD, DD);
        // FF2
        small_gemm<0><<<DD, blk>>>(p_c_hid, W2 + (size_t)l * DD * FFD,
                                   b2 + (size_t)l * DD, p_c_t2, DD, FFD);
        // LN2: base = compact x
        resid_ln_last<<<BB, blk>>>(p_c_x, (long)DD,
                                   p_c_t2, ln2_g + (size_t)l * DD, ln2_b + (size_t)l * DD,
                                   p_c_x);
    }

    loss_kernel<<<1, blk>>>(W_ham, b_ham, y, w, (float*)d_out);
}

// round 11
// speedup vs baseline: 13.4428x; 1.0970x over previous
#include <cuda_runtime.h>
#include <cuda_fp16.h>
#include <math.h>
#include <stdint.h>

// Problem dims (fixed by setup_inputs)
#define BB 8
#define LX 512
#define NWTOK 384
#define SS 896
#define DD 1024
#define NH 16
#define HD 64
#define FFD 4096
#define NLAYER 4

// ---------------- scratch (device globals) ----------------
__device__ __half g_tgt_s[BB * SS * DD];          // fp16 residual stream
__device__ __half g_qkv[(size_t)BB * SS * 3 * DD];
__device__ __half g_attno[(size_t)BB * SS * DD];
__device__ __half g_hid[(size_t)BB * SS * FFD];
__device__ __half g_tmp_h[BB * SS * DD];
__device__ int   g_xmask[BB * LX];
__device__ __half g_embA[BB * LX * 64];           // packed x features (K=64 padded)
__device__ __half g_wnail_h[DD * 64];             // W_nail half, K padded to 64
__device__ float g_pe_t[BB * LX];                 // t value per x row
// weights fp16
__device__ __half g_wqkv[(size_t)NLAYER * 3 * DD * DD];
__device__ __half g_wo[(size_t)NLAYER * DD * DD];
__device__ __half g_w1[(size_t)NLAYER * FFD * DD];
__device__ __half g_w2[(size_t)NLAYER * DD * FFD];
// compact last-layer buffers (fp32, 8 rows)
__device__ float g_c_attn[BB * DD];
__device__ float g_c_t2[BB * DD];
__device__ float g_c_x[BB * DD];
__device__ float g_c_hid[BB * FFD];

// scores arrive pre-multiplied by 0.125*log2(e); softmax works in log2 domain
#define QSCALE 0.18033688011112042f

// ---------------- helpers ----------------
__device__ __forceinline__ uint32_t smem_u32(const void* p) {
    uint32_t a;
    asm("{ .reg .u64 t; cvta.to.shared.u64 t, %1; cvt.u32.u64 %0, t; }" : "=r"(a) : "l"(p));
    return a;
}
__device__ __forceinline__ uint32_t swz(uint32_t base, int row, int byteoff) {
    return base + row * 128 + (((byteoff >> 4) ^ (row & 7)) << 4);
}
__device__ __forceinline__ void cp_async16(uint32_t saddr, const void* gaddr) {
    asm volatile("cp.async.cg.shared.global [%0], [%1], 16;" :: "r"(saddr), "l"(gaddr));
}
__device__ __forceinline__ void cp_commit() {
    asm volatile("cp.async.commit_group;" ::: "memory");
}
template<int N>
__device__ __forceinline__ void cp_wait() {
    asm volatile("cp.async.wait_group %0;" :: "n"(N) : "memory");
}
__device__ __forceinline__ void ldsm_x4(uint32_t (&r)[4], uint32_t addr) {
    asm volatile("ldmatrix.sync.aligned.m8n8.x4.shared.b16 {%0,%1,%2,%3}, [%4];"
        : "=r"(r[0]), "=r"(r[1]), "=r"(r[2]), "=r"(r[3]) : "r"(addr));
}
__device__ __forceinline__ void ldsm_x4_trans(uint32_t (&r)[4], uint32_t addr) {
    asm volatile("ldmatrix.sync.aligned.m8n8.x4.trans.shared.b16 {%0,%1,%2,%3}, [%4];"
        : "=r"(r[0]), "=r"(r[1]), "=r"(r[2]), "=r"(r[3]) : "r"(addr));
}
__device__ __forceinline__ void mma16816(float (&d)[4], const uint32_t (&a)[4],
                                         uint32_t b0, uint32_t b1) {
    asm volatile("mma.sync.aligned.m16n8k16.row.col.f32.f16.f16.f32 "
        "{%0,%1,%2,%3}, {%4,%5,%6,%7}, {%8,%9}, {%0,%1,%2,%3};"
        : "+f"(d[0]), "+f"(d[1]), "+f"(d[2]), "+f"(d[3])
        : "r"(a[0]), "r"(a[1]), "r"(a[2]), "r"(a[3]), "r"(b0), "r"(b1));
}
__device__ __forceinline__ float gelu_exact(float x) {
    return 0.5f * x * (1.0f + erff(x * 0.70710678118654752f));
}
__device__ __forceinline__ uint32_t pack_h2(float f0, float f1) {
    __half2 h = __floats2half2_rn(f0, f1);
    return *(uint32_t*)&h;
}
__device__ __forceinline__ uint32_t ex2_h2(uint32_t t) {
    uint32_t r;
    asm("ex2.approx.f16x2 %0, %1;" : "=r"(r) : "r"(t));
    return r;
}
__device__ __forceinline__ float ex2f(float x) {
    float r;
    asm("ex2.approx.f32 %0, %1;" : "=f"(r) : "f"(x));
    return r;
}

// =====================================================================
// Dense fp16 GEMM: C = act(A @ B^T + bias) [optionally scale cols<1024 by QSCALE]
// =====================================================================
template<int ACT, int SCALEQ>
__global__ void __launch_bounds__(256, 2)
mma_gemm(const __half* __restrict__ A, const __half* __restrict__ B,
         const float* __restrict__ bias, __half* __restrict__ Ch,
         int K, int lda, int ldb, int ldc)
{
    extern __shared__ __align__(16) char sm[];
    constexpr int B_OFF = 128 * 128;
    constexpr int STAGE = 2 * B_OFF;

    const int tid = threadIdx.x;
    const int wid = tid >> 5, lane = tid & 31;
    const int warp_m = wid >> 1, warp_n = wid & 1;
    const int m0 = blockIdx.x * 128;
    const int n0 = blockIdx.y * 128;
    const uint32_t smem_base = smem_u32(sm);
    const int nch = K >> 6;

    float acc[2][8][4];
    #pragma unroll
    for (int a = 0; a < 2; a++)
        #pragma unroll
        for (int b = 0; b < 8; b++)
            #pragma unroll
            for (int c = 0; c < 4; c++) acc[a][b][c] = 0.f;

    auto load_stage = [&](int stage, int ch) {
        const int k0 = ch << 6;
        const uint32_t sbase = smem_base + stage * STAGE;
        #pragma unroll
        for (int i = tid; i < 1024; i += 256) {
            int row = i >> 3, seg = i & 7;
            cp_async16(sbase + row * 128 + ((seg ^ (row & 7)) << 4),
                       A + (long)(m0 + row) * lda + k0 + seg * 8);
        }
        #pragma unroll
        for (int i = tid; i < 1024; i += 256) {
            int row = i >> 3, seg = i & 7;
            cp_async16(sbase + B_OFF + row * 128 + ((seg ^ (row & 7)) << 4),
                       B + (long)(n0 + row) * ldb + k0 + seg * 8);
        }
        cp_commit();
    };

    auto compute = [&](int stage) {
        const uint32_t sbase = smem_base + stage * STAGE;
        const int arow = warp_m * 32 + (lane & 15);
        const int bn   = (lane & 7) + (lane >> 4) * 8;
        const int bka  = ((lane >> 3) & 1) * 8;
        #pragma unroll
        for (int kk = 0; kk < 4; kk++) {
            const int acol = kk * 16 + (lane >> 4) * 8;
            uint32_t af[2][4];
            #pragma unroll
            for (int mt = 0; mt < 2; mt++)
                ldsm_x4(af[mt], swz(sbase, arow + mt * 16, acol * 2));
            const int bk = kk * 16 + bka;
            #pragma unroll
            for (int nt2 = 0; nt2 < 4; nt2++) {
                uint32_t bf[4];
                ldsm_x4(bf, swz(sbase + B_OFF, warp_n * 64 + nt2 * 16 + bn, bk * 2));
                #pragma unroll
                for (int mt = 0; mt < 2; mt++) {
                    #pragma unroll
                    for (int j = 0; j < 2; j++)
                        mma16816(acc[mt][nt2 * 2 + j], af[mt], bf[2 * j], bf[2 * j + 1]);
                }
            }
        }
    };

    load_stage(0, 0);
    if (nch > 1) load_stage(1, 1);
    for (int ch = 0; ch < nch; ch++) {
        if (ch + 1 < nch) cp_wait<1>(); else cp_wait<0>();
        __syncthreads();
        if (ch + 2 < nch) load_stage((ch + 2) % 3, ch + 2);
        compute(ch % 3);
    }

    const int r0 = lane >> 2, c0 = (lane & 3) * 2;
    #pragma unroll
    for (int mt = 0; mt < 2; mt++) {
        #pragma unroll
        for (int nt = 0; nt < 8; nt++) {
            const int n = n0 + warp_n * 64 + nt * 8 + c0;
            float bv0 = bias ? bias[n] : 0.f;
            float bv1 = bias ? bias[n + 1] : 0.f;
            #pragma unroll
            for (int hrow = 0; hrow < 2; hrow++) {
                const int m = m0 + warp_m * 32 + mt * 16 + r0 + hrow * 8;
                float f0 = acc[mt][nt][hrow * 2 + 0] + bv0;
                float f1 = acc[mt][nt][hrow * 2 + 1] + bv1;
                if (ACT == 1) { f0 = gelu_exact(f0); f1 = gelu_exact(f1); }
                if (SCALEQ && n < DD) { f0 *= QSCALE; f1 *= QSCALE; }
                *(uint32_t*)(Ch + (long)m * ldc + n) = pack_h2(f0, f1);
            }
        }
    }
}

// =====================================================================
// Flash attention (fp16), layers 0..2
// =====================================================================
__global__ void __launch_bounds__(256, 2)
flash_kernel()
{
    extern __shared__ __align__(16) char fsm[];
    __shared__ uint32_t maskbits[16];
    constexpr int KV_OFF = 128 * 128;
    constexpr int TILE = 64 * 128;
    constexpr int KSTAGE = 2 * TILE;

    const int bh = blockIdx.y;
    const int b = bh >> 4, h = bh & 15;
    const int q0 = (gridDim.x - 1 - blockIdx.x) * 128;
    const int tid = threadIdx.x;
    const int wid = tid >> 5, lane = tid & 31;
    const uint32_t smem = smem_u32(fsm);

    if (tid < 16) {
        uint32_t m = 0;
        const int* xm = g_xmask + b * LX + tid * 32;
        #pragma unroll
        for (int i = 0; i < 32; i++) m |= (xm[i] ? 1u : 0u) << i;
        maskbits[tid] = m;
    }

    #pragma unroll
    for (int i = tid; i < 1024; i += 256) {
        int row = i >> 3, seg = i & 7;
        cp_async16(smem + row * 128 + ((seg ^ (row & 7)) << 4),
                   g_qkv + ((size_t)(b * SS + q0 + row)) * (3 * DD) + h * 64 + seg * 8);
    }
    cp_commit();

    const int nch = (q0 < LX) ? 8 : ((q0 + 128) >> 6);

    auto load_kv = [&](int c, int s) {
        const int k0 = c << 6;
        const uint32_t sb = smem + KV_OFF + s * KSTAGE;
        #pragma unroll
        for (int i = tid; i < 512; i += 256) {
            int row = i >> 3, seg = i & 7;
            cp_async16(sb + row * 128 + ((seg ^ (row & 7)) << 4),
                       g_qkv + ((size_t)(b * SS + k0 + row)) * (3 * DD) + DD + h * 64 + seg * 8);
        }
        #pragma unroll
        for (int i = tid; i < 512; i += 256) {
            int row = i >> 3, seg = i & 7;
            cp_async16(sb + TILE + row * 128 + ((seg ^ (row & 7)) << 4),
                       g_qkv + ((size_t)(b * SS + k0 + row)) * (3 * DD) + 2 * DD + h * 64 + seg * 8);
        }
        cp_commit();
    };

    load_kv(0, 0);
    load_kv(1, 1);

    float m_[2] = {-1e30f, -1e30f}, l_[2] = {0.f, 0.f};
    float out[8][4];
    #pragma unroll
    for (int j = 0; j < 8; j++)
        #pragma unroll
        for (int e = 0; e < 4; e++) out[j][e] = 0.f;

    const int r0 = lane >> 2;
    const int qrow0 = q0 + wid * 16 + r0;
    const int arow = wid * 16 + (lane & 15);
    const int bn   = (lane & 7) + (lane >> 4) * 8;
    const int bka  = ((lane >> 3) & 1) * 8;
    const int trow = (lane & 7) + ((lane >> 3) & 1) * 8;
    const int tcol = (lane >> 4) * 8;

    for (int c = 0; c < nch; c++) {
        if (c + 1 < nch) cp_wait<1>(); else cp_wait<0>();
        __syncthreads();
        if (c + 2 < nch) load_kv(c + 2, (c + 2) % 3);
        const uint32_t sb = smem + KV_OFF + (c % 3) * KSTAGE;

        float s[8][4];
        #pragma unroll
        for (int j = 0; j < 8; j++)
            #pragma unroll
            for (int e = 0; e < 4; e++) s[j][e] = 0.f;
        #pragma unroll
        for (int t = 0; t < 4; t++) {
            const int acol = t * 16 + (lane >> 4) * 8;
            uint32_t qf[4];
            ldsm_x4(qf, swz(smem, arow, acol * 2));
            const int bk = t * 16 + bka;
            #pragma unroll
            for (int j = 0; j < 4; j++) {
                uint32_t kf[4];
                ldsm_x4(kf, swz(sb, j * 16 + bn, bk * 2));
                mma16816(s[2 * j], qf, kf[0], kf[1]);
                mma16816(s[2 * j + 1], qf, kf[2], kf[3]);
            }
        }

        const int k0 = c << 6;
        uint32_t vmask;
        float cmax[2] = {-1e30f, -1e30f};
        if (k0 + 64 <= LX) {
            vmask = 0;
            #pragma unroll
            for (int j = 0; j < 8; j++) {
                #pragma unroll
                for (int e = 0; e < 4; e++) {
                    int col = k0 + j * 8 + (lane & 3) * 2 + (e & 1);
                    if (!((maskbits[col >> 5] >> (col & 31)) & 1)) {
                        vmask |= 1u << (j * 4 + e);
                        cmax[e >> 1] = fmaxf(cmax[e >> 1], s[j][e]);
                    }
                }
            }
        } else if (k0 + 64 <= q0 + wid * 16) {
            vmask = 0xffffffffu;
            #pragma unroll
            for (int j = 0; j < 8; j++) {
                #pragma unroll
                for (int e = 0; e < 4; e++)
                    cmax[e >> 1] = fmaxf(cmax[e >> 1], s[j][e]);
            }
        } else {
            vmask = 0;
            #pragma unroll
            for (int j = 0; j < 8; j++) {
                #pragma unroll
                for (int e = 0; e < 4; e++) {
                    int col = k0 + j * 8 + (lane & 3) * 2 + (e & 1);
                    int row = (e < 2) ? qrow0 : (qrow0 + 8);
                    if (col <= row) {
                        vmask |= 1u << (j * 4 + e);
                        cmax[e >> 1] = fmaxf(cmax[e >> 1], s[j][e]);
                    }
                }
            }
        }
        #pragma unroll
        for (int o = 1; o <= 2; o <<= 1) {
            cmax[0] = fmaxf(cmax[0], __shfl_xor_sync(0xffffffffu, cmax[0], o));
            cmax[1] = fmaxf(cmax[1], __shfl_xor_sync(0xffffffffu, cmax[1], o));
        }
        float mn0 = fmaxf(m_[0], cmax[0]);
        float mn1 = fmaxf(m_[1], cmax[1]);
        float f0 = ex2f(m_[0] - mn0);
        float f1 = ex2f(m_[1] - mn1);

        uint32_t ph01[8], ph23[8];
        __half2 a01 = __floats2half2_rn(0.f, 0.f);
        __half2 a23 = a01;
        #pragma unroll
        for (int j = 0; j < 8; j++) {
            float t0 = ((vmask >> (j * 4 + 0)) & 1) ? (s[j][0] - mn0) : -100.f;
            float t1 = ((vmask >> (j * 4 + 1)) & 1) ? (s[j][1] - mn0) : -100.f;
            float t2 = ((vmask >> (j * 4 + 2)) & 1) ? (s[j][2] - mn1) : -100.f;
            float t3 = ((vmask >> (j * 4 + 3)) & 1) ? (s[j][3] - mn1) : -100.f;
            ph01[j] = ex2_h2(pack_h2(t0, t1));
            ph23[j] = ex2_h2(pack_h2(t2, t3));
            a01 = __hadd2(a01, *(__half2*)&ph01[j]);
            a23 = __hadd2(a23, *(__half2*)&ph23[j]);
        }
        float2 s01 = __half22float2(a01);
        float2 s23 = __half22float2(a23);
        float rs0 = s01.x + s01.y;
        float rs1 = s23.x + s23.y;
        #pragma unroll
        for (int o = 1; o <= 2; o <<= 1) {
            rs0 += __shfl_xor_sync(0xffffffffu, rs0, o);
            rs1 += __shfl_xor_sync(0xffffffffu, rs1, o);
        }
        l_[0] = l_[0] * f0 + rs0;
        l_[1] = l_[1] * f1 + rs1;
        m_[0] = mn0; m_[1] = mn1;
        if (f0 != 1.f) {
            #pragma unroll
            for (int j = 0; j < 8; j++) { out[j][0] *= f0; out[j][1] *= f0; }
        }
        if (f1 != 1.f) {
            #pragma unroll
            for (int j = 0; j < 8; j++) { out[j][2] *= f1; out[j][3] *= f1; }
        }

        #pragma unroll
        for (int t = 0; t < 4; t++) {
            uint32_t pf[4] = { ph01[2 * t], ph23[2 * t], ph01[2 * t + 1], ph23[2 * t + 1] };
            #pragma unroll
            for (int j = 0; j < 4; j++) {
                uint32_t vf[4];
                ldsm_x4_trans(vf, swz(sb + TILE, t * 16 + trow, (j * 16 + tcol) * 2));
                mma16816(out[2 * j], pf, vf[0], vf[1]);
                mma16816(out[2 * j + 1], pf, vf[2], vf[3]);
            }
        }
    }

    float inv0 = 1.f / l_[0];
    float inv1 = 1.f / l_[1];
    #pragma unroll
    for (int j = 0; j < 8; j++) {
        const int d = h * 64 + j * 8 + (lane & 3) * 2;
        *(uint32_t*)(g_attno + ((size_t)(b * SS + qrow0)) * DD + d) =
            pack_h2(out[j][0] * inv0, out[j][1] * inv0);
        *(uint32_t*)(g_attno + ((size_t)(b * SS + qrow0 + 8)) * DD + d) =
            pack_h2(out[j][2] * inv1, out[j][3] * inv1);
    }
}

// =====================================================================
// Last layer: attention for ONLY the final token of each batch.
// =====================================================================
__global__ void flash_last_kernel(const float* __restrict__ Wq,
                                  const float* __restrict__ bq)
{
    __shared__ float xrow[DD];
    __shared__ float q[HD];
    __shared__ float probs[SS];
    __shared__ float red[256];
    const int bh = blockIdx.x;
    const int b = bh >> 4, h = bh & 15;
    const int tid = threadIdx.x;

    const __half* trow = g_tgt_s + ((size_t)b * SS + SS - 1) * DD;
    for (int i = tid; i < DD; i += 256) xrow[i] = __half2float(trow[i]);
    __syncthreads();

    {
        int d = tid >> 2, part = tid & 3;
        const float* wr = Wq + (size_t)(h * HD + d) * DD;
        float s = 0.f;
        for (int k = part; k < DD; k += 4) s = fmaf(xrow[k], wr[k], s);
        s += __shfl_xor_sync(0xffffffffu, s, 1);
        s += __shfl_xor_sync(0xffffffffu, s, 2);
        if (part == 0) q[d] = (s + bq[h * HD + d]) * 0.125f;
    }
    __syncthreads();

    const int* xm = g_xmask + b * LX;
    float lmax = -1e30f;
    for (int k = tid; k < SS; k += 256) {
        bool valid = (k < LX) ? (xm[k] == 0) : true;
        float s = 0.f;
        const __half* krow = g_qkv + ((size_t)(b * SS + k)) * (3 * DD) + DD + h * 64;
        #pragma unroll 16
        for (int d = 0; d < HD; d++) s = fmaf(q[d], __half2float(krow[d]), s);
        probs[k] = valid ? s : -1e30f;
        if (valid) lmax = fmaxf(lmax, s);
    }
    red[tid] = lmax; __syncthreads();
    for (int o = 128; o > 0; o >>= 1) { if (tid < o) red[tid] = fmaxf(red[tid], red[tid + o]); __syncthreads(); }
    float mx = red[0]; __syncthreads();
    float lsum = 0.f;
    for (int k = tid; k < SS; k += 256) {
        float p = (probs[k] > -1e29f) ? __expf(probs[k] - mx) : 0.f;
        probs[k] = p; lsum += p;
    }
    red[tid] = lsum; __syncthreads();
    for (int o = 128; o > 0; o >>= 1) { if (tid < o) red[tid] += red[tid + o]; __syncthreads(); }
    float inv = 1.f / red[0]; __syncthreads();

    {
        int d = tid >> 2, part = tid & 3;
        float s = 0.f;
        for (int k = part; k < SS; k += 4) {
            const __half* vrow = g_qkv + ((size_t)(b * SS + k)) * (3 * DD) + 2 * DD + h * 64;
            s = fmaf(probs[k], __half2float(vrow[d]), s);
        }
        s += __shfl_xor_sync(0xffffffffu, s, 1);
        s += __shfl_xor_sync(0xffffffffu, s, 2);
        if (part == 0) g_c_attn[b * DD + h * HD + d] = s * inv;
    }
}

// ---------------- small GEMM on 8 compact rows ----------------
template<int ACT>
__global__ void small_gemm(const float* __restrict__ in, const float* __restrict__ W,
                           const float* __restrict__ bias, float* __restrict__ out,
                           int N, int K)
{
    int n = blockIdx.x;
    int wid = threadIdx.x >> 5, lane = threadIdx.x & 31;
    const float* wrow = W + (size_t)n * K;
    const float* irow = in + (size_t)wid * K;
    float s = 0.f;
    for (int k = lane; k < K; k += 32) s = fmaf(irow[k], wrow[k], s);
    #pragma unroll
    for (int o = 16; o > 0; o >>= 1) s += __shfl_xor_sync(0xffffffffu, s, o);
    if (lane == 0) {
        float v = s + bias[n];
        if (ACT) v = gelu_exact(v);
        out[(size_t)wid * N + n] = v;
    }
}

// ---------------- compact residual + LN (base: half if baseH, else float) ----------------
__global__ void resid_ln_last(const __half* __restrict__ baseH, long baseStride,
                              const float* __restrict__ baseF,
                              const float* __restrict__ delta,
                              const float* __restrict__ g, const float* __restrict__ beta,
                              float* __restrict__ dst)
{
    int b = blockIdx.x;
    int tid = threadIdx.x;
    const float* dr = delta + (size_t)b * DD;
    float v[4];
    float s = 0.f;
    #pragma unroll
    for (int i = 0; i < 4; i++) {
        int idx = tid + i * 256;
        float base = baseH ? __half2float(baseH[(size_t)b * baseStride + idx])
                           : baseF[(size_t)b * DD + idx];
        v[i] = base + dr[idx];
        s += v[i];
    }
    __shared__ float red[256];
    red[tid] = s; __syncthreads();
    #pragma unroll
    for (int o = 128; o > 0; o >>= 1) { if (tid < o) red[tid] += red[tid + o]; __syncthreads(); }
    float mean = red[0] * (1.f / 1024.f);
    __syncthreads();
    float s2 = 0.f;
    #pragma unroll
    for (int i = 0; i < 4; i++) { float d = v[i] - mean; s2 += d * d; }
    red[tid] = s2; __syncthreads();
    #pragma unroll
    for (int o = 128; o > 0; o >>= 1) { if (tid < o) red[tid] += red[tid + o]; __syncthreads(); }
    float inv = rsqrtf(red[0] * (1.f / 1024.f) + 1e-5f);
    #pragma unroll
    for (int i = 0; i < 4; i++) {
        int idx = tid + i * 256;
        dst[(size_t)b * DD + idx] = (v[i] - mean) * inv * g[idx] + beta[idx];
    }
}

// ---------------- fp32 -> fp16 ----------------
__global__ void cvt_kernel(const float* __restrict__ src,
                           __half* __restrict__ h, long n4)
{
    long i = (long)blockIdx.x * blockDim.x + threadIdx.x;
    if (i >= n4) return;
    float4 v = *(const float4*)(src + i * 4);
    uint2 hv;
    hv.x = pack_h2(v.x, v.y);
    hv.y = pack_h2(v.z, v.w);
    *(uint2*)(h + i * 4) = hv;
}

// ---------------- prep x: pack features to half [4096 x 64], mask, t ----------------
__global__ void prep_x_kernel(const float* __restrict__ x)
{
    const float RSC = 0.99995000374968753f;
    int row = blockIdx.x;          // b*LX + l
    int tid = threadIdx.x;         // 64
    const float* xr = x + (long)row * 64;
    if (tid == 0) {
        float t0 = xr[0];
        g_xmask[row] = isnan(t0) ? 1 : 0;
        g_pe_t[row] = isnan(t0) ? 0.f : t0;
    }
    float v = 0.f;
    if (tid < 63) {
        float u = xr[tid + 1];
        if (isnan(u)) u = 0.f;
        u *= RSC;
        v = fminf(fmaxf(u, -5.f), 5.f);
    }
    g_embA[row * 64 + tid] = __float2half_rn(v);
}

// ---------------- pad W_nail to half [1024 x 64] ----------------
__global__ void prep_wnail_kernel(const float* __restrict__ W_nail)
{
    int d = blockIdx.x;
    int k = threadIdx.x;   // 64
    g_wnail_h[d * 64 + k] = __float2half_rn(k < 63 ? W_nail[d * 63 + k] : 0.f);
}

// ---------------- PE add for x tokens: tmp_h[4096x1024] + PE -> tgt_s ----------------
__global__ void pe_x_kernel()
{
    int row = blockIdx.x;          // b*LX + l
    int b = row / LX, l = row % LX;
    int tid = threadIdx.x;         // 256
    float t = g_pe_t[row];
    const float kfac = -logf(1000.f) / 1024.f;
    const __half* src = g_tmp_h + (size_t)row * DD;
    __half* dst = g_tgt_s + ((size_t)b * SS + l) * DD;
    for (int d = tid; d < DD; d += 256) {
        int i = d >> 1;
        float ang = t * expf((float)i * kfac);
        float pe = (d & 1) ? cosf(ang) : sinf(ang);
        dst[d] = __float2half_rn(__half2float(src[d]) + pe);
    }
}

// ---------------- embedding: w tokens + global PE (half out) ----------------
__global__ void embed_w_kernel(const float* __restrict__ w,
                               const float* __restrict__ W_cond,
                               const float* __restrict__ b_cond)
{
    const float RSC = 0.99995000374968753f;
    int row = blockIdx.x;
    int b = row / NWTOK, r = row % NWTOK;
    const float* wr6 = w + (long)b * (NWTOK * 6) + r * 6;
    __shared__ float wn[6];
    int tid = threadIdx.x;
    if (tid < 6) {
        float v = wr6[tid];
        if (isnan(v)) v = 0.f;
        v *= RSC;
        wn[tid] = fminf(fmaxf(v, -5.f), 5.f);
    }
    __syncthreads();
    int spos = LX + r;
    const float kfac = -logf(1000.f) / 1024.f;
    for (int d = tid; d < DD; d += 256) {
        const float* wc = W_cond + d * 6;
        float acc = b_cond[d];
        #pragma unroll
        for (int c = 0; c < 6; c++) acc = fmaf(wn[c], wc[c], acc);
        int i = d >> 1;
        float ang = (float)spos * expf((float)i * kfac);
        acc += (d & 1) ? cosf(ang) : sinf(ang);
        g_tgt_s[((size_t)b * SS + spos) * DD + d] = __float2half_rn(acc);
    }
}

// ---------------- residual add + LayerNorm (fp16 stream, fp32 math) ----------------
__global__ void resid_ln_kernel(const __half* __restrict__ delta,
                                const float* __restrict__ g,
                                const float* __restrict__ beta)
{
    size_t row = blockIdx.x;
    __half* t = g_tgt_s + row * DD;
    const __half* dl = delta + row * DD;
    int tid = threadIdx.x;
    float v[4];
    float s = 0.f;
    #pragma unroll
    for (int i = 0; i < 4; i++) {
        int idx = tid + i * 256;
        v[i] = __half2float(t[idx]) + __half2float(dl[idx]);
        s += v[i];
    }
    __shared__ float red[256];
    red[tid] = s; __syncthreads();
    #pragma unroll
    for (int o = 128; o > 0; o >>= 1) { if (tid < o) red[tid] += red[tid + o]; __syncthreads(); }
    float mean = red[0] * (1.f / 1024.f);
    __syncthreads();
    float s2 = 0.f;
    #pragma unroll
    for (int i = 0; i < 4; i++) { float d = v[i] - mean; s2 += d * d; }
    red[tid] = s2; __syncthreads();
    #pragma unroll
    for (int o = 128; o > 0; o >>= 1) { if (tid < o) red[tid] += red[tid + o]; __syncthreads(); }
    float inv = rsqrtf(red[0] * (1.f / 1024.f) + 1e-5f);
    #pragma unroll
    for (int i = 0; i < 4; i++) {
        int idx = tid + i * 256;
        t[idx] = __float2half_rn((v[i] - mean) * inv * g[idx] + beta[idx]);
    }
}

// ---------------- head + loss (reads compact final rows) ----------------
__global__ void loss_kernel(const float* __restrict__ W_ham, const float* __restrict__ b_ham,
                            const float* __restrict__ y, const float* __restrict__ w,
                            float* __restrict__ out)
{
    __shared__ float red[256];
    int tid = threadIdx.x;
    float acc = 0.f;
    for (int idx = tid; idx < BB * 144; idx += 256) {
        int b = idx / 144;
        int j = idx % 144;
        const float* row = g_c_x + (size_t)b * DD;
        const float* wr = W_ham + (size_t)j * DD;
        float dot = b_ham[j];
        for (int k = 0; k < DD; k++) dot = fmaf(row[k], wr[k], dot);
        float yr = y[b * 144 + j] - w[(size_t)b * 2304 + 2160 + j];
        float d = dot - yr;
        acc += d * d;
    }
    red[tid] = acc; __syncthreads();
    #pragma unroll
    for (int o = 128; o > 0; o >>= 1) { if (tid < o) red[tid] += red[tid + o]; __syncthreads(); }
    if (tid == 0) out[0] = red[0] / (float)(BB * 144);
}

// ---------------- launch ----------------
extern "C" void kernel_launch(void* const* d_in, const int* in_sizes, int n_in,
                              void* d_out, int out_size)
{
    const float* x      = (const float*)d_in[0];
    const float* w      = (const float*)d_in[1];
    const float* y      = (const float*)d_in[2];
    const float* W_nail = (const float*)d_in[3];
    const float* b_nail = (const float*)d_in[4];
    const float* W_cond = (const float*)d_in[5];
    const float* b_cond = (const float*)d_in[6];
    const float* Wqkv   = (const float*)d_in[7];
    const float* bqkv   = (const float*)d_in[8];
    const float* Wo     = (const float*)d_in[9];
    const float* bo     = (const float*)d_in[10];
    const float* ln1_g  = (const float*)d_in[11];
    const float* ln1_b  = (const float*)d_in[12];
    const float* ln2_g  = (const float*)d_in[13];
    const float* ln2_b  = (const float*)d_in[14];
    const float* W1     = (const float*)d_in[15];
    const float* b1     = (const float*)d_in[16];
    const float* W2     = (const float*)d_in[17];
    const float* b2     = (const float*)d_in[18];
    const float* W_ham  = (const float*)d_in[19];
    const float* b_ham  = (const float*)d_in[20];

    float *p_c_attn, *p_c_t2, *p_c_x, *p_c_hid;
    __half *p_tgt_s, *p_qkv, *p_attno, *p_hid, *p_tmp_h, *p_embA, *p_wnail;
    __half *p_wqkv, *p_wo, *p_w1, *p_w2;
    cudaGetSymbolAddress((void**)&p_tgt_s,  g_tgt_s);
    cudaGetSymbolAddress((void**)&p_qkv,    g_qkv);
    cudaGetSymbolAddress((void**)&p_attno,  g_attno);
    cudaGetSymbolAddress((void**)&p_hid,    g_hid);
    cudaGetSymbolAddress((void**)&p_tmp_h,  g_tmp_h);
    cudaGetSymbolAddress((void**)&p_embA,   g_embA);
    cudaGetSymbolAddress((void**)&p_wnail,  g_wnail_h);
    cudaGetSymbolAddress((void**)&p_wqkv,   g_wqkv);
    cudaGetSymbolAddress((void**)&p_wo,     g_wo);
    cudaGetSymbolAddress((void**)&p_w1,     g_w1);
    cudaGetSymbolAddress((void**)&p_w2,     g_w2);
    cudaGetSymbolAddress((void**)&p_c_attn, g_c_attn);
    cudaGetSymbolAddress((void**)&p_c_t2,   g_c_t2);
    cudaGetSymbolAddress((void**)&p_c_x,    g_c_x);
    cudaGetSymbolAddress((void**)&p_c_hid,  g_c_hid);

    static const int SMG = 32768 * 3;
    static const int SMF = 16384 + 3 * 16384;
    cudaFuncSetAttribute(mma_gemm<0, 0>, cudaFuncAttributeMaxDynamicSharedMemorySize, SMG);
    cudaFuncSetAttribute(mma_gemm<0, 1>, cudaFuncAttributeMaxDynamicSharedMemorySize, SMG);
    cudaFuncSetAttribute(mma_gemm<1, 0>, cudaFuncAttributeMaxDynamicSharedMemorySize, SMG);
    cudaFuncSetAttribute(flash_kernel,   cudaFuncAttributeMaxDynamicSharedMemorySize, SMF);

    const int M = BB * SS;   // 7168
    dim3 blk(256);

    // weight conversions
    {
        long n;
        n = (long)NLAYER * 3 * DD * DD / 4;
        cvt_kernel<<<(unsigned)((n + 255) / 256), blk>>>(Wqkv, p_wqkv, n);
        n = (long)(NLAYER - 1) * DD * DD / 4;
        cvt_kernel<<<(unsigned)((n + 255) / 256), blk>>>(Wo, p_wo, n);
        n = (long)(NLAYER - 1) * FFD * DD / 4;
        cvt_kernel<<<(unsigned)((n + 255) / 256), blk>>>(W1, p_w1, n);
        n = (long)(NLAYER - 1) * DD * FFD / 4;
        cvt_kernel<<<(unsigned)((n + 255) / 256), blk>>>(W2, p_w2, n);
    }

    // embeddings: x via GEMM, w via SIMT
    prep_x_kernel<<<BB * LX, 64>>>(x);
    prep_wnail_kernel<<<DD, 64>>>(W_nail);
    mma_gemm<0, 0><<<dim3(BB * LX / 128, DD / 128), blk, SMG>>>(
        p_embA, p_wnail, b_nail, p_tmp_h, 64, 64, 64, DD);
    pe_x_kernel<<<BB * LX, blk>>>();
    embed_w_kernel<<<BB * NWTOK, blk>>>(w, W_cond, b_cond);

    // ---- layers 0..2: full pipeline ----
    for (int l = 0; l < NLAYER - 1; l++) {
        const __half* wqkv_l = p_wqkv + (size_t)l * 3 * DD * DD;
        const __half* wo_l   = p_wo + (size_t)l * DD * DD;
        const __half* w1_l   = p_w1 + (size_t)l * FFD * DD;
        const __half* w2_l   = p_w2 + (size_t)l * DD * FFD;

        mma_gemm<0, 1><<<dim3(M / 128, 3 * DD / 128), blk, SMG>>>(
            p_tgt_s, wqkv_l, bqkv + (size_t)l * 3 * DD,
            p_qkv, DD, DD, DD, 3 * DD);

        flash_kernel<<<dim3(SS / 128, BB * NH), blk, SMF>>>();

        mma_gemm<0, 0><<<dim3(M / 128, DD / 128), blk, SMG>>>(
            p_attno, wo_l, bo + (size_t)l * DD,
            p_tmp_h, DD, DD, DD, DD);

        resid_ln_kernel<<<M, blk>>>(p_tmp_h, ln1_g + (size_t)l * DD, ln1_b + (size_t)l * DD);

        mma_gemm<1, 0><<<dim3(M / 128, FFD / 128), blk, SMG>>>(
            p_tgt_s, w1_l, b1 + (size_t)l * FFD,
            p_hid, DD, DD, DD, FFD);

        mma_gemm<0, 0><<<dim3(M / 128, DD / 128), blk, SMG>>>(
            p_hid, w2_l, b2 + (size_t)l * DD,
            p_tmp_h, FFD, FFD, FFD, DD);

        resid_ln_kernel<<<M, blk>>>(p_tmp_h, ln2_g + (size_t)l * DD, ln2_b + (size_t)l * DD);
    }

    // ---- layer 3: only the final token per batch matters downstream ----
    {
        const int l = NLAYER - 1;
        mma_gemm<0, 0><<<dim3(M / 128, 2 * DD / 128), blk, SMG>>>(
            p_tgt_s, p_wqkv + (size_t)l * 3 * DD * DD + (size_t)DD * DD,
            bqkv + (size_t)l * 3 * DD + DD,
            p_qkv + DD, DD, DD, DD, 3 * DD);

        flash_last_kernel<<<BB * NH, blk>>>(
            Wqkv + (size_t)l * 3 * DD * DD, bqkv + (size_t)l * 3 * DD);

        small_gemm<0><<<DD, blk>>>(p_c_attn, Wo + (size_t)l * DD * DD,
                                   bo + (size_t)l * DD, p_c_t2, DD, DD);
        resid_ln_last<<<BB, blk>>>(p_tgt_s + (size_t)(SS - 1) * DD, (long)SS * DD,
                                   nullptr,
                                   p_c_t2, ln1_g + (size_t)l * DD, ln1_b + (size_t)l * DD,
                                   p_c_x);
        small_gemm<1><<<FFD, blk>>>(p_c_x, W1 + (size_t)l * FFD * DD,
                                    b1 + (size_t)l * FFD, p_c_hid, FFD, DD);
        small_gemm<0><<<DD, blk>>>(p_c_hid, W2 + (size_t)l * DD * FFD,
                                   b2 + (size_t)l * DD, p_c_t2, DD, FFD);
        resid_ln_last<<<BB, blk>>>(nullptr, 0,
                                   p_c_x,
                                   p_c_t2, ln2_g + (size_t)l * DD, ln2_b + (size_t)l * DD,
                                   p_c_x);
    }

    loss_kernel<<<1, blk>>>(W_ham, b_ham, y, w, (float*)d_out);
}